// round 5
// baseline (speedup 1.0000x reference)
#include <cuda_runtime.h>
#include <math.h>

// ---------------- problem dims ----------------
#define R_   2
#define K_   3
#define N_   16384
#define V_   256
#define E_   1
#define L_   8
#define VE_  128
#define LK_  1
#define OUT_ 64
#define IN_  256
#define HID_ 512
#define C_   5
#define CH_  (C_*HID_)   // 2560

// ---------------- workspace (device globals; no runtime alloc) ----------------
__device__ float g_x1[(size_t)N_ * CH_];          // per-r activations stage 1
__device__ float g_x2[(size_t)N_ * CH_];          // per-r activations stage 2
__device__ float g_outr[(size_t)R_ * N_ * HID_];  // per-relation pooled output
__device__ float g_hfin[(size_t)N_ * HID_];       // globally pooled
__device__ float g_xp[(size_t)R_ * N_ * VE_];     // pooled extra raw feats
__device__ float g_stats1[N_ * 2];                // LN1 mean/rstd per row
__device__ float g_u[R_ * VE_];                   // extra_emb @ w_extra
__device__ float g_Wraw[(size_t)R_ * K_ * V_ * HID_];   // femb @ W1[c], c<3
__device__ float g_Wex [(size_t)R_ * VE_ * HID_];       // extra_emb @ W1[3]
__device__ float g_Wlab[(size_t)R_ * OUT_ * HID_];      // label_emb @ W1[4]

// =========================================================================
// Packed-f32x2 (FFMA2) tiled GEMM. BN=128, BK=16, TN=8 fixed; BM/TM template.
// C[M,Ncols] = op_A(A[M,Kd]) @ B[Kd,Ncols] (+bias) (opt. PReLU out)
// op_A (LN_A): a' = prelu((a - mean[row])*rstd[row]*gamma[k] + beta[k], alpha)
// Requires Kd % 16 == 0 and Ncols % 4 == 0 (all call sites satisfy this).
// =========================================================================
constexpr int BN2 = 128, BK2 = 16, TN2 = 8;

template<int BM, int TM, bool LN_A, bool PRELU_OUT>
__device__ __forceinline__ void gemm2_core(
    const float* __restrict__ A, int lda, int M, int Kd,
    const float* __restrict__ B, int ldb,
    const float* __restrict__ bias,
    float* __restrict__ Co, int ldc, int Ncols,
    const float* __restrict__ stats,
    const float* __restrict__ gamma,
    const float* __restrict__ beta,
    const float* __restrict__ alpha_p)
{
    constexpr int TX = BN2 / TN2;                 // 16
    constexpr int TY = BM / TM;
    constexpr int THREADS = TX * TY;              // 256
    constexpr int A4 = BM * (BK2 / 4) / THREADS;  // float4 per thread (A tile)
    constexpr int B4 = BK2 * (BN2 / 4) / THREADS; // float4 per thread (B tile)

    // pad so row stride (BM+4) is float4-aligned; A-tile stores are 2-way
    // bank-conflicted (stride*4 mod 32 == 16) which costs ~6% of compute.
    __shared__ __align__(16) float As[BK2][BM + 4];
    __shared__ __align__(16) float Bs[BK2][BN2];

    const int tid  = threadIdx.x;
    const int tx   = tid % TX;
    const int ty   = tid / TX;
    const int row0 = blockIdx.y * BM;
    const int col0 = blockIdx.x * BN2;

    float alpha = 0.f;
    if constexpr (LN_A || PRELU_OUT) alpha = __ldg(alpha_p);

    unsigned long long acc[TM][TN2 / 2];
    #pragma unroll
    for (int i = 0; i < TM; i++)
        #pragma unroll
        for (int j = 0; j < TN2 / 2; j++) acc[i][j] = 0ull;  // bit pattern = (0.f,0.f)

    float4 ra[A4], rb[B4];

    // ---- global -> registers (with optional fused LN+PReLU on A) ----
    auto load_tiles = [&](int k0) {
        #pragma unroll
        for (int q = 0; q < A4; q++) {
            int v  = tid + q * THREADS;
            int r  = v / (BK2 / 4);
            int kq = (v % (BK2 / 4)) * 4;
            int gr = row0 + r;
            float4 val = make_float4(0.f, 0.f, 0.f, 0.f);
            if (gr < M) {
                val = *reinterpret_cast<const float4*>(A + (size_t)gr * lda + k0 + kq);
                if constexpr (LN_A) {
                    float mn = stats[2 * gr], rs = stats[2 * gr + 1];
                    float4 gm = *reinterpret_cast<const float4*>(gamma + k0 + kq);
                    float4 bt = *reinterpret_cast<const float4*>(beta  + k0 + kq);
                    val.x = (val.x - mn) * rs * gm.x + bt.x;
                    val.y = (val.y - mn) * rs * gm.y + bt.y;
                    val.z = (val.z - mn) * rs * gm.z + bt.z;
                    val.w = (val.w - mn) * rs * gm.w + bt.w;
                    val.x = val.x >= 0.f ? val.x : alpha * val.x;
                    val.y = val.y >= 0.f ? val.y : alpha * val.y;
                    val.z = val.z >= 0.f ? val.z : alpha * val.z;
                    val.w = val.w >= 0.f ? val.w : alpha * val.w;
                }
            }
            ra[q] = val;
        }
        #pragma unroll
        for (int q = 0; q < B4; q++) {
            int v  = tid + q * THREADS;
            int r  = v / (BN2 / 4);
            int c4 = (v % (BN2 / 4)) * 4;
            int gc = col0 + c4;
            float4 val = make_float4(0.f, 0.f, 0.f, 0.f);
            if (gc < Ncols)
                val = *reinterpret_cast<const float4*>(B + (size_t)(k0 + r) * ldb + gc);
            rb[q] = val;
        }
    };
    // ---- registers -> shared ----
    auto store_tiles = [&]() {
        #pragma unroll
        for (int q = 0; q < A4; q++) {
            int v  = tid + q * THREADS;
            int r  = v / (BK2 / 4);
            int kq = (v % (BK2 / 4)) * 4;
            As[kq + 0][r] = ra[q].x;
            As[kq + 1][r] = ra[q].y;
            As[kq + 2][r] = ra[q].z;
            As[kq + 3][r] = ra[q].w;
        }
        #pragma unroll
        for (int q = 0; q < B4; q++) {
            int v  = tid + q * THREADS;
            int r  = v / (BN2 / 4);
            int c4 = (v % (BN2 / 4)) * 4;
            *reinterpret_cast<float4*>(&Bs[r][c4]) = rb[q];
        }
    };

    load_tiles(0);
    store_tiles();
    __syncthreads();

    for (int k0 = 0; k0 < Kd; k0 += BK2) {
        bool more = (k0 + BK2) < Kd;
        if (more) load_tiles(k0 + BK2);   // register prefetch overlaps compute

        #pragma unroll
        for (int kk = 0; kk < BK2; kk++) {
            float a[TM];
            #pragma unroll
            for (int i = 0; i < TM; i += 4) {
                float4 t = *reinterpret_cast<const float4*>(&As[kk][ty * TM + i]);
                a[i] = t.x; a[i + 1] = t.y; a[i + 2] = t.z; a[i + 3] = t.w;
            }
            unsigned long long b2[TN2 / 2];
            {
                const ulonglong2* bp =
                    reinterpret_cast<const ulonglong2*>(&Bs[kk][tx * TN2]);
                ulonglong2 t0 = bp[0], t1 = bp[1];
                b2[0] = t0.x; b2[1] = t0.y; b2[2] = t1.x; b2[3] = t1.y;
            }
            #pragma unroll
            for (int i = 0; i < TM; i++) {
                unsigned long long a2;
                asm("mov.b64 %0, {%1, %1};" : "=l"(a2) : "f"(a[i]));
                #pragma unroll
                for (int j = 0; j < TN2 / 2; j++)
                    asm("fma.rn.f32x2 %0, %1, %2, %0;"
                        : "+l"(acc[i][j]) : "l"(a2), "l"(b2[j]));
            }
        }
        __syncthreads();
        if (more) { store_tiles(); __syncthreads(); }
    }

    // ---- epilogue: unpack, bias, optional PReLU ----
    #pragma unroll
    for (int i = 0; i < TM; i++) {
        int gr = row0 + ty * TM + i;
        if (gr >= M) continue;
        float* crow = Co + (size_t)gr * ldc;
        #pragma unroll
        for (int j = 0; j < TN2 / 2; j++) {
            float lo, hi;
            asm("mov.b64 {%0, %1}, %2;" : "=f"(lo), "=f"(hi) : "l"(acc[i][j]));
            int gc = col0 + tx * TN2 + 2 * j;
            if (gc < Ncols) {
                float v0 = lo;
                if (bias) v0 += bias[gc];
                if constexpr (PRELU_OUT) v0 = v0 >= 0.f ? v0 : alpha * v0;
                crow[gc] = v0;
            }
            if (gc + 1 < Ncols) {
                float v1 = hi;
                if (bias) v1 += bias[gc + 1];
                if constexpr (PRELU_OUT) v1 = v1 >= 0.f ? v1 : alpha * v1;
                crow[gc + 1] = v1;
            }
        }
    }
}

template<int BM, int TM, bool LN_A, bool PRELU_OUT>
__global__ void __launch_bounds__(256, 1) gemm2_kernel(
    const float* __restrict__ A, int lda, long long aZ, int M, int Kd,
    const float* __restrict__ B, int ldb, long long bZ,
    const float* __restrict__ bias, long long biasZ,
    float* __restrict__ Co, int ldc, long long cZ, int Ncols,
    const float* __restrict__ stats,
    const float* __restrict__ gamma, const float* __restrict__ beta, long long gZ,
    const float* __restrict__ alpha_p)
{
    long long z = blockIdx.z;
    gemm2_core<BM, TM, LN_A, PRELU_OUT>(
        A + z * aZ, lda, M, Kd,
        B + z * bZ, ldb,
        bias ? bias + z * biasZ : nullptr,
        Co + z * cZ, ldc, Ncols,
        stats,
        gamma ? gamma + z * gZ : nullptr,
        beta  ? beta  + z * gZ : nullptr,
        alpha_p);
}

// ---------------- plain fp32 GEMM core (kept for tiny weight-fusion GEMMs) ----
constexpr int BN = 128, BK = 16, TN = 8;

template<int BM, int TM>
__device__ __forceinline__ void gemm_core(
    const float* __restrict__ A, int lda, int M, int Kd,
    const float* __restrict__ B, int ldb,
    float* __restrict__ Co, int ldc, int Ncols)
{
    constexpr int TX = BN / TN;
    constexpr int TY = BM / TM;
    constexpr int THREADS = TX * TY;

    __shared__ __align__(16) float As[BK][BM + 4];
    __shared__ __align__(16) float Bs[BK][BN];

    const int tid  = threadIdx.x;
    const int tx   = tid % TX;
    const int ty   = tid / TX;
    const int row0 = blockIdx.y * BM;
    const int col0 = blockIdx.x * BN;

    float acc[TM][TN];
    #pragma unroll
    for (int i = 0; i < TM; i++)
        #pragma unroll
        for (int j = 0; j < TN; j++) acc[i][j] = 0.f;

    for (int k0 = 0; k0 < Kd; k0 += BK) {
        for (int v = tid; v < BM * (BK / 4); v += THREADS) {
            int r  = v / (BK / 4);
            int kq = (v % (BK / 4)) * 4;
            int gr = row0 + r;
            float4 val = make_float4(0.f, 0.f, 0.f, 0.f);
            if (gr < M)
                val = *reinterpret_cast<const float4*>(A + (size_t)gr * lda + k0 + kq);
            As[kq + 0][r] = val.x;
            As[kq + 1][r] = val.y;
            As[kq + 2][r] = val.z;
            As[kq + 3][r] = val.w;
        }
        for (int v = tid; v < BK * (BN / 4); v += THREADS) {
            int r  = v / (BN / 4);
            int c4 = (v % (BN / 4)) * 4;
            int gc = col0 + c4;
            float4 val = make_float4(0.f, 0.f, 0.f, 0.f);
            if (gc < Ncols)
                val = *reinterpret_cast<const float4*>(B + (size_t)(k0 + r) * ldb + gc);
            *reinterpret_cast<float4*>(&Bs[r][c4]) = val;
        }
        __syncthreads();
        #pragma unroll
        for (int kk = 0; kk < BK; kk++) {
            float a[TM], b[TN];
            #pragma unroll
            for (int i = 0; i < TM; i += 4) {
                float4 t = *reinterpret_cast<const float4*>(&As[kk][ty * TM + i]);
                a[i] = t.x; a[i + 1] = t.y; a[i + 2] = t.z; a[i + 3] = t.w;
            }
            #pragma unroll
            for (int j = 0; j < TN; j += 4) {
                float4 t = *reinterpret_cast<const float4*>(&Bs[kk][tx * TN + j]);
                b[j] = t.x; b[j + 1] = t.y; b[j + 2] = t.z; b[j + 3] = t.w;
            }
            #pragma unroll
            for (int i = 0; i < TM; i++)
                #pragma unroll
                for (int j = 0; j < TN; j++)
                    acc[i][j] += a[i] * b[j];
        }
        __syncthreads();
    }
    #pragma unroll
    for (int i = 0; i < TM; i++) {
        int gr = row0 + ty * TM + i;
        if (gr >= M) continue;
        float* crow = Co + (size_t)gr * ldc;
        #pragma unroll
        for (int j = 0; j < TN; j++) {
            int gc = col0 + tx * TN + j;
            if (gc < Ncols) crow[gc] = acc[i][j];
        }
    }
}

// ---------------- fused-weight precompute: emb @ W1[c] (10 small GEMMs) --------
__global__ void __launch_bounds__(256, 2) fuse_weights_kernel(
    const float* __restrict__ femb, const float* __restrict__ eemb,
    const float* __restrict__ lemb, const float* __restrict__ W1)
{
    int z = blockIdx.z;            // 0..9 -> (r, c)
    int r = z / C_, c = z % C_;
    const float* Ap; int M; float* out;
    if (c < K_) {
        Ap = femb + (size_t)(r * K_ + c) * V_ * IN_;  M = V_;
        out = g_Wraw + (size_t)(r * K_ + c) * V_ * HID_;
    } else if (c == 3) {
        Ap = eemb + (size_t)r * VE_ * IN_;            M = VE_;
        out = g_Wex + (size_t)r * VE_ * HID_;
    } else {
        Ap = lemb + (size_t)r * OUT_ * IN_;           M = OUT_;
        out = g_Wlab + (size_t)r * OUT_ * HID_;
    }
    const float* Bp = W1 + (size_t)c * IN_ * HID_;
    gemm_core<64, 4>(Ap, IN_, M, IN_, Bp, HID_, out, HID_, HID_);
}

// ---------------- u[r][v] = extra_emb[r,0,v,:] . w_extra[0,:] ----------------
__global__ void k_u(const float* __restrict__ eemb, const float* __restrict__ w_extra)
{
    int t = blockIdx.x * blockDim.x + threadIdx.x;
    if (t >= R_ * VE_) return;
    int r = t / VE_, v = t % VE_;
    const float* row = eemb + ((size_t)r * VE_ + v) * IN_;
    float s = 0.f;
    for (int d = 0; d < IN_; d++) s += row[d] * w_extra[d];
    g_u[t] = s;
}

// ---------------- extra-feature attention pool in raw space (warp per (r,n)) ---
__global__ void __launch_bounds__(256) k_extra_pool(const float* __restrict__ extra)
{
    int wg   = (blockIdx.x * blockDim.x + threadIdx.x) >> 5;
    int lane = threadIdx.x & 31;
    if (wg >= R_ * N_) return;
    int r = wg / N_, n = wg % N_;
    const float* base = extra + (size_t)(r * N_ + n) * (L_ * VE_);

    float u[4];
    #pragma unroll
    for (int j = 0; j < 4; j++) u[j] = g_u[r * VE_ + lane + 32 * j];

    float x[L_][4];
    float s[L_];
    #pragma unroll
    for (int l = 0; l < L_; l++) {
        float p = 0.f;
        #pragma unroll
        for (int j = 0; j < 4; j++) {
            x[l][j] = base[l * VE_ + lane + 32 * j];
            p += x[l][j] * u[j];
        }
        #pragma unroll
        for (int o = 16; o > 0; o >>= 1) p += __shfl_xor_sync(0xffffffffu, p, o);
        s[l] = 1.f / (1.f + expf(-p));           // sigmoid
    }
    float mx = s[0];
    #pragma unroll
    for (int l = 1; l < L_; l++) mx = fmaxf(mx, s[l]);
    float e[L_], esum = 0.f;
    #pragma unroll
    for (int l = 0; l < L_; l++) { e[l] = expf(s[l] - mx); esum += e[l]; }
    float inv = 1.f / esum;

    float out[4] = {0.f, 0.f, 0.f, 0.f};
    #pragma unroll
    for (int l = 0; l < L_; l++) {
        float w = e[l] * inv;
        #pragma unroll
        for (int j = 0; j < 4; j++) out[j] += w * x[l][j];
    }
    float* op = g_xp + (size_t)(r * N_ + n) * VE_;
    #pragma unroll
    for (int j = 0; j < 4; j++) op[lane + 32 * j] = out[j];
}

// ---------------- LayerNorm stats over [C,HID] per row (warp per row) ----------
__global__ void __launch_bounds__(256) k_stats(const float* __restrict__ X, float* __restrict__ stats)
{
    int w    = (blockIdx.x * blockDim.x + threadIdx.x) >> 5;
    int lane = threadIdx.x & 31;
    if (w >= N_) return;
    const float4* row = reinterpret_cast<const float4*>(X + (size_t)w * CH_);
    float s = 0.f, s2 = 0.f;
    for (int v = lane; v < CH_ / 4; v += 32) {
        float4 t = row[v];
        s  += t.x + t.y + t.z + t.w;
        s2 += t.x * t.x + t.y * t.y + t.z * t.z + t.w * t.w;
    }
    #pragma unroll
    for (int o = 16; o > 0; o >>= 1) {
        s  += __shfl_xor_sync(0xffffffffu, s,  o);
        s2 += __shfl_xor_sync(0xffffffffu, s2, o);
    }
    if (lane == 0) {
        float m   = s / (float)CH_;
        float var = s2 / (float)CH_ - m * m;
        stats[2 * w]     = m;
        stats[2 * w + 1] = rsqrtf(var + 1e-5f);
    }
}

// ---------------- channel attention pool (block per n) -------------------------
// Computes LN2 stats in-block (no separate stats pass), then LN2+PReLU,
// sigmoid-softmax over C, weighted sum -> g_outr.
__global__ void __launch_bounds__(256) k_pool_c(
    const float* __restrict__ g2, const float* __restrict__ be2,
    const float* __restrict__ a2p, const float* __restrict__ wr, int r)
{
    int n = blockIdx.x, tid = threadIdx.x;
    __shared__ __align__(16) float sx[CH_];
    __shared__ float red[C_][8];
    __shared__ float rsum[8], rsum2[8];
    __shared__ float salpha[C_];
    __shared__ float smn, srs;

    const float* xr = g_x2 + (size_t)n * CH_;

    // load row + accumulate sum / sumsq
    float s = 0.f, s2 = 0.f;
    for (int i = tid; i < CH_ / 4; i += 256) {
        float4 t = reinterpret_cast<const float4*>(xr)[i];
        reinterpret_cast<float4*>(sx)[i] = t;
        s  += t.x + t.y + t.z + t.w;
        s2 += t.x * t.x + t.y * t.y + t.z * t.z + t.w * t.w;
    }
    int lane = tid & 31, wid = tid >> 5;
    #pragma unroll
    for (int o = 16; o > 0; o >>= 1) {
        s  += __shfl_xor_sync(0xffffffffu, s,  o);
        s2 += __shfl_xor_sync(0xffffffffu, s2, o);
    }
    if (lane == 0) { rsum[wid] = s; rsum2[wid] = s2; }
    __syncthreads();
    if (tid == 0) {
        float ts = 0.f, ts2 = 0.f;
        #pragma unroll
        for (int w2 = 0; w2 < 8; w2++) { ts += rsum[w2]; ts2 += rsum2[w2]; }
        float m   = ts / (float)CH_;
        float var = ts2 / (float)CH_ - m * m;
        smn = m;
        srs = rsqrtf(var + 1e-5f);
    }
    __syncthreads();

    float mn = smn, rs = srs, a = __ldg(a2p);
    for (int i = tid; i < CH_; i += 256) {
        float v = (sx[i] - mn) * rs * g2[i] + be2[i];
        sx[i] = v >= 0.f ? v : a * v;
    }
    __syncthreads();

    float p[C_] = {0.f, 0.f, 0.f, 0.f, 0.f};
    for (int h = tid; h < HID_; h += 256) {
        float w = wr[h];
        #pragma unroll
        for (int c = 0; c < C_; c++) p[c] += sx[c * HID_ + h] * w;
    }
    #pragma unroll
    for (int c = 0; c < C_; c++) {
        #pragma unroll
        for (int o = 16; o > 0; o >>= 1) p[c] += __shfl_xor_sync(0xffffffffu, p[c], o);
    }
    if (lane == 0) {
        #pragma unroll
        for (int c = 0; c < C_; c++) red[c][wid] = p[c];
    }
    __syncthreads();
    if (tid == 0) {
        float sv[C_];
        float mx = -1e30f;
        #pragma unroll
        for (int c = 0; c < C_; c++) {
            float t = 0.f;
            #pragma unroll
            for (int w2 = 0; w2 < 8; w2++) t += red[c][w2];
            sv[c] = 1.f / (1.f + expf(-t));
            mx = fmaxf(mx, sv[c]);
        }
        float esum = 0.f, e[C_];
        #pragma unroll
        for (int c = 0; c < C_; c++) { e[c] = expf(sv[c] - mx); esum += e[c]; }
        float inv = 1.f / esum;
        #pragma unroll
        for (int c = 0; c < C_; c++) salpha[c] = e[c] * inv;
    }
    __syncthreads();

    float* op = g_outr + (size_t)r * N_ * HID_ + (size_t)n * HID_;
    for (int h = tid; h < HID_; h += 256) {
        float acc = 0.f;
        #pragma unroll
        for (int c = 0; c < C_; c++) acc += salpha[c] * sx[c * HID_ + h];
        op[h] = acc;
    }
}

// ---------------- global (over R) attention pool (warp per n) ------------------
__global__ void __launch_bounds__(256) k_pool_global(const float* __restrict__ wg)
{
    int w    = (blockIdx.x * blockDim.x + threadIdx.x) >> 5;
    int lane = threadIdx.x & 31;
    if (w >= N_) return;
    const float* pa = g_outr + (size_t)w * HID_;
    const float* pb = g_outr + (size_t)N_ * HID_ + (size_t)w * HID_;
    float a[16], b[16], wv[16];
    float sa = 0.f, sb = 0.f;
    #pragma unroll
    for (int j = 0; j < 16; j++) {
        int h = lane + 32 * j;
        a[j] = pa[h]; b[j] = pb[h]; wv[j] = wg[h];
        sa += a[j] * wv[j]; sb += b[j] * wv[j];
    }
    #pragma unroll
    for (int o = 16; o > 0; o >>= 1) {
        sa += __shfl_xor_sync(0xffffffffu, sa, o);
        sb += __shfl_xor_sync(0xffffffffu, sb, o);
    }
    sa = 1.f / (1.f + expf(-sa));
    sb = 1.f / (1.f + expf(-sb));
    float mx = fmaxf(sa, sb);
    float ea = expf(sa - mx), eb = expf(sb - mx);
    float aa = ea / (ea + eb);
    float ab = 1.f - aa;
    float* op = g_hfin + (size_t)w * HID_;
    #pragma unroll
    for (int j = 0; j < 16; j++) op[lane + 32 * j] = aa * a[j] + ab * b[j];
}

// ---------------- input mapping (resolved from size signature at launch) -------
struct Ins {
    const float *raw, *extra, *label, *femb, *eemb, *lemb;
    const float *w_extra, *w_r, *w_g;
    const float *W1, *b1, *g1, *be1, *a1, *W2, *b2, *g2, *be2, *a2;
    const float *Wf1, *bf1, *af, *Wf2, *bf2;
};

static void resolve(void* const* d_in, const int* sz, Ins& I)
{
    auto F = [&](int i) { return (const float*)d_in[i]; };
    if (sz[0] == R_ * K_ * N_ * V_) {
        I.raw = F(0);  I.extra = F(1);  I.label = F(2);
        I.femb = F(3); I.eemb = F(4);   I.lemb = F(5);
        I.w_extra = F(6); I.w_r = F(7); I.w_g = F(8);
        I.W1 = F(9);  I.b1 = F(10); I.g1 = F(11); I.be1 = F(12); I.a1 = F(13);
        I.W2 = F(14); I.b2 = F(15); I.g2 = F(16); I.be2 = F(17); I.a2 = F(18);
        I.Wf1 = F(19); I.bf1 = F(20); I.af = F(21); I.Wf2 = F(22); I.bf2 = F(23);
    } else {
        // sorted-key order
        I.W1 = F(0);  I.W2 = F(1);  I.Wf1 = F(2); I.Wf2 = F(3);
        I.a1 = F(4);  I.a2 = F(5);  I.af = F(6);
        I.b1 = F(7);  I.b2 = F(8);  I.be1 = F(9); I.be2 = F(10);
        I.bf1 = F(11); I.bf2 = F(12);
        I.eemb = F(13); I.extra = F(14); I.femb = F(15);
        I.g1 = F(16); I.g2 = F(17);
        I.lemb = F(18); I.label = F(19); I.raw = F(20);
        I.w_extra = F(21); I.w_g = F(22); I.w_r = F(23);
    }
}

extern "C" void kernel_launch(void* const* d_in, const int* in_sizes, int n_in,
                              void* d_out, int out_size)
{
    if (n_in < 24) return;
    Ins I;
    resolve(d_in, in_sizes, I);

    float *px1, *px2, *pxp, *pWraw, *pWex, *pWlab, *ps1, *phf;
    cudaGetSymbolAddress((void**)&px1,   g_x1);
    cudaGetSymbolAddress((void**)&px2,   g_x2);
    cudaGetSymbolAddress((void**)&pxp,   g_xp);
    cudaGetSymbolAddress((void**)&pWraw, g_Wraw);
    cudaGetSymbolAddress((void**)&pWex,  g_Wex);
    cudaGetSymbolAddress((void**)&pWlab, g_Wlab);
    cudaGetSymbolAddress((void**)&ps1,   g_stats1);
    cudaGetSymbolAddress((void**)&phf,   g_hfin);

    // prolog: u vectors, fused W1 weights, extra pooling (reads extra_feats once)
    k_u<<<1, 256>>>(I.eemb, I.w_extra);
    fuse_weights_kernel<<<dim3(4, 4, 10), 256>>>(I.femb, I.eemb, I.lemb, I.W1);
    k_extra_pool<<<(R_ * N_) / 8, 256>>>(I.extra);

    for (int r = 0; r < R_; r++) {
        // x1: channels 0..2 (raw @ fused weights), batched over z
        gemm2_kernel<256, 16, false, false><<<dim3(HID_ / BN2, N_ / 256, K_), 256>>>(
            I.raw + (size_t)r * K_ * N_ * V_, V_, (long long)N_ * V_, N_, V_,
            pWraw + (size_t)r * K_ * V_ * HID_, HID_, (long long)V_ * HID_,
            I.b1, HID_,
            px1, CH_, HID_, HID_,
            nullptr, nullptr, nullptr, 0, nullptr);
        // x1: channel 3 (pooled extra @ fused weights), K=128
        gemm2_kernel<128, 8, false, false><<<dim3(HID_ / BN2, N_ / 128, 1), 256>>>(
            pxp + (size_t)r * N_ * VE_, VE_, 0, N_, VE_,
            pWex + (size_t)r * VE_ * HID_, HID_, 0,
            I.b1 + 3 * HID_, 0,
            px1 + 3 * HID_, CH_, 0, HID_,
            nullptr, nullptr, nullptr, 0, nullptr);
        // x1: channel 4 (label @ fused weights), K=64
        gemm2_kernel<128, 8, false, false><<<dim3(HID_ / BN2, N_ / 128, 1), 256>>>(
            I.label + (size_t)r * N_ * OUT_, OUT_, 0, N_, OUT_,
            pWlab + (size_t)r * OUT_ * HID_, HID_, 0,
            I.b1 + 4 * HID_, 0,
            px1 + 4 * HID_, CH_, 0, HID_,
            nullptr, nullptr, nullptr, 0, nullptr);

        // LN1 stats; x2 = prelu(LN(x1)) @ W2 + b2  (LN+PReLU fused into A-load)
        k_stats<<<N_ / 8, 256>>>(px1, ps1);
        gemm2_kernel<256, 16, true, false><<<dim3(HID_ / BN2, N_ / 256, C_), 256>>>(
            px1, CH_, (long long)HID_, N_, HID_,
            I.W2, HID_, (long long)HID_ * HID_,
            I.b2, HID_,
            px2, CH_, HID_, HID_,
            ps1, I.g1, I.be1, HID_, I.a1);

        // per-n channel attention pool (LN2 stats + LN2 + PReLU fused in-block)
        k_pool_c<<<N_, 256>>>(I.g2, I.be2, I.a2, I.w_r + r * HID_, r);
    }

    // pool over relations, then feed-forward head
    k_pool_global<<<N_ / 8, 256>>>(I.w_g);
    gemm2_kernel<256, 16, false, true><<<dim3(HID_ / BN2, N_ / 256, 1), 256>>>(
        phf, HID_, 0, N_, HID_,
        I.Wf1, HID_, 0,
        I.bf1, 0,
        px1, HID_, 0, HID_,             // reuse g_x1 as z buffer
        nullptr, nullptr, nullptr, 0, I.af);
    gemm2_kernel<128, 8, false, false><<<dim3(1, N_ / 128, 1), 256>>>(
        px1, HID_, 0, N_, HID_,
        I.Wf2, OUT_, 0,
        I.bf2, 0,
        (float*)d_out, OUT_, 0, OUT_,
        nullptr, nullptr, nullptr, 0, nullptr);
}

// round 6
// speedup vs baseline: 1.0061x; 1.0061x over previous
#include <cuda_runtime.h>
#include <math.h>

// ---------------- problem dims ----------------
#define R_   2
#define K_   3
#define N_   16384
#define V_   256
#define E_   1
#define L_   8
#define VE_  128
#define LK_  1
#define OUT_ 64
#define IN_  256
#define HID_ 512
#define C_   5
#define CH_  (C_*HID_)   // 2560

// ---------------- workspace (device globals; no runtime alloc) ----------------
__device__ float g_x1[(size_t)N_ * CH_];          // per-r activations stage 1
__device__ float g_x2[(size_t)N_ * CH_];          // per-r activations stage 2
__device__ float g_outr[(size_t)R_ * N_ * HID_];  // per-relation pooled output
__device__ float g_hfin[(size_t)N_ * HID_];       // globally pooled
__device__ float g_xp[(size_t)R_ * N_ * VE_];     // pooled extra raw feats
__device__ float g_stats1[N_ * 2];                // LN1 mean/rstd per row
__device__ float g_u[R_ * VE_];                   // extra_emb @ w_extra
__device__ float g_Wraw[(size_t)R_ * K_ * V_ * HID_];   // femb @ W1[c], c<3
__device__ float g_Wex [(size_t)R_ * VE_ * HID_];       // extra_emb @ W1[3]
__device__ float g_Wlab[(size_t)R_ * OUT_ * HID_];      // label_emb @ W1[4]

// =========================================================================
// Packed-f32x2 (FFMA2) tiled GEMM. BN=128, BK=16, TN=8 fixed; BM/TM template.
// C[M,Ncols] = op_A(A[M,Kd]) @ B[Kd,Ncols] (+bias) (opt. PReLU out)
// op_A (LN_A): a' = prelu((a - mean[row])*rstd[row]*gamma[k] + beta[k], alpha)
// Requires Kd % 16 == 0 and Ncols % 4 == 0 (all call sites satisfy this).
// =========================================================================
constexpr int BN2 = 128, BK2 = 16, TN2 = 8;

template<int BM, int TM, bool LN_A, bool PRELU_OUT>
__device__ __forceinline__ void gemm2_core(
    const float* __restrict__ A, int lda, int M, int Kd,
    const float* __restrict__ B, int ldb,
    const float* __restrict__ bias,
    float* __restrict__ Co, int ldc, int Ncols,
    const float* __restrict__ stats,
    const float* __restrict__ gamma,
    const float* __restrict__ beta,
    const float* __restrict__ alpha_p)
{
    constexpr int TX = BN2 / TN2;                 // 16
    constexpr int TY = BM / TM;
    constexpr int THREADS = TX * TY;              // 256
    constexpr int A4 = BM * (BK2 / 4) / THREADS;  // float4 per thread (A tile)
    constexpr int B4 = BK2 * (BN2 / 4) / THREADS; // float4 per thread (B tile)

    // pad so row stride (BM+4) is float4-aligned; A-tile stores are 2-way
    // bank-conflicted (stride*4 mod 32 == 16) which costs ~6% of compute.
    __shared__ __align__(16) float As[BK2][BM + 4];
    __shared__ __align__(16) float Bs[BK2][BN2];

    const int tid  = threadIdx.x;
    const int tx   = tid % TX;
    const int ty   = tid / TX;
    const int row0 = blockIdx.y * BM;
    const int col0 = blockIdx.x * BN2;

    float alpha = 0.f;
    if constexpr (LN_A || PRELU_OUT) alpha = __ldg(alpha_p);

    unsigned long long acc[TM][TN2 / 2];
    #pragma unroll
    for (int i = 0; i < TM; i++)
        #pragma unroll
        for (int j = 0; j < TN2 / 2; j++) acc[i][j] = 0ull;  // bit pattern = (0.f,0.f)

    float4 ra[A4], rb[B4];

    // ---- global -> registers (with optional fused LN+PReLU on A) ----
    auto load_tiles = [&](int k0) {
        #pragma unroll
        for (int q = 0; q < A4; q++) {
            int v  = tid + q * THREADS;
            int r  = v / (BK2 / 4);
            int kq = (v % (BK2 / 4)) * 4;
            int gr = row0 + r;
            float4 val = make_float4(0.f, 0.f, 0.f, 0.f);
            if (gr < M) {
                val = *reinterpret_cast<const float4*>(A + (size_t)gr * lda + k0 + kq);
                if constexpr (LN_A) {
                    float mn = stats[2 * gr], rs = stats[2 * gr + 1];
                    float4 gm = *reinterpret_cast<const float4*>(gamma + k0 + kq);
                    float4 bt = *reinterpret_cast<const float4*>(beta  + k0 + kq);
                    val.x = (val.x - mn) * rs * gm.x + bt.x;
                    val.y = (val.y - mn) * rs * gm.y + bt.y;
                    val.z = (val.z - mn) * rs * gm.z + bt.z;
                    val.w = (val.w - mn) * rs * gm.w + bt.w;
                    val.x = val.x >= 0.f ? val.x : alpha * val.x;
                    val.y = val.y >= 0.f ? val.y : alpha * val.y;
                    val.z = val.z >= 0.f ? val.z : alpha * val.z;
                    val.w = val.w >= 0.f ? val.w : alpha * val.w;
                }
            }
            ra[q] = val;
        }
        #pragma unroll
        for (int q = 0; q < B4; q++) {
            int v  = tid + q * THREADS;
            int r  = v / (BN2 / 4);
            int c4 = (v % (BN2 / 4)) * 4;
            int gc = col0 + c4;
            float4 val = make_float4(0.f, 0.f, 0.f, 0.f);
            if (gc < Ncols)
                val = *reinterpret_cast<const float4*>(B + (size_t)(k0 + r) * ldb + gc);
            rb[q] = val;
        }
    };
    // ---- registers -> shared ----
    auto store_tiles = [&]() {
        #pragma unroll
        for (int q = 0; q < A4; q++) {
            int v  = tid + q * THREADS;
            int r  = v / (BK2 / 4);
            int kq = (v % (BK2 / 4)) * 4;
            As[kq + 0][r] = ra[q].x;
            As[kq + 1][r] = ra[q].y;
            As[kq + 2][r] = ra[q].z;
            As[kq + 3][r] = ra[q].w;
        }
        #pragma unroll
        for (int q = 0; q < B4; q++) {
            int v  = tid + q * THREADS;
            int r  = v / (BN2 / 4);
            int c4 = (v % (BN2 / 4)) * 4;
            *reinterpret_cast<float4*>(&Bs[r][c4]) = rb[q];
        }
    };

    load_tiles(0);
    store_tiles();
    __syncthreads();

    for (int k0 = 0; k0 < Kd; k0 += BK2) {
        bool more = (k0 + BK2) < Kd;
        if (more) load_tiles(k0 + BK2);   // register prefetch overlaps compute

        #pragma unroll
        for (int kk = 0; kk < BK2; kk++) {
            float a[TM];
            #pragma unroll
            for (int i = 0; i < TM; i += 4) {
                float4 t = *reinterpret_cast<const float4*>(&As[kk][ty * TM + i]);
                a[i] = t.x; a[i + 1] = t.y; a[i + 2] = t.z; a[i + 3] = t.w;
            }
            unsigned long long b2[TN2 / 2];
            {
                const ulonglong2* bp =
                    reinterpret_cast<const ulonglong2*>(&Bs[kk][tx * TN2]);
                ulonglong2 t0 = bp[0], t1 = bp[1];
                b2[0] = t0.x; b2[1] = t0.y; b2[2] = t1.x; b2[3] = t1.y;
            }
            #pragma unroll
            for (int i = 0; i < TM; i++) {
                unsigned long long a2;
                asm("mov.b64 %0, {%1, %1};" : "=l"(a2) : "f"(a[i]));
                #pragma unroll
                for (int j = 0; j < TN2 / 2; j++)
                    asm("fma.rn.f32x2 %0, %1, %2, %0;"
                        : "+l"(acc[i][j]) : "l"(a2), "l"(b2[j]));
            }
        }
        __syncthreads();
        if (more) { store_tiles(); __syncthreads(); }
    }

    // ---- epilogue: unpack, bias, optional PReLU ----
    #pragma unroll
    for (int i = 0; i < TM; i++) {
        int gr = row0 + ty * TM + i;
        if (gr >= M) continue;
        float* crow = Co + (size_t)gr * ldc;
        #pragma unroll
        for (int j = 0; j < TN2 / 2; j++) {
            float lo, hi;
            asm("mov.b64 {%0, %1}, %2;" : "=f"(lo), "=f"(hi) : "l"(acc[i][j]));
            int gc = col0 + tx * TN2 + 2 * j;
            if (gc < Ncols) {
                float v0 = lo;
                if (bias) v0 += bias[gc];
                if constexpr (PRELU_OUT) v0 = v0 >= 0.f ? v0 : alpha * v0;
                crow[gc] = v0;
            }
            if (gc + 1 < Ncols) {
                float v1 = hi;
                if (bias) v1 += bias[gc + 1];
                if constexpr (PRELU_OUT) v1 = v1 >= 0.f ? v1 : alpha * v1;
                crow[gc + 1] = v1;
            }
        }
    }
}

template<int BM, int TM, bool LN_A, bool PRELU_OUT>
__global__ void __launch_bounds__(256, 1) gemm2_kernel(
    const float* __restrict__ A, int lda, long long aZ, int M, int Kd,
    const float* __restrict__ B, int ldb, long long bZ,
    const float* __restrict__ bias, long long biasZ,
    float* __restrict__ Co, int ldc, long long cZ, int Ncols,
    const float* __restrict__ stats,
    const float* __restrict__ gamma, const float* __restrict__ beta, long long gZ,
    const float* __restrict__ alpha_p)
{
    long long z = blockIdx.z;
    gemm2_core<BM, TM, LN_A, PRELU_OUT>(
        A + z * aZ, lda, M, Kd,
        B + z * bZ, ldb,
        bias ? bias + z * biasZ : nullptr,
        Co + z * cZ, ldc, Ncols,
        stats,
        gamma ? gamma + z * gZ : nullptr,
        beta  ? beta  + z * gZ : nullptr,
        alpha_p);
}

// ---------------- plain fp32 GEMM core (kept for tiny weight-fusion GEMMs) ----
constexpr int BN = 128, BK = 16, TN = 8;

template<int BM, int TM>
__device__ __forceinline__ void gemm_core(
    const float* __restrict__ A, int lda, int M, int Kd,
    const float* __restrict__ B, int ldb,
    float* __restrict__ Co, int ldc, int Ncols)
{
    constexpr int TX = BN / TN;
    constexpr int TY = BM / TM;
    constexpr int THREADS = TX * TY;

    __shared__ __align__(16) float As[BK][BM + 4];
    __shared__ __align__(16) float Bs[BK][BN];

    const int tid  = threadIdx.x;
    const int tx   = tid % TX;
    const int ty   = tid / TX;
    const int row0 = blockIdx.y * BM;
    const int col0 = blockIdx.x * BN;

    float acc[TM][TN];
    #pragma unroll
    for (int i = 0; i < TM; i++)
        #pragma unroll
        for (int j = 0; j < TN; j++) acc[i][j] = 0.f;

    for (int k0 = 0; k0 < Kd; k0 += BK) {
        for (int v = tid; v < BM * (BK / 4); v += THREADS) {
            int r  = v / (BK / 4);
            int kq = (v % (BK / 4)) * 4;
            int gr = row0 + r;
            float4 val = make_float4(0.f, 0.f, 0.f, 0.f);
            if (gr < M)
                val = *reinterpret_cast<const float4*>(A + (size_t)gr * lda + k0 + kq);
            As[kq + 0][r] = val.x;
            As[kq + 1][r] = val.y;
            As[kq + 2][r] = val.z;
            As[kq + 3][r] = val.w;
        }
        for (int v = tid; v < BK * (BN / 4); v += THREADS) {
            int r  = v / (BN / 4);
            int c4 = (v % (BN / 4)) * 4;
            int gc = col0 + c4;
            float4 val = make_float4(0.f, 0.f, 0.f, 0.f);
            if (gc < Ncols)
                val = *reinterpret_cast<const float4*>(B + (size_t)(k0 + r) * ldb + gc);
            *reinterpret_cast<float4*>(&Bs[r][c4]) = val;
        }
        __syncthreads();
        #pragma unroll
        for (int kk = 0; kk < BK; kk++) {
            float a[TM], b[TN];
            #pragma unroll
            for (int i = 0; i < TM; i += 4) {
                float4 t = *reinterpret_cast<const float4*>(&As[kk][ty * TM + i]);
                a[i] = t.x; a[i + 1] = t.y; a[i + 2] = t.z; a[i + 3] = t.w;
            }
            #pragma unroll
            for (int j = 0; j < TN; j += 4) {
                float4 t = *reinterpret_cast<const float4*>(&Bs[kk][tx * TN + j]);
                b[j] = t.x; b[j + 1] = t.y; b[j + 2] = t.z; b[j + 3] = t.w;
            }
            #pragma unroll
            for (int i = 0; i < TM; i++)
                #pragma unroll
                for (int j = 0; j < TN; j++)
                    acc[i][j] += a[i] * b[j];
        }
        __syncthreads();
    }
    #pragma unroll
    for (int i = 0; i < TM; i++) {
        int gr = row0 + ty * TM + i;
        if (gr >= M) continue;
        float* crow = Co + (size_t)gr * ldc;
        #pragma unroll
        for (int j = 0; j < TN; j++) {
            int gc = col0 + tx * TN + j;
            if (gc < Ncols) crow[gc] = acc[i][j];
        }
    }
}

// ---------------- fused-weight precompute: emb @ W1[c] (10 small GEMMs) --------
__global__ void __launch_bounds__(256, 2) fuse_weights_kernel(
    const float* __restrict__ femb, const float* __restrict__ eemb,
    const float* __restrict__ lemb, const float* __restrict__ W1)
{
    int z = blockIdx.z;            // 0..9 -> (r, c)
    int r = z / C_, c = z % C_;
    const float* Ap; int M; float* out;
    if (c < K_) {
        Ap = femb + (size_t)(r * K_ + c) * V_ * IN_;  M = V_;
        out = g_Wraw + (size_t)(r * K_ + c) * V_ * HID_;
    } else if (c == 3) {
        Ap = eemb + (size_t)r * VE_ * IN_;            M = VE_;
        out = g_Wex + (size_t)r * VE_ * HID_;
    } else {
        Ap = lemb + (size_t)r * OUT_ * IN_;           M = OUT_;
        out = g_Wlab + (size_t)r * OUT_ * HID_;
    }
    const float* Bp = W1 + (size_t)c * IN_ * HID_;
    gemm_core<64, 4>(Ap, IN_, M, IN_, Bp, HID_, out, HID_, HID_);
}

// ---------------- u[r][v] = extra_emb[r,0,v,:] . w_extra[0,:] ----------------
__global__ void k_u(const float* __restrict__ eemb, const float* __restrict__ w_extra)
{
    int t = blockIdx.x * blockDim.x + threadIdx.x;
    if (t >= R_ * VE_) return;
    int r = t / VE_, v = t % VE_;
    const float* row = eemb + ((size_t)r * VE_ + v) * IN_;
    float s = 0.f;
    for (int d = 0; d < IN_; d++) s += row[d] * w_extra[d];
    g_u[t] = s;
}

// ---------------- extra-feature attention pool in raw space (warp per (r,n)) ---
__global__ void __launch_bounds__(256) k_extra_pool(const float* __restrict__ extra)
{
    int wg   = (blockIdx.x * blockDim.x + threadIdx.x) >> 5;
    int lane = threadIdx.x & 31;
    if (wg >= R_ * N_) return;
    int r = wg / N_, n = wg % N_;
    const float* base = extra + (size_t)(r * N_ + n) * (L_ * VE_);

    float u[4];
    #pragma unroll
    for (int j = 0; j < 4; j++) u[j] = g_u[r * VE_ + lane + 32 * j];

    float x[L_][4];
    float s[L_];
    #pragma unroll
    for (int l = 0; l < L_; l++) {
        float p = 0.f;
        #pragma unroll
        for (int j = 0; j < 4; j++) {
            x[l][j] = base[l * VE_ + lane + 32 * j];
            p += x[l][j] * u[j];
        }
        #pragma unroll
        for (int o = 16; o > 0; o >>= 1) p += __shfl_xor_sync(0xffffffffu, p, o);
        s[l] = 1.f / (1.f + expf(-p));           // sigmoid
    }
    float mx = s[0];
    #pragma unroll
    for (int l = 1; l < L_; l++) mx = fmaxf(mx, s[l]);
    float e[L_], esum = 0.f;
    #pragma unroll
    for (int l = 0; l < L_; l++) { e[l] = expf(s[l] - mx); esum += e[l]; }
    float inv = 1.f / esum;

    float out[4] = {0.f, 0.f, 0.f, 0.f};
    #pragma unroll
    for (int l = 0; l < L_; l++) {
        float w = e[l] * inv;
        #pragma unroll
        for (int j = 0; j < 4; j++) out[j] += w * x[l][j];
    }
    float* op = g_xp + (size_t)(r * N_ + n) * VE_;
    #pragma unroll
    for (int j = 0; j < 4; j++) op[lane + 32 * j] = out[j];
}

// ---------------- LayerNorm stats over [C,HID] per row (warp per row) ----------
__global__ void __launch_bounds__(256) k_stats(const float* __restrict__ X, float* __restrict__ stats)
{
    int w    = (blockIdx.x * blockDim.x + threadIdx.x) >> 5;
    int lane = threadIdx.x & 31;
    if (w >= N_) return;
    const float4* row = reinterpret_cast<const float4*>(X + (size_t)w * CH_);
    float s = 0.f, s2 = 0.f;
    for (int v = lane; v < CH_ / 4; v += 32) {
        float4 t = row[v];
        s  += t.x + t.y + t.z + t.w;
        s2 += t.x * t.x + t.y * t.y + t.z * t.z + t.w * t.w;
    }
    #pragma unroll
    for (int o = 16; o > 0; o >>= 1) {
        s  += __shfl_xor_sync(0xffffffffu, s,  o);
        s2 += __shfl_xor_sync(0xffffffffu, s2, o);
    }
    if (lane == 0) {
        float m   = s / (float)CH_;
        float var = s2 / (float)CH_ - m * m;
        stats[2 * w]     = m;
        stats[2 * w + 1] = rsqrtf(var + 1e-5f);
    }
}

// ---------------- channel attention pool (block per n) -------------------------
// Computes LN2 stats in-block (no separate stats pass), then LN2+PReLU,
// sigmoid-softmax over C, weighted sum -> g_outr.
__global__ void __launch_bounds__(256) k_pool_c(
    const float* __restrict__ g2, const float* __restrict__ be2,
    const float* __restrict__ a2p, const float* __restrict__ wr, int r)
{
    int n = blockIdx.x, tid = threadIdx.x;
    __shared__ __align__(16) float sx[CH_];
    __shared__ float red[C_][8];
    __shared__ float rsum[8], rsum2[8];
    __shared__ float salpha[C_];
    __shared__ float smn, srs;

    const float* xr = g_x2 + (size_t)n * CH_;

    // load row + accumulate sum / sumsq
    float s = 0.f, s2 = 0.f;
    for (int i = tid; i < CH_ / 4; i += 256) {
        float4 t = reinterpret_cast<const float4*>(xr)[i];
        reinterpret_cast<float4*>(sx)[i] = t;
        s  += t.x + t.y + t.z + t.w;
        s2 += t.x * t.x + t.y * t.y + t.z * t.z + t.w * t.w;
    }
    int lane = tid & 31, wid = tid >> 5;
    #pragma unroll
    for (int o = 16; o > 0; o >>= 1) {
        s  += __shfl_xor_sync(0xffffffffu, s,  o);
        s2 += __shfl_xor_sync(0xffffffffu, s2, o);
    }
    if (lane == 0) { rsum[wid] = s; rsum2[wid] = s2; }
    __syncthreads();
    if (tid == 0) {
        float ts = 0.f, ts2 = 0.f;
        #pragma unroll
        for (int w2 = 0; w2 < 8; w2++) { ts += rsum[w2]; ts2 += rsum2[w2]; }
        float m   = ts / (float)CH_;
        float var = ts2 / (float)CH_ - m * m;
        smn = m;
        srs = rsqrtf(var + 1e-5f);
    }
    __syncthreads();

    float mn = smn, rs = srs, a = __ldg(a2p);
    for (int i = tid; i < CH_; i += 256) {
        float v = (sx[i] - mn) * rs * g2[i] + be2[i];
        sx[i] = v >= 0.f ? v : a * v;
    }
    __syncthreads();

    float p[C_] = {0.f, 0.f, 0.f, 0.f, 0.f};
    for (int h = tid; h < HID_; h += 256) {
        float w = wr[h];
        #pragma unroll
        for (int c = 0; c < C_; c++) p[c] += sx[c * HID_ + h] * w;
    }
    #pragma unroll
    for (int c = 0; c < C_; c++) {
        #pragma unroll
        for (int o = 16; o > 0; o >>= 1) p[c] += __shfl_xor_sync(0xffffffffu, p[c], o);
    }
    if (lane == 0) {
        #pragma unroll
        for (int c = 0; c < C_; c++) red[c][wid] = p[c];
    }
    __syncthreads();
    if (tid == 0) {
        float sv[C_];
        float mx = -1e30f;
        #pragma unroll
        for (int c = 0; c < C_; c++) {
            float t = 0.f;
            #pragma unroll
            for (int w2 = 0; w2 < 8; w2++) t += red[c][w2];
            sv[c] = 1.f / (1.f + expf(-t));
            mx = fmaxf(mx, sv[c]);
        }
        float esum = 0.f, e[C_];
        #pragma unroll
        for (int c = 0; c < C_; c++) { e[c] = expf(sv[c] - mx); esum += e[c]; }
        float inv = 1.f / esum;
        #pragma unroll
        for (int c = 0; c < C_; c++) salpha[c] = e[c] * inv;
    }
    __syncthreads();

    float* op = g_outr + (size_t)r * N_ * HID_ + (size_t)n * HID_;
    for (int h = tid; h < HID_; h += 256) {
        float acc = 0.f;
        #pragma unroll
        for (int c = 0; c < C_; c++) acc += salpha[c] * sx[c * HID_ + h];
        op[h] = acc;
    }
}

// ---------------- global (over R) attention pool (warp per n) ------------------
__global__ void __launch_bounds__(256) k_pool_global(const float* __restrict__ wg)
{
    int w    = (blockIdx.x * blockDim.x + threadIdx.x) >> 5;
    int lane = threadIdx.x & 31;
    if (w >= N_) return;
    const float* pa = g_outr + (size_t)w * HID_;
    const float* pb = g_outr + (size_t)N_ * HID_ + (size_t)w * HID_;
    float a[16], b[16], wv[16];
    float sa = 0.f, sb = 0.f;
    #pragma unroll
    for (int j = 0; j < 16; j++) {
        int h = lane + 32 * j;
        a[j] = pa[h]; b[j] = pb[h]; wv[j] = wg[h];
        sa += a[j] * wv[j]; sb += b[j] * wv[j];
    }
    #pragma unroll
    for (int o = 16; o > 0; o >>= 1) {
        sa += __shfl_xor_sync(0xffffffffu, sa, o);
        sb += __shfl_xor_sync(0xffffffffu, sb, o);
    }
    sa = 1.f / (1.f + expf(-sa));
    sb = 1.f / (1.f + expf(-sb));
    float mx = fmaxf(sa, sb);
    float ea = expf(sa - mx), eb = expf(sb - mx);
    float aa = ea / (ea + eb);
    float ab = 1.f - aa;
    float* op = g_hfin + (size_t)w * HID_;
    #pragma unroll
    for (int j = 0; j < 16; j++) op[lane + 32 * j] = aa * a[j] + ab * b[j];
}

// ---------------- input mapping (resolved from size signature at launch) -------
struct Ins {
    const float *raw, *extra, *label, *femb, *eemb, *lemb;
    const float *w_extra, *w_r, *w_g;
    const float *W1, *b1, *g1, *be1, *a1, *W2, *b2, *g2, *be2, *a2;
    const float *Wf1, *bf1, *af, *Wf2, *bf2;
};

static void resolve(void* const* d_in, const int* sz, Ins& I)
{
    auto F = [&](int i) { return (const float*)d_in[i]; };
    if (sz[0] == R_ * K_ * N_ * V_) {
        I.raw = F(0);  I.extra = F(1);  I.label = F(2);
        I.femb = F(3); I.eemb = F(4);   I.lemb = F(5);
        I.w_extra = F(6); I.w_r = F(7); I.w_g = F(8);
        I.W1 = F(9);  I.b1 = F(10); I.g1 = F(11); I.be1 = F(12); I.a1 = F(13);
        I.W2 = F(14); I.b2 = F(15); I.g2 = F(16); I.be2 = F(17); I.a2 = F(18);
        I.Wf1 = F(19); I.bf1 = F(20); I.af = F(21); I.Wf2 = F(22); I.bf2 = F(23);
    } else {
        // sorted-key order
        I.W1 = F(0);  I.W2 = F(1);  I.Wf1 = F(2); I.Wf2 = F(3);
        I.a1 = F(4);  I.a2 = F(5);  I.af = F(6);
        I.b1 = F(7);  I.b2 = F(8);  I.be1 = F(9); I.be2 = F(10);
        I.bf1 = F(11); I.bf2 = F(12);
        I.eemb = F(13); I.extra = F(14); I.femb = F(15);
        I.g1 = F(16); I.g2 = F(17);
        I.lemb = F(18); I.label = F(19); I.raw = F(20);
        I.w_extra = F(21); I.w_g = F(22); I.w_r = F(23);
    }
}

extern "C" void kernel_launch(void* const* d_in, const int* in_sizes, int n_in,
                              void* d_out, int out_size)
{
    if (n_in < 24) return;
    Ins I;
    resolve(d_in, in_sizes, I);

    float *px1, *px2, *pxp, *pWraw, *pWex, *pWlab, *ps1, *phf;
    cudaGetSymbolAddress((void**)&px1,   g_x1);
    cudaGetSymbolAddress((void**)&px2,   g_x2);
    cudaGetSymbolAddress((void**)&pxp,   g_xp);
    cudaGetSymbolAddress((void**)&pWraw, g_Wraw);
    cudaGetSymbolAddress((void**)&pWex,  g_Wex);
    cudaGetSymbolAddress((void**)&pWlab, g_Wlab);
    cudaGetSymbolAddress((void**)&ps1,   g_stats1);
    cudaGetSymbolAddress((void**)&phf,   g_hfin);

    // prolog: u vectors, fused W1 weights, extra pooling (reads extra_feats once)
    k_u<<<1, 256>>>(I.eemb, I.w_extra);
    fuse_weights_kernel<<<dim3(4, 4, 10), 256>>>(I.femb, I.eemb, I.lemb, I.W1);
    k_extra_pool<<<(R_ * N_) / 8, 256>>>(I.extra);

    for (int r = 0; r < R_; r++) {
        // x1: channels 0..2 (raw @ fused weights), batched over z
        gemm2_kernel<256, 16, false, false><<<dim3(HID_ / BN2, N_ / 256, K_), 256>>>(
            I.raw + (size_t)r * K_ * N_ * V_, V_, (long long)N_ * V_, N_, V_,
            pWraw + (size_t)r * K_ * V_ * HID_, HID_, (long long)V_ * HID_,
            I.b1, HID_,
            px1, CH_, HID_, HID_,
            nullptr, nullptr, nullptr, 0, nullptr);
        // x1: channel 3 (pooled extra @ fused weights), K=128
        gemm2_kernel<128, 8, false, false><<<dim3(HID_ / BN2, N_ / 128, 1), 256>>>(
            pxp + (size_t)r * N_ * VE_, VE_, 0, N_, VE_,
            pWex + (size_t)r * VE_ * HID_, HID_, 0,
            I.b1 + 3 * HID_, 0,
            px1 + 3 * HID_, CH_, 0, HID_,
            nullptr, nullptr, nullptr, 0, nullptr);
        // x1: channel 4 (label @ fused weights), K=64
        gemm2_kernel<128, 8, false, false><<<dim3(HID_ / BN2, N_ / 128, 1), 256>>>(
            I.label + (size_t)r * N_ * OUT_, OUT_, 0, N_, OUT_,
            pWlab + (size_t)r * OUT_ * HID_, HID_, 0,
            I.b1 + 4 * HID_, 0,
            px1 + 4 * HID_, CH_, 0, HID_,
            nullptr, nullptr, nullptr, 0, nullptr);

        // LN1 stats; x2 = prelu(LN(x1)) @ W2 + b2  (LN+PReLU fused into A-load)
        k_stats<<<N_ / 8, 256>>>(px1, ps1);
        gemm2_kernel<256, 16, true, false><<<dim3(HID_ / BN2, N_ / 256, C_), 256>>>(
            px1, CH_, (long long)HID_, N_, HID_,
            I.W2, HID_, (long long)HID_ * HID_,
            I.b2, HID_,
            px2, CH_, HID_, HID_,
            ps1, I.g1, I.be1, HID_, I.a1);

        // per-n channel attention pool (LN2 stats + LN2 + PReLU fused in-block)
        k_pool_c<<<N_, 256>>>(I.g2, I.be2, I.a2, I.w_r + r * HID_, r);
    }

    // pool over relations, then feed-forward head
    k_pool_global<<<N_ / 8, 256>>>(I.w_g);
    gemm2_kernel<256, 16, false, true><<<dim3(HID_ / BN2, N_ / 256, 1), 256>>>(
        phf, HID_, 0, N_, HID_,
        I.Wf1, HID_, 0,
        I.bf1, 0,
        px1, HID_, 0, HID_,             // reuse g_x1 as z buffer
        nullptr, nullptr, nullptr, 0, I.af);
    gemm2_kernel<128, 8, false, false><<<dim3(1, N_ / 128, 1), 256>>>(
        px1, HID_, 0, N_, HID_,
        I.Wf2, OUT_, 0,
        I.bf2, 0,
        (float*)d_out, OUT_, 0, OUT_,
        nullptr, nullptr, nullptr, 0, nullptr);
}

// round 8
// speedup vs baseline: 1.7570x; 1.7463x over previous
#include <cuda_runtime.h>
#include <cuda_bf16.h>
#include <math.h>

#define R_   2
#define K_   3
#define N_   16384
#define V_   256
#define L_   8
#define VE_  128
#define OUT_ 64
#define IN_  256
#define HID_ 512
#define C_   5
#define CH_  (C_*HID_)

// ---------------- fp32 workspace ----------------
__device__ float g_x1[(size_t)N_ * CH_];
__device__ float g_x2[(size_t)N_ * CH_];
__device__ float g_outr[(size_t)R_ * N_ * HID_];
__device__ float g_hfin[(size_t)N_ * HID_];
__device__ float g_xp[(size_t)R_ * N_ * VE_];
__device__ float g_stats1[N_ * 2];
__device__ float g_u[R_ * VE_];
__device__ float g_Wraw[(size_t)R_ * K_ * V_ * HID_];
__device__ float g_Wex [(size_t)R_ * VE_ * HID_];
__device__ float g_Wlab[(size_t)R_ * OUT_ * HID_];

// ---------------- bf16 split workspace ----------------
__device__ __align__(16) __nv_bfloat16 g_rawA[(size_t)R_ * K_ * N_ * (3*V_)];
__device__ __align__(16) __nv_bfloat16 g_labA[(size_t)R_ * N_ * (3*OUT_)];
__device__ __align__(16) __nv_bfloat16 g_xpA [(size_t)R_ * N_ * (3*VE_)];
__device__ __align__(16) __nv_bfloat16 g_x1A [(size_t)C_ * N_ * (3*HID_)];
__device__ __align__(16) __nv_bfloat16 g_hfA [(size_t)N_ * (3*HID_)];
__device__ __align__(16) __nv_bfloat16 g_ff1A[(size_t)N_ * (3*HID_)];
__device__ __align__(16) __nv_bfloat16 g_W2T  [(size_t)C_ * HID_ * (3*HID_)];
__device__ __align__(16) __nv_bfloat16 g_WrawT[(size_t)R_ * K_ * HID_ * (3*V_)];
__device__ __align__(16) __nv_bfloat16 g_WexT [(size_t)R_ * HID_ * (3*VE_)];
__device__ __align__(16) __nv_bfloat16 g_WlabT[(size_t)R_ * HID_ * (3*OUT_)];
__device__ __align__(16) __nv_bfloat16 g_Wf1T [(size_t)HID_ * (3*HID_)];
__device__ __align__(16) __nv_bfloat16 g_Wf2T [(size_t)OUT_ * (3*HID_)];

// ---------------- PTX helpers (base-target features only) ----------------
__device__ __forceinline__ unsigned smem_u32(const void* p) {
    unsigned a;
    asm("{ .reg .u64 t; cvta.to.shared.u64 t, %1; cvt.u32.u64 %0, t; }" : "=r"(a) : "l"(p));
    return a;
}
__device__ __forceinline__ void cp16(unsigned dst, const void* src) {
    asm volatile("cp.async.cg.shared.global [%0], [%1], 16;" :: "r"(dst), "l"(src) : "memory");
}
__device__ __forceinline__ void ldsm4(unsigned* r, unsigned addr) {
    asm volatile("ldmatrix.sync.aligned.m8n8.x4.shared.b16 {%0,%1,%2,%3}, [%4];"
        : "=r"(r[0]), "=r"(r[1]), "=r"(r[2]), "=r"(r[3]) : "r"(addr));
}
__device__ __forceinline__ void mma16816(float* d, const unsigned* a, const unsigned* b) {
    asm volatile(
        "mma.sync.aligned.m16n8k16.row.col.f32.bf16.bf16.f32 "
        "{%0,%1,%2,%3}, {%4,%5,%6,%7}, {%8,%9}, {%0,%1,%2,%3};"
        : "+f"(d[0]), "+f"(d[1]), "+f"(d[2]), "+f"(d[3])
        : "r"(a[0]), "r"(a[1]), "r"(a[2]), "r"(a[3]), "r"(b[0]), "r"(b[1]));
}

// =========================================================================
// bf16 tensor-core GEMM via mma.sync: C[M,Ncols] = A[M,Kpp] @ B[Ncols,Kpp]^T
// A row-major [M,Kpp], B row-major [Ncols,Kpp] (K-major both). +bias, +PReLU.
// CTA: 128 x BN, 8 warps (4 along M x 2 along N), BK=32, 3-stage cp.async.
// =========================================================================
template<int BN>
__global__ void __launch_bounds__(256, 1) k_tc_gemm(
    const __nv_bfloat16* __restrict__ A, long long aZ, int ldA,
    const __nv_bfloat16* __restrict__ B, long long bZ, int ldB, int Kpp,
    const float* __restrict__ bias, long long biasZ,
    float* __restrict__ Co, int ldc, long long cZ,
    const float* __restrict__ alpha_p)
{
    constexpr int BM = 128, BK = 32, LDS = 40;          // LDS in bf16 (80B row)
    constexpr int WN  = BN / 2;                          // per-warp N tile
    constexpr int NT8 = WN / 8;                          // n8 tiles per warp
    constexpr int ABYTES = BM * LDS * 2;
    constexpr int BBYTES = BN * LDS * 2;
    constexpr int STAGE  = ABYTES + BBYTES;

    extern __shared__ char smem[];
    const int tid = threadIdx.x, lane = tid & 31, wid = tid >> 5;
    const int warp_m = wid & 3, warp_n = wid >> 2;
    const int m0 = blockIdx.y * BM, n0 = blockIdx.x * BN;
    const long long z = blockIdx.z;
    const __nv_bfloat16* Az = A + z * aZ;
    const __nv_bfloat16* Bz = B + z * bZ;
    float* Cz = Co + z * cZ;
    const float* biasz = bias ? bias + z * biasZ : nullptr;

    const unsigned sb = smem_u32(smem);
    const int nkb = Kpp / BK;

    float acc[2][NT8][4];
    #pragma unroll
    for (int mt = 0; mt < 2; mt++)
        #pragma unroll
        for (int nt = 0; nt < NT8; nt++)
            #pragma unroll
            for (int j = 0; j < 4; j++) acc[mt][nt][j] = 0.f;

    auto load = [&](int kb) {
        if (kb < nkb) {
            unsigned ab = sb + (unsigned)(kb % 3) * STAGE;
            unsigned bb = ab + ABYTES;
            int k0 = kb * BK;
            #pragma unroll
            for (int q = 0; q < (BM * 4) / 256; q++) {
                int ch = tid + q * 256;
                int row = ch >> 2, c = ch & 3;
                cp16(ab + row * (LDS * 2) + c * 16,
                     Az + (size_t)(m0 + row) * ldA + k0 + c * 8);
            }
            #pragma unroll
            for (int q = 0; q < (BN * 4) / 256; q++) {
                int ch = tid + q * 256;
                int row = ch >> 2, c = ch & 3;
                cp16(bb + row * (LDS * 2) + c * 16,
                     Bz + (size_t)(n0 + row) * ldB + k0 + c * 8);
            }
        }
        asm volatile("cp.async.commit_group;" ::: "memory");
    };

    load(0); load(1); load(2);

    for (int kb = 0; kb < nkb; kb++) {
        asm volatile("cp.async.wait_group 2;" ::: "memory");
        __syncthreads();
        unsigned ab = sb + (unsigned)(kb % 3) * STAGE;
        unsigned bb = ab + ABYTES;

        #pragma unroll
        for (int ks = 0; ks < 2; ks++) {
            int k0 = ks * 16;
            unsigned af[2][4], bf[NT8 / 2][4];
            // A fragments: x4 over 16x16; lanes 0-15 rows, lane>>4 selects k half
            {
                int row = warp_m * 32 + (lane & 15);
                int kc  = k0 + (lane >> 4) * 8;
                #pragma unroll
                for (int mt = 0; mt < 2; mt++)
                    ldsm4(af[mt], ab + (row + mt * 16) * (LDS * 2) + kc * 2);
            }
            // B fragments: x4 = {(n+0..7,k0),(n+0..7,k0+8),(n+8..15,k0),(n+8..15,k0+8)}
            {
                int rowi = lane & 7, quad = lane >> 3;
                int nofs = (quad >> 1) * 8, kofs = (quad & 1) * 8;
                #pragma unroll
                for (int j = 0; j < NT8 / 2; j++) {
                    int nb = warp_n * WN + j * 16 + nofs + rowi;
                    ldsm4(bf[j], bb + nb * (LDS * 2) + (k0 + kofs) * 2);
                }
            }
            #pragma unroll
            for (int mt = 0; mt < 2; mt++)
                #pragma unroll
                for (int nt = 0; nt < NT8; nt++)
                    mma16816(acc[mt][nt], af[mt], &bf[nt >> 1][(nt & 1) * 2]);
        }
        __syncthreads();
        load(kb + 3);
    }

    // ---- epilogue ----
    float alpha = alpha_p ? __ldg(alpha_p) : 0.f;
    int g = lane >> 2, q = lane & 3;
    #pragma unroll
    for (int mt = 0; mt < 2; mt++) {
        int row = m0 + warp_m * 32 + mt * 16 + g;
        #pragma unroll
        for (int nt = 0; nt < NT8; nt++) {
            int col = n0 + warp_n * WN + nt * 8 + q * 2;
            float b0 = 0.f, b1 = 0.f;
            if (biasz) { b0 = biasz[col]; b1 = biasz[col + 1]; }
            float2 v0 = make_float2(acc[mt][nt][0] + b0, acc[mt][nt][1] + b1);
            float2 v1 = make_float2(acc[mt][nt][2] + b0, acc[mt][nt][3] + b1);
            if (alpha_p) {
                v0.x = v0.x >= 0.f ? v0.x : alpha * v0.x;
                v0.y = v0.y >= 0.f ? v0.y : alpha * v0.y;
                v1.x = v1.x >= 0.f ? v1.x : alpha * v1.x;
                v1.y = v1.y >= 0.f ? v1.y : alpha * v1.y;
            }
            *reinterpret_cast<float2*>(Cz + (size_t)row * ldc + col) = v0;
            *reinterpret_cast<float2*>(Cz + (size_t)(row + 8) * ldc + col) = v1;
        }
    }
}

// ---------------- split conversions ----------------
__device__ __forceinline__ void split2(float x, unsigned short& h, unsigned short& l) {
    __nv_bfloat16 hb = __float2bfloat16(x);
    __nv_bfloat16 lb = __float2bfloat16(x - __bfloat162float(hb));
    h = __bfloat16_as_ushort(hb); l = __bfloat16_as_ushort(lb);
}

// A-side: fp32 [N_, ldin] -> bf16 [N_, 3K] = [hi|hi|lo]
__global__ void __launch_bounds__(256) k_splitA(
    const float* __restrict__ in, long long inZ, int ldin, int K,
    __nv_bfloat16* __restrict__ out, long long outZ)
{
    long long z = blockIdx.z;
    in += z * inZ; out += z * outZ;
    int K4 = K / 4;
    int idx = blockIdx.x * 256 + threadIdx.x;
    if (idx >= N_ * K4) return;
    int m = idx / K4, k4 = (idx % K4) * 4;
    float4 v = *reinterpret_cast<const float4*>(in + (size_t)m * ldin + k4);
    ushort4 h, l;
    split2(v.x, h.x, l.x); split2(v.y, h.y, l.y);
    split2(v.z, h.z, l.z); split2(v.w, h.w, l.w);
    size_t b = (size_t)m * 3 * K;
    *reinterpret_cast<ushort4*>(out + b + k4) = h;
    *reinterpret_cast<ushort4*>(out + b + K + k4) = h;
    *reinterpret_cast<ushort4*>(out + b + 2*K + k4) = l;
}

// A-side with fused LN1+PReLU: z = channel
__global__ void __launch_bounds__(256) k_splitA_ln(
    const float* __restrict__ x1, const float* __restrict__ stats,
    const float* __restrict__ g1, const float* __restrict__ be1,
    const float* __restrict__ a1p, __nv_bfloat16* __restrict__ out)
{
    int c = blockIdx.z;
    const float* in = x1 + c * HID_;
    const float* gm = g1 + c * HID_;
    const float* bt = be1 + c * HID_;
    __nv_bfloat16* op = out + (size_t)c * N_ * (3 * HID_);
    int idx = blockIdx.x * 256 + threadIdx.x;
    if (idx >= N_ * (HID_/4)) return;
    int m = idx / (HID_/4), k4 = (idx % (HID_/4)) * 4;
    float4 v = *reinterpret_cast<const float4*>(in + (size_t)m * CH_ + k4);
    float mn = stats[2*m], rs = stats[2*m+1], a = __ldg(a1p);
    float4 g = *reinterpret_cast<const float4*>(gm + k4);
    float4 b = *reinterpret_cast<const float4*>(bt + k4);
    v.x = (v.x-mn)*rs*g.x + b.x; v.y = (v.y-mn)*rs*g.y + b.y;
    v.z = (v.z-mn)*rs*g.z + b.z; v.w = (v.w-mn)*rs*g.w + b.w;
    v.x = v.x >= 0.f ? v.x : a*v.x; v.y = v.y >= 0.f ? v.y : a*v.y;
    v.z = v.z >= 0.f ? v.z : a*v.z; v.w = v.w >= 0.f ? v.w : a*v.w;
    ushort4 h, l;
    split2(v.x, h.x, l.x); split2(v.y, h.y, l.y);
    split2(v.z, h.z, l.z); split2(v.w, h.w, l.w);
    size_t base = (size_t)m * (3 * HID_);
    *reinterpret_cast<ushort4*>(op + base + k4) = h;
    *reinterpret_cast<ushort4*>(op + base + HID_ + k4) = h;
    *reinterpret_cast<ushort4*>(op + base + 2*HID_ + k4) = l;
}

// B-side: fp32 [Kd, Nn] -> bf16 [Nn, 3Kd] = [hi|lo|hi] (transposed)
__global__ void __launch_bounds__(256) k_splitB(
    const float* __restrict__ in, long long inZ, int Kd, int Nn,
    __nv_bfloat16* __restrict__ out, long long outZ)
{
    long long z = blockIdx.z;
    in += z * inZ; out += z * outZ;
    int idx = blockIdx.x * 256 + threadIdx.x;
    if (idx >= Kd * Nn) return;
    int n = idx / Kd, k = idx % Kd;
    float x = in[(size_t)k * Nn + n];
    unsigned short h, l;
    split2(x, h, l);
    __nv_bfloat16 hb = __ushort_as_bfloat16(h), lb = __ushort_as_bfloat16(l);
    size_t b = (size_t)n * 3 * Kd;
    out[b + k] = hb; out[b + Kd + k] = lb; out[b + 2*Kd + k] = hb;
}

// ---------------- plain fp32 GEMM for tiny weight fusion ----------------
__global__ void __launch_bounds__(256, 2) fuse_weights_kernel(
    const float* __restrict__ femb, const float* __restrict__ eemb,
    const float* __restrict__ lemb, const float* __restrict__ W1)
{
    constexpr int BM = 64, TM = 4, BN = 128, BK = 16, TN = 8;
    int zz = blockIdx.z, r = zz / C_, c = zz % C_;
    const float* A; int M; float* out;
    if (c < K_)      { A = femb + (size_t)(r*K_+c)*V_*IN_; M = V_;   out = g_Wraw + (size_t)(r*K_+c)*V_*HID_; }
    else if (c == 3) { A = eemb + (size_t)r*VE_*IN_;       M = VE_;  out = g_Wex  + (size_t)r*VE_*HID_; }
    else             { A = lemb + (size_t)r*OUT_*IN_;      M = OUT_; out = g_Wlab + (size_t)r*OUT_*HID_; }
    const float* B = W1 + (size_t)c * IN_ * HID_;

    __shared__ __align__(16) float As[BK][BM+4];
    __shared__ __align__(16) float Bs[BK][BN];
    int tid = threadIdx.x, tx = tid % (BN/TN), ty = tid / (BN/TN);
    int row0 = blockIdx.y * BM, col0 = blockIdx.x * BN;
    float acc[TM][TN] = {};
    for (int k0 = 0; k0 < IN_; k0 += BK) {
        for (int v = tid; v < BM*(BK/4); v += 256) {
            int rr = v / (BK/4), kq = (v % (BK/4)) * 4, gr = row0 + rr;
            float4 val = make_float4(0,0,0,0);
            if (gr < M) val = *reinterpret_cast<const float4*>(A + (size_t)gr*IN_ + k0 + kq);
            As[kq][rr] = val.x; As[kq+1][rr] = val.y; As[kq+2][rr] = val.z; As[kq+3][rr] = val.w;
        }
        for (int v = tid; v < BK*(BN/4); v += 256) {
            int rr = v / (BN/4), c4 = (v % (BN/4)) * 4;
            *reinterpret_cast<float4*>(&Bs[rr][c4]) =
                *reinterpret_cast<const float4*>(B + (size_t)(k0+rr)*HID_ + col0 + c4);
        }
        __syncthreads();
        #pragma unroll
        for (int kk = 0; kk < BK; kk++) {
            float a[TM], b[TN];
            #pragma unroll
            for (int i = 0; i < TM; i++) a[i] = As[kk][ty*TM+i];
            #pragma unroll
            for (int j = 0; j < TN; j++) b[j] = Bs[kk][tx*TN+j];
            #pragma unroll
            for (int i = 0; i < TM; i++)
                #pragma unroll
                for (int j = 0; j < TN; j++) acc[i][j] += a[i]*b[j];
        }
        __syncthreads();
    }
    #pragma unroll
    for (int i = 0; i < TM; i++) {
        int gr = row0 + ty*TM + i;
        if (gr >= M) continue;
        #pragma unroll
        for (int j = 0; j < TN; j++) out[(size_t)gr*HID_ + col0 + tx*TN + j] = acc[i][j];
    }
}

// ---------------- small SIMT kernels ----------------
__global__ void k_u(const float* __restrict__ eemb, const float* __restrict__ wx)
{
    int t = blockIdx.x * blockDim.x + threadIdx.x;
    if (t >= R_ * VE_) return;
    const float* row = eemb + (size_t)t * IN_;
    float s = 0.f;
    for (int d = 0; d < IN_; d++) s += row[d] * wx[d];
    g_u[t] = s;
}

__global__ void __launch_bounds__(256) k_extra_pool(const float* __restrict__ extra)
{
    int wg = (blockIdx.x * blockDim.x + threadIdx.x) >> 5, lane = threadIdx.x & 31;
    if (wg >= R_ * N_) return;
    int r = wg / N_;
    const float* base = extra + (size_t)wg * (L_ * VE_);
    float u[4];
    #pragma unroll
    for (int j = 0; j < 4; j++) u[j] = g_u[r * VE_ + lane + 32*j];
    float x[L_][4], s[L_];
    #pragma unroll
    for (int l = 0; l < L_; l++) {
        float p = 0.f;
        #pragma unroll
        for (int j = 0; j < 4; j++) { x[l][j] = base[l*VE_ + lane + 32*j]; p += x[l][j]*u[j]; }
        #pragma unroll
        for (int o = 16; o > 0; o >>= 1) p += __shfl_xor_sync(0xffffffffu, p, o);
        s[l] = 1.f / (1.f + expf(-p));
    }
    float mx = s[0];
    #pragma unroll
    for (int l = 1; l < L_; l++) mx = fmaxf(mx, s[l]);
    float e[L_], es = 0.f;
    #pragma unroll
    for (int l = 0; l < L_; l++) { e[l] = expf(s[l]-mx); es += e[l]; }
    float inv = 1.f / es, out[4] = {0,0,0,0};
    #pragma unroll
    for (int l = 0; l < L_; l++) {
        float w = e[l]*inv;
        #pragma unroll
        for (int j = 0; j < 4; j++) out[j] += w * x[l][j];
    }
    float* op = g_xp + (size_t)wg * VE_;
    #pragma unroll
    for (int j = 0; j < 4; j++) op[lane + 32*j] = out[j];
}

__global__ void __launch_bounds__(256) k_stats(const float* __restrict__ X, float* __restrict__ st)
{
    int w = (blockIdx.x * blockDim.x + threadIdx.x) >> 5, lane = threadIdx.x & 31;
    if (w >= N_) return;
    const float4* row = reinterpret_cast<const float4*>(X + (size_t)w * CH_);
    float s = 0.f, s2 = 0.f;
    for (int v = lane; v < CH_/4; v += 32) {
        float4 t = row[v];
        s += t.x+t.y+t.z+t.w; s2 += t.x*t.x+t.y*t.y+t.z*t.z+t.w*t.w;
    }
    #pragma unroll
    for (int o = 16; o > 0; o >>= 1) {
        s += __shfl_xor_sync(0xffffffffu, s, o);
        s2 += __shfl_xor_sync(0xffffffffu, s2, o);
    }
    if (lane == 0) {
        float m = s/(float)CH_, var = s2/(float)CH_ - m*m;
        st[2*w] = m; st[2*w+1] = rsqrtf(var + 1e-5f);
    }
}

__global__ void __launch_bounds__(256) k_pool_c(
    const float* __restrict__ g2, const float* __restrict__ be2,
    const float* __restrict__ a2p, const float* __restrict__ wr, int r)
{
    int n = blockIdx.x, tid = threadIdx.x;
    __shared__ __align__(16) float sx[CH_];
    __shared__ float red[C_][8], rsum[8], rsum2[8], salpha[C_], smn, srs;
    const float* xr = g_x2 + (size_t)n * CH_;
    float s = 0.f, s2 = 0.f;
    for (int i = tid; i < CH_/4; i += 256) {
        float4 t = reinterpret_cast<const float4*>(xr)[i];
        reinterpret_cast<float4*>(sx)[i] = t;
        s += t.x+t.y+t.z+t.w; s2 += t.x*t.x+t.y*t.y+t.z*t.z+t.w*t.w;
    }
    int lane = tid & 31, wid = tid >> 5;
    #pragma unroll
    for (int o = 16; o > 0; o >>= 1) {
        s += __shfl_xor_sync(0xffffffffu, s, o);
        s2 += __shfl_xor_sync(0xffffffffu, s2, o);
    }
    if (lane == 0) { rsum[wid] = s; rsum2[wid] = s2; }
    __syncthreads();
    if (tid == 0) {
        float ts = 0.f, ts2 = 0.f;
        #pragma unroll
        for (int w2 = 0; w2 < 8; w2++) { ts += rsum[w2]; ts2 += rsum2[w2]; }
        float m = ts/(float)CH_;
        smn = m; srs = rsqrtf(ts2/(float)CH_ - m*m + 1e-5f);
    }
    __syncthreads();
    float mn = smn, rs = srs, a = __ldg(a2p);
    for (int i = tid; i < CH_; i += 256) {
        float v = (sx[i]-mn)*rs*g2[i] + be2[i];
        sx[i] = v >= 0.f ? v : a*v;
    }
    __syncthreads();
    float p[C_] = {0,0,0,0,0};
    for (int h = tid; h < HID_; h += 256) {
        float w = wr[h];
        #pragma unroll
        for (int c = 0; c < C_; c++) p[c] += sx[c*HID_+h] * w;
    }
    #pragma unroll
    for (int c = 0; c < C_; c++)
        #pragma unroll
        for (int o = 16; o > 0; o >>= 1) p[c] += __shfl_xor_sync(0xffffffffu, p[c], o);
    if (lane == 0)
        #pragma unroll
        for (int c = 0; c < C_; c++) red[c][wid] = p[c];
    __syncthreads();
    if (tid == 0) {
        float sv[C_], mx = -1e30f;
        #pragma unroll
        for (int c = 0; c < C_; c++) {
            float t = 0.f;
            #pragma unroll
            for (int w2 = 0; w2 < 8; w2++) t += red[c][w2];
            sv[c] = 1.f / (1.f + expf(-t)); mx = fmaxf(mx, sv[c]);
        }
        float es = 0.f, e[C_];
        #pragma unroll
        for (int c = 0; c < C_; c++) { e[c] = expf(sv[c]-mx); es += e[c]; }
        #pragma unroll
        for (int c = 0; c < C_; c++) salpha[c] = e[c] / es;
    }
    __syncthreads();
    float* op = g_outr + (size_t)r * N_ * HID_ + (size_t)n * HID_;
    for (int h = tid; h < HID_; h += 256) {
        float acc = 0.f;
        #pragma unroll
        for (int c = 0; c < C_; c++) acc += salpha[c] * sx[c*HID_+h];
        op[h] = acc;
    }
}

__global__ void __launch_bounds__(256) k_pool_global(const float* __restrict__ wg)
{
    int w = (blockIdx.x * blockDim.x + threadIdx.x) >> 5, lane = threadIdx.x & 31;
    if (w >= N_) return;
    const float* pa = g_outr + (size_t)w * HID_;
    const float* pb = g_outr + (size_t)N_ * HID_ + (size_t)w * HID_;
    float a[16], b[16], sa = 0.f, sb = 0.f;
    #pragma unroll
    for (int j = 0; j < 16; j++) {
        int h = lane + 32*j;
        a[j] = pa[h]; b[j] = pb[h];
        float wv = wg[h];
        sa += a[j]*wv; sb += b[j]*wv;
    }
    #pragma unroll
    for (int o = 16; o > 0; o >>= 1) {
        sa += __shfl_xor_sync(0xffffffffu, sa, o);
        sb += __shfl_xor_sync(0xffffffffu, sb, o);
    }
    sa = 1.f/(1.f+expf(-sa)); sb = 1.f/(1.f+expf(-sb));
    float mx = fmaxf(sa, sb), ea = expf(sa-mx), eb = expf(sb-mx);
    float aa = ea/(ea+eb), ab = 1.f - aa;
    float* op = g_hfin + (size_t)w * HID_;
    #pragma unroll
    for (int j = 0; j < 16; j++) op[lane + 32*j] = aa*a[j] + ab*b[j];
}

// ---------------- input mapping ----------------
struct Ins {
    const float *raw, *extra, *label, *femb, *eemb, *lemb;
    const float *w_extra, *w_r, *w_g;
    const float *W1, *b1, *g1, *be1, *a1, *W2, *b2, *g2, *be2, *a2;
    const float *Wf1, *bf1, *af, *Wf2, *bf2;
};
static void resolve(void* const* d_in, const int* sz, Ins& I)
{
    auto F = [&](int i) { return (const float*)d_in[i]; };
    if (sz[0] == R_ * K_ * N_ * V_) {
        I.raw=F(0); I.extra=F(1); I.label=F(2); I.femb=F(3); I.eemb=F(4); I.lemb=F(5);
        I.w_extra=F(6); I.w_r=F(7); I.w_g=F(8);
        I.W1=F(9); I.b1=F(10); I.g1=F(11); I.be1=F(12); I.a1=F(13);
        I.W2=F(14); I.b2=F(15); I.g2=F(16); I.be2=F(17); I.a2=F(18);
        I.Wf1=F(19); I.bf1=F(20); I.af=F(21); I.Wf2=F(22); I.bf2=F(23);
    } else {
        I.W1=F(0); I.W2=F(1); I.Wf1=F(2); I.Wf2=F(3);
        I.a1=F(4); I.a2=F(5); I.af=F(6);
        I.b1=F(7); I.b2=F(8); I.be1=F(9); I.be2=F(10); I.bf1=F(11); I.bf2=F(12);
        I.eemb=F(13); I.extra=F(14); I.femb=F(15); I.g1=F(16); I.g2=F(17);
        I.lemb=F(18); I.label=F(19); I.raw=F(20);
        I.w_extra=F(21); I.w_g=F(22); I.w_r=F(23);
    }
}

extern "C" void kernel_launch(void* const* d_in, const int* in_sizes, int n_in,
                              void* d_out, int out_size)
{
    if (n_in < 24) return;
    Ins I; resolve(d_in, in_sizes, I);

    float *px1, *px2, *pxp, *pWraw, *pWex, *pWlab, *ps1, *phf;
    __nv_bfloat16 *prawA, *plabA, *pxpA, *px1A, *phfA, *pff1A;
    __nv_bfloat16 *pW2T, *pWrawT, *pWexT, *pWlabT, *pWf1T, *pWf2T;
    cudaGetSymbolAddress((void**)&px1, g_x1);     cudaGetSymbolAddress((void**)&px2, g_x2);
    cudaGetSymbolAddress((void**)&pxp, g_xp);     cudaGetSymbolAddress((void**)&pWraw, g_Wraw);
    cudaGetSymbolAddress((void**)&pWex, g_Wex);   cudaGetSymbolAddress((void**)&pWlab, g_Wlab);
    cudaGetSymbolAddress((void**)&ps1, g_stats1); cudaGetSymbolAddress((void**)&phf, g_hfin);
    cudaGetSymbolAddress((void**)&prawA, g_rawA); cudaGetSymbolAddress((void**)&plabA, g_labA);
    cudaGetSymbolAddress((void**)&pxpA, g_xpA);   cudaGetSymbolAddress((void**)&px1A, g_x1A);
    cudaGetSymbolAddress((void**)&phfA, g_hfA);   cudaGetSymbolAddress((void**)&pff1A, g_ff1A);
    cudaGetSymbolAddress((void**)&pW2T, g_W2T);   cudaGetSymbolAddress((void**)&pWrawT, g_WrawT);
    cudaGetSymbolAddress((void**)&pWexT, g_WexT); cudaGetSymbolAddress((void**)&pWlabT, g_WlabT);
    cudaGetSymbolAddress((void**)&pWf1T, g_Wf1T); cudaGetSymbolAddress((void**)&pWf2T, g_Wf2T);

    constexpr int SM128 = 3 * (128 * 80 + 128 * 80);   // 61440 B
    constexpr int SM64  = 3 * (128 * 80 + 64 * 80);    // 46080 B
    cudaFuncSetAttribute(k_tc_gemm<128>, cudaFuncAttributeMaxDynamicSharedMemorySize, SM128);
    cudaFuncSetAttribute(k_tc_gemm<64>,  cudaFuncAttributeMaxDynamicSharedMemorySize, SM64);

    // ---- prolog ----
    k_u<<<1, 256>>>(I.eemb, I.w_extra);
    fuse_weights_kernel<<<dim3(4, 4, 10), 256>>>(I.femb, I.eemb, I.lemb, I.W1);
    k_extra_pool<<<(R_ * N_) / 8, 256>>>(I.extra);

    // ---- weight splits (B-side, transposed to [N,3K]) ----
    k_splitB<<<dim3(512, 1, 6), 256>>>(pWraw, (long long)V_*HID_, V_, HID_, pWrawT, (long long)HID_*3*V_);
    k_splitB<<<dim3(256, 1, 2), 256>>>(pWex,  (long long)VE_*HID_, VE_, HID_, pWexT, (long long)HID_*3*VE_);
    k_splitB<<<dim3(128, 1, 2), 256>>>(pWlab, (long long)OUT_*HID_, OUT_, HID_, pWlabT, (long long)HID_*3*OUT_);
    k_splitB<<<dim3(1024, 1, 5), 256>>>(I.W2, (long long)HID_*HID_, HID_, HID_, pW2T, (long long)HID_*3*HID_);
    k_splitB<<<dim3(1024, 1, 1), 256>>>(I.Wf1, 0, HID_, HID_, pWf1T, 0);
    k_splitB<<<dim3(128, 1, 1), 256>>>(I.Wf2, 0, HID_, OUT_, pWf2T, 0);

    // ---- activation splits (A-side, [M,3K]) ----
    k_splitA<<<dim3(4096, 1, 6), 256>>>(I.raw, (long long)N_*V_, V_, V_, prawA, (long long)N_*3*V_);
    k_splitA<<<dim3(1024, 1, 2), 256>>>(I.label, (long long)N_*OUT_, OUT_, OUT_, plabA, (long long)N_*3*OUT_);
    k_splitA<<<dim3(2048, 1, 2), 256>>>(pxp, (long long)N_*VE_, VE_, VE_, pxpA, (long long)N_*3*VE_);

    for (int r = 0; r < R_; r++) {
        // x1 channels 0..2 : [N,768] @ [512,768]^T
        k_tc_gemm<128><<<dim3(HID_/128, N_/128, 3), 256, SM128>>>(
            prawA + (size_t)r*3*N_*(3*V_), (long long)N_*3*V_, 3*V_,
            pWrawT + (size_t)r*3*HID_*(3*V_), (long long)HID_*3*V_, 3*V_, 3*V_,
            I.b1, HID_, px1, CH_, HID_, nullptr);
        // channel 3 (pooled extra) : K''=384
        k_tc_gemm<128><<<dim3(HID_/128, N_/128, 1), 256, SM128>>>(
            pxpA + (size_t)r*N_*(3*VE_), 0, 3*VE_,
            pWexT + (size_t)r*HID_*(3*VE_), 0, 3*VE_, 3*VE_,
            I.b1 + 3*HID_, 0, px1 + 3*HID_, CH_, 0, nullptr);
        // channel 4 (label) : K''=192
        k_tc_gemm<128><<<dim3(HID_/128, N_/128, 1), 256, SM128>>>(
            plabA + (size_t)r*N_*(3*OUT_), 0, 3*OUT_,
            pWlabT + (size_t)r*HID_*(3*OUT_), 0, 3*OUT_, 3*OUT_,
            I.b1 + 4*HID_, 0, px1 + 4*HID_, CH_, 0, nullptr);

        // LN1 stats -> fused LN+PReLU split -> W2 GEMM (K''=1536, z over C)
        k_stats<<<N_ / 8, 256>>>(px1, ps1);
        k_splitA_ln<<<dim3(8192, 1, C_), 256>>>(px1, ps1, I.g1, I.be1, I.a1, px1A);
        k_tc_gemm<128><<<dim3(HID_/128, N_/128, C_), 256, SM128>>>(
            px1A, (long long)N_*3*HID_, 3*HID_,
            pW2T, (long long)HID_*3*HID_, 3*HID_, 3*HID_,
            I.b2, HID_, px2, CH_, HID_, nullptr);

        k_pool_c<<<N_, 256>>>(I.g2, I.be2, I.a2, I.w_r + r*HID_, r);
    }

    // ---- global pool + FFN head ----
    k_pool_global<<<N_ / 8, 256>>>(I.w_g);
    k_splitA<<<dim3(8192, 1, 1), 256>>>(phf, 0, HID_, HID_, phfA, 0);
    k_tc_gemm<128><<<dim3(HID_/128, N_/128, 1), 256, SM128>>>(
        phfA, 0, 3*HID_, pWf1T, 0, 3*HID_, 3*HID_,
        I.bf1, 0, px2, HID_, 0, I.af);                 // PReLU out, [N,512]
    k_splitA<<<dim3(8192, 1, 1), 256>>>(px2, 0, HID_, HID_, pff1A, 0);
    k_tc_gemm<64><<<dim3(1, N_/128, 1), 256, SM64>>>(
        pff1A, 0, 3*HID_, pWf2T, 0, 3*HID_, 3*HID_,
        I.bf2, 0, (float*)d_out, OUT_, 0, nullptr);
}

// round 9
// speedup vs baseline: 1.8724x; 1.0657x over previous
#include <cuda_runtime.h>
#include <cuda_bf16.h>
#include <math.h>

#define R_   2
#define K_   3
#define N_   16384
#define V_   256
#define L_   8
#define VE_  128
#define OUT_ 64
#define IN_  256
#define HID_ 512
#define C_   5
#define CH_  (C_*HID_)

// ---------------- fp32 workspace ----------------
__device__ float g_x1[(size_t)N_ * CH_];
__device__ float g_x2[(size_t)N_ * CH_];
__device__ float g_outr[(size_t)R_ * N_ * HID_];
__device__ float g_hfin[(size_t)N_ * HID_];
__device__ float g_xp[(size_t)R_ * N_ * VE_];
__device__ float g_stats1[N_ * 2];
__device__ float g_u[R_ * VE_];
__device__ float g_Wraw[(size_t)R_ * K_ * V_ * HID_];
__device__ float g_Wex [(size_t)R_ * VE_ * HID_];
__device__ float g_Wlab[(size_t)R_ * OUT_ * HID_];

// ---------------- bf16 2-plane split workspace ([hi|lo], width 2K) ----------------
__device__ __align__(16) __nv_bfloat16 g_rawA[(size_t)R_ * K_ * N_ * (2*V_)];
__device__ __align__(16) __nv_bfloat16 g_labA[(size_t)R_ * N_ * (2*OUT_)];
__device__ __align__(16) __nv_bfloat16 g_xpA [(size_t)R_ * N_ * (2*VE_)];
__device__ __align__(16) __nv_bfloat16 g_x1A [(size_t)C_ * N_ * (2*HID_)];
__device__ __align__(16) __nv_bfloat16 g_hfA [(size_t)N_ * (2*HID_)];
__device__ __align__(16) __nv_bfloat16 g_ff1A[(size_t)N_ * (2*HID_)];
__device__ __align__(16) __nv_bfloat16 g_W2T  [(size_t)C_ * HID_ * (2*HID_)];
__device__ __align__(16) __nv_bfloat16 g_WrawT[(size_t)R_ * K_ * HID_ * (2*V_)];
__device__ __align__(16) __nv_bfloat16 g_WexT [(size_t)R_ * HID_ * (2*VE_)];
__device__ __align__(16) __nv_bfloat16 g_WlabT[(size_t)R_ * HID_ * (2*OUT_)];
__device__ __align__(16) __nv_bfloat16 g_Wf1T [(size_t)HID_ * (2*HID_)];
__device__ __align__(16) __nv_bfloat16 g_Wf2T [(size_t)OUT_ * (2*HID_)];

// ---------------- PTX helpers (base-target features only) ----------------
__device__ __forceinline__ unsigned smem_u32(const void* p) {
    unsigned a;
    asm("{ .reg .u64 t; cvta.to.shared.u64 t, %1; cvt.u32.u64 %0, t; }" : "=r"(a) : "l"(p));
    return a;
}
__device__ __forceinline__ void cp16(unsigned dst, const void* src) {
    asm volatile("cp.async.cg.shared.global [%0], [%1], 16;" :: "r"(dst), "l"(src) : "memory");
}
__device__ __forceinline__ void ldsm4(unsigned* r, unsigned addr) {
    asm volatile("ldmatrix.sync.aligned.m8n8.x4.shared.b16 {%0,%1,%2,%3}, [%4];"
        : "=r"(r[0]), "=r"(r[1]), "=r"(r[2]), "=r"(r[3]) : "r"(addr));
}
__device__ __forceinline__ void mma16816(float* d, const unsigned* a, const unsigned* b) {
    asm volatile(
        "mma.sync.aligned.m16n8k16.row.col.f32.bf16.bf16.f32 "
        "{%0,%1,%2,%3}, {%4,%5,%6,%7}, {%8,%9}, {%0,%1,%2,%3};"
        : "+f"(d[0]), "+f"(d[1]), "+f"(d[2]), "+f"(d[3])
        : "r"(a[0]), "r"(a[1]), "r"(a[2]), "r"(a[3]), "r"(b[0]), "r"(b[1]));
}

// =========================================================================
// bf16 tensor-core GEMM via mma.sync with 3-product split on 2-plane storage.
// Logical C[M,Ncols] = sum over 3 phases of A_plane @ B_plane^T:
//   phase 0: A_hi.B_hi   phase 1: A_hi.B_lo   phase 2: A_lo.B_hi
// A row-major [M, 2*Kd] = [hi|lo], B row-major [Ncols, 2*Kd] = [hi|lo].
// CTA: 128 x BN; warps 4(M) x (BN/64)(N); warp tile 32x64; BK=32; 3-stage cp.async.
// =========================================================================
template<int BN>
__global__ void __launch_bounds__(128 * (BN > 64 ? BN / 64 : 1), 1) k_tc_gemm(
    const __nv_bfloat16* __restrict__ A, long long aZ,
    const __nv_bfloat16* __restrict__ B, long long bZ, int Kd,
    const float* __restrict__ bias, long long biasZ,
    float* __restrict__ Co, int ldc, long long cZ,
    const float* __restrict__ alpha_p)
{
    constexpr int BM = 128, BK = 32, LDS = 40;           // LDS row pitch in bf16 (80 B)
    constexpr int NWN = (BN > 64 ? BN / 64 : 1);         // warps along N
    constexpr int THREADS = 128 * NWN;
    constexpr int WN  = BN / NWN;                        // per-warp N tile (=64)
    constexpr int NT8 = WN / 8;                          // n8 tiles per warp (=8)
    constexpr int ABYTES = BM * LDS * 2;
    constexpr int BBYTES = BN * LDS * 2;
    constexpr int STAGE  = ABYTES + BBYTES;
    constexpr int ACH = BM * 4, BCH = BN * 4;            // 16B chunks per tile

    extern __shared__ char smem[];
    const int tid = threadIdx.x, lane = tid & 31, wid = tid >> 5;
    const int warp_m = wid & 3, warp_n = wid >> 2;
    const int m0 = blockIdx.y * BM, n0 = blockIdx.x * BN;
    const long long z = blockIdx.z;
    const int ldAB = 2 * Kd;
    const __nv_bfloat16* Az = A + z * aZ;
    const __nv_bfloat16* Bz = B + z * bZ;
    float* Cz = Co + z * cZ;
    const float* biasz = bias ? bias + z * biasZ : nullptr;

    const unsigned sb = smem_u32(smem);
    const int kbK = Kd / BK;            // k-blocks per plane
    const int nkb = 3 * kbK;            // total logical k-blocks

    float acc[2][NT8][4];
    #pragma unroll
    for (int mt = 0; mt < 2; mt++)
        #pragma unroll
        for (int nt = 0; nt < NT8; nt++)
            #pragma unroll
            for (int j = 0; j < 4; j++) acc[mt][nt][j] = 0.f;

    auto load = [&](int kb) {
        if (kb < nkb) {
            int ph = kb / kbK, kr = kb - ph * kbK;
            int ka = kr * BK + (ph == 2 ? Kd : 0);   // A: hi,hi,lo
            int kbb = kr * BK + (ph == 1 ? Kd : 0);  // B: hi,lo,hi
            unsigned ab = sb + (unsigned)(kb % 3) * STAGE;
            unsigned bb = ab + ABYTES;
            #pragma unroll
            for (int q = 0; q < ACH / THREADS; q++) {
                int ch = tid + q * THREADS;
                int row = ch >> 2, c = ch & 3;
                cp16(ab + row * (LDS * 2) + c * 16,
                     Az + (size_t)(m0 + row) * ldAB + ka + c * 8);
            }
            #pragma unroll
            for (int q = 0; q < BCH / THREADS; q++) {
                int ch = tid + q * THREADS;
                int row = ch >> 2, c = ch & 3;
                cp16(bb + row * (LDS * 2) + c * 16,
                     Bz + (size_t)(n0 + row) * ldAB + kbb + c * 8);
            }
        }
        asm volatile("cp.async.commit_group;" ::: "memory");
    };

    load(0); load(1); load(2);

    for (int kb = 0; kb < nkb; kb++) {
        asm volatile("cp.async.wait_group 2;" ::: "memory");
        __syncthreads();
        unsigned ab = sb + (unsigned)(kb % 3) * STAGE;
        unsigned bb = ab + ABYTES;

        #pragma unroll
        for (int ks = 0; ks < 2; ks++) {
            int k0 = ks * 16;
            unsigned af[2][4], bf[NT8 / 2][4];
            {
                int row = warp_m * 32 + (lane & 15);
                int kc  = k0 + (lane >> 4) * 8;
                #pragma unroll
                for (int mt = 0; mt < 2; mt++)
                    ldsm4(af[mt], ab + (row + mt * 16) * (LDS * 2) + kc * 2);
            }
            {
                int rowi = lane & 7, quad = lane >> 3;
                int nofs = (quad >> 1) * 8, kofs = (quad & 1) * 8;
                #pragma unroll
                for (int j = 0; j < NT8 / 2; j++) {
                    int nb = warp_n * WN + j * 16 + nofs + rowi;
                    ldsm4(bf[j], bb + nb * (LDS * 2) + (k0 + kofs) * 2);
                }
            }
            #pragma unroll
            for (int mt = 0; mt < 2; mt++)
                #pragma unroll
                for (int nt = 0; nt < NT8; nt++)
                    mma16816(acc[mt][nt], af[mt], &bf[nt >> 1][(nt & 1) * 2]);
        }
        __syncthreads();
        load(kb + 3);
    }

    // ---- epilogue ----
    float alpha = alpha_p ? __ldg(alpha_p) : 0.f;
    int g = lane >> 2, q = lane & 3;
    #pragma unroll
    for (int mt = 0; mt < 2; mt++) {
        int row = m0 + warp_m * 32 + mt * 16 + g;
        #pragma unroll
        for (int nt = 0; nt < NT8; nt++) {
            int col = n0 + warp_n * WN + nt * 8 + q * 2;
            float b0 = 0.f, b1 = 0.f;
            if (biasz) { b0 = biasz[col]; b1 = biasz[col + 1]; }
            float2 v0 = make_float2(acc[mt][nt][0] + b0, acc[mt][nt][1] + b1);
            float2 v1 = make_float2(acc[mt][nt][2] + b0, acc[mt][nt][3] + b1);
            if (alpha_p) {
                v0.x = v0.x >= 0.f ? v0.x : alpha * v0.x;
                v0.y = v0.y >= 0.f ? v0.y : alpha * v0.y;
                v1.x = v1.x >= 0.f ? v1.x : alpha * v1.x;
                v1.y = v1.y >= 0.f ? v1.y : alpha * v1.y;
            }
            *reinterpret_cast<float2*>(Cz + (size_t)row * ldc + col) = v0;
            *reinterpret_cast<float2*>(Cz + (size_t)(row + 8) * ldc + col) = v1;
        }
    }
}

// ---------------- split conversions (2-plane [hi|lo]) ----------------
__device__ __forceinline__ void split2(float x, unsigned short& h, unsigned short& l) {
    __nv_bfloat16 hb = __float2bfloat16(x);
    __nv_bfloat16 lb = __float2bfloat16(x - __bfloat162float(hb));
    h = __bfloat16_as_ushort(hb); l = __bfloat16_as_ushort(lb);
}

// A-side: fp32 [N_, ldin] -> bf16 [N_, 2K]
__global__ void __launch_bounds__(256) k_splitA(
    const float* __restrict__ in, long long inZ, int ldin, int K,
    __nv_bfloat16* __restrict__ out, long long outZ)
{
    long long z = blockIdx.z;
    in += z * inZ; out += z * outZ;
    int K4 = K / 4;
    int idx = blockIdx.x * 256 + threadIdx.x;
    if (idx >= N_ * K4) return;
    int m = idx / K4, k4 = (idx % K4) * 4;
    float4 v = *reinterpret_cast<const float4*>(in + (size_t)m * ldin + k4);
    ushort4 h, l;
    split2(v.x, h.x, l.x); split2(v.y, h.y, l.y);
    split2(v.z, h.z, l.z); split2(v.w, h.w, l.w);
    size_t b = (size_t)m * 2 * K;
    *reinterpret_cast<ushort4*>(out + b + k4) = h;
    *reinterpret_cast<ushort4*>(out + b + K + k4) = l;
}

// A-side with fused LN1+PReLU: z = channel
__global__ void __launch_bounds__(256) k_splitA_ln(
    const float* __restrict__ x1, const float* __restrict__ stats,
    const float* __restrict__ g1, const float* __restrict__ be1,
    const float* __restrict__ a1p, __nv_bfloat16* __restrict__ out)
{
    int c = blockIdx.z;
    const float* in = x1 + c * HID_;
    const float* gm = g1 + c * HID_;
    const float* bt = be1 + c * HID_;
    __nv_bfloat16* op = out + (size_t)c * N_ * (2 * HID_);
    int idx = blockIdx.x * 256 + threadIdx.x;
    if (idx >= N_ * (HID_/4)) return;
    int m = idx / (HID_/4), k4 = (idx % (HID_/4)) * 4;
    float4 v = *reinterpret_cast<const float4*>(in + (size_t)m * CH_ + k4);
    float mn = stats[2*m], rs = stats[2*m+1], a = __ldg(a1p);
    float4 g = *reinterpret_cast<const float4*>(gm + k4);
    float4 b = *reinterpret_cast<const float4*>(bt + k4);
    v.x = (v.x-mn)*rs*g.x + b.x; v.y = (v.y-mn)*rs*g.y + b.y;
    v.z = (v.z-mn)*rs*g.z + b.z; v.w = (v.w-mn)*rs*g.w + b.w;
    v.x = v.x >= 0.f ? v.x : a*v.x; v.y = v.y >= 0.f ? v.y : a*v.y;
    v.z = v.z >= 0.f ? v.z : a*v.z; v.w = v.w >= 0.f ? v.w : a*v.w;
    ushort4 h, l;
    split2(v.x, h.x, l.x); split2(v.y, h.y, l.y);
    split2(v.z, h.z, l.z); split2(v.w, h.w, l.w);
    size_t base = (size_t)m * (2 * HID_);
    *reinterpret_cast<ushort4*>(op + base + k4) = h;
    *reinterpret_cast<ushort4*>(op + base + HID_ + k4) = l;
}

// B-side: fp32 [Kd, Nn] -> bf16 [Nn, 2Kd] (transposed)
__global__ void __launch_bounds__(256) k_splitB(
    const float* __restrict__ in, long long inZ, int Kd, int Nn,
    __nv_bfloat16* __restrict__ out, long long outZ)
{
    long long z = blockIdx.z;
    in += z * inZ; out += z * outZ;
    int idx = blockIdx.x * 256 + threadIdx.x;
    if (idx >= Kd * Nn) return;
    int n = idx / Kd, k = idx % Kd;
    float x = in[(size_t)k * Nn + n];
    unsigned short h, l;
    split2(x, h, l);
    size_t b = (size_t)n * 2 * Kd;
    out[b + k] = __ushort_as_bfloat16(h);
    out[b + Kd + k] = __ushort_as_bfloat16(l);
}

// ---------------- plain fp32 GEMM for tiny weight fusion ----------------
__global__ void __launch_bounds__(256, 2) fuse_weights_kernel(
    const float* __restrict__ femb, const float* __restrict__ eemb,
    const float* __restrict__ lemb, const float* __restrict__ W1)
{
    constexpr int BM = 64, TM = 4, BN = 128, BK = 16, TN = 8;
    int zz = blockIdx.z, r = zz / C_, c = zz % C_;
    const float* A; int M; float* out;
    if (c < K_)      { A = femb + (size_t)(r*K_+c)*V_*IN_; M = V_;   out = g_Wraw + (size_t)(r*K_+c)*V_*HID_; }
    else if (c == 3) { A = eemb + (size_t)r*VE_*IN_;       M = VE_;  out = g_Wex  + (size_t)r*VE_*HID_; }
    else             { A = lemb + (size_t)r*OUT_*IN_;      M = OUT_; out = g_Wlab + (size_t)r*OUT_*HID_; }
    const float* B = W1 + (size_t)c * IN_ * HID_;

    __shared__ __align__(16) float As[BK][BM+4];
    __shared__ __align__(16) float Bs[BK][BN];
    int tid = threadIdx.x, tx = tid % (BN/TN), ty = tid / (BN/TN);
    int row0 = blockIdx.y * BM, col0 = blockIdx.x * BN;
    float acc[TM][TN] = {};
    for (int k0 = 0; k0 < IN_; k0 += BK) {
        for (int v = tid; v < BM*(BK/4); v += 256) {
            int rr = v / (BK/4), kq = (v % (BK/4)) * 4, gr = row0 + rr;
            float4 val = make_float4(0,0,0,0);
            if (gr < M) val = *reinterpret_cast<const float4*>(A + (size_t)gr*IN_ + k0 + kq);
            As[kq][rr] = val.x; As[kq+1][rr] = val.y; As[kq+2][rr] = val.z; As[kq+3][rr] = val.w;
        }
        for (int v = tid; v < BK*(BN/4); v += 256) {
            int rr = v / (BN/4), c4 = (v % (BN/4)) * 4;
            *reinterpret_cast<float4*>(&Bs[rr][c4]) =
                *reinterpret_cast<const float4*>(B + (size_t)(k0+rr)*HID_ + col0 + c4);
        }
        __syncthreads();
        #pragma unroll
        for (int kk = 0; kk < BK; kk++) {
            float a[TM], b[TN];
            #pragma unroll
            for (int i = 0; i < TM; i++) a[i] = As[kk][ty*TM+i];
            #pragma unroll
            for (int j = 0; j < TN; j++) b[j] = Bs[kk][tx*TN+j];
            #pragma unroll
            for (int i = 0; i < TM; i++)
                #pragma unroll
                for (int j = 0; j < TN; j++) acc[i][j] += a[i]*b[j];
        }
        __syncthreads();
    }
    #pragma unroll
    for (int i = 0; i < TM; i++) {
        int gr = row0 + ty*TM + i;
        if (gr >= M) continue;
        #pragma unroll
        for (int j = 0; j < TN; j++) out[(size_t)gr*HID_ + col0 + tx*TN + j] = acc[i][j];
    }
}

// ---------------- small SIMT kernels ----------------
__global__ void k_u(const float* __restrict__ eemb, const float* __restrict__ wx)
{
    int t = blockIdx.x * blockDim.x + threadIdx.x;
    if (t >= R_ * VE_) return;
    const float* row = eemb + (size_t)t * IN_;
    float s = 0.f;
    for (int d = 0; d < IN_; d++) s += row[d] * wx[d];
    g_u[t] = s;
}

__global__ void __launch_bounds__(256) k_extra_pool(const float* __restrict__ extra)
{
    int wg = (blockIdx.x * blockDim.x + threadIdx.x) >> 5, lane = threadIdx.x & 31;
    if (wg >= R_ * N_) return;
    int r = wg / N_;
    const float* base = extra + (size_t)wg * (L_ * VE_);
    float u[4];
    #pragma unroll
    for (int j = 0; j < 4; j++) u[j] = g_u[r * VE_ + lane + 32*j];
    float x[L_][4], s[L_];
    #pragma unroll
    for (int l = 0; l < L_; l++) {
        float p = 0.f;
        #pragma unroll
        for (int j = 0; j < 4; j++) { x[l][j] = base[l*VE_ + lane + 32*j]; p += x[l][j]*u[j]; }
        #pragma unroll
        for (int o = 16; o > 0; o >>= 1) p += __shfl_xor_sync(0xffffffffu, p, o);
        s[l] = 1.f / (1.f + expf(-p));
    }
    float mx = s[0];
    #pragma unroll
    for (int l = 1; l < L_; l++) mx = fmaxf(mx, s[l]);
    float e[L_], es = 0.f;
    #pragma unroll
    for (int l = 0; l < L_; l++) { e[l] = expf(s[l]-mx); es += e[l]; }
    float inv = 1.f / es, out[4] = {0,0,0,0};
    #pragma unroll
    for (int l = 0; l < L_; l++) {
        float w = e[l]*inv;
        #pragma unroll
        for (int j = 0; j < 4; j++) out[j] += w * x[l][j];
    }
    float* op = g_xp + (size_t)wg * VE_;
    #pragma unroll
    for (int j = 0; j < 4; j++) op[lane + 32*j] = out[j];
}

__global__ void __launch_bounds__(256) k_stats(const float* __restrict__ X, float* __restrict__ st)
{
    int w = (blockIdx.x * blockDim.x + threadIdx.x) >> 5, lane = threadIdx.x & 31;
    if (w >= N_) return;
    const float4* row = reinterpret_cast<const float4*>(X + (size_t)w * CH_);
    float s = 0.f, s2 = 0.f;
    for (int v = lane; v < CH_/4; v += 32) {
        float4 t = row[v];
        s += t.x+t.y+t.z+t.w; s2 += t.x*t.x+t.y*t.y+t.z*t.z+t.w*t.w;
    }
    #pragma unroll
    for (int o = 16; o > 0; o >>= 1) {
        s += __shfl_xor_sync(0xffffffffu, s, o);
        s2 += __shfl_xor_sync(0xffffffffu, s2, o);
    }
    if (lane == 0) {
        float m = s/(float)CH_, var = s2/(float)CH_ - m*m;
        st[2*w] = m; st[2*w+1] = rsqrtf(var + 1e-5f);
    }
}

__global__ void __launch_bounds__(256) k_pool_c(
    const float* __restrict__ g2, const float* __restrict__ be2,
    const float* __restrict__ a2p, const float* __restrict__ wr, int r)
{
    int n = blockIdx.x, tid = threadIdx.x;
    __shared__ __align__(16) float sx[CH_];
    __shared__ float red[C_][8], rsum[8], rsum2[8], salpha[C_], smn, srs;
    const float* xr = g_x2 + (size_t)n * CH_;
    float s = 0.f, s2 = 0.f;
    for (int i = tid; i < CH_/4; i += 256) {
        float4 t = reinterpret_cast<const float4*>(xr)[i];
        reinterpret_cast<float4*>(sx)[i] = t;
        s += t.x+t.y+t.z+t.w; s2 += t.x*t.x+t.y*t.y+t.z*t.z+t.w*t.w;
    }
    int lane = tid & 31, wid = tid >> 5;
    #pragma unroll
    for (int o = 16; o > 0; o >>= 1) {
        s += __shfl_xor_sync(0xffffffffu, s, o);
        s2 += __shfl_xor_sync(0xffffffffu, s2, o);
    }
    if (lane == 0) { rsum[wid] = s; rsum2[wid] = s2; }
    __syncthreads();
    if (tid == 0) {
        float ts = 0.f, ts2 = 0.f;
        #pragma unroll
        for (int w2 = 0; w2 < 8; w2++) { ts += rsum[w2]; ts2 += rsum2[w2]; }
        float m = ts/(float)CH_;
        smn = m; srs = rsqrtf(ts2/(float)CH_ - m*m + 1e-5f);
    }
    __syncthreads();
    float mn = smn, rs = srs, a = __ldg(a2p);
    for (int i = tid; i < CH_; i += 256) {
        float v = (sx[i]-mn)*rs*g2[i] + be2[i];
        sx[i] = v >= 0.f ? v : a*v;
    }
    __syncthreads();
    float p[C_] = {0,0,0,0,0};
    for (int h = tid; h < HID_; h += 256) {
        float w = wr[h];
        #pragma unroll
        for (int c = 0; c < C_; c++) p[c] += sx[c*HID_+h] * w;
    }
    #pragma unroll
    for (int c = 0; c < C_; c++)
        #pragma unroll
        for (int o = 16; o > 0; o >>= 1) p[c] += __shfl_xor_sync(0xffffffffu, p[c], o);
    if (lane == 0)
        #pragma unroll
        for (int c = 0; c < C_; c++) red[c][wid] = p[c];
    __syncthreads();
    if (tid == 0) {
        float sv[C_], mx = -1e30f;
        #pragma unroll
        for (int c = 0; c < C_; c++) {
            float t = 0.f;
            #pragma unroll
            for (int w2 = 0; w2 < 8; w2++) t += red[c][w2];
            sv[c] = 1.f / (1.f + expf(-t)); mx = fmaxf(mx, sv[c]);
        }
        float es = 0.f, e[C_];
        #pragma unroll
        for (int c = 0; c < C_; c++) { e[c] = expf(sv[c]-mx); es += e[c]; }
        #pragma unroll
        for (int c = 0; c < C_; c++) salpha[c] = e[c] / es;
    }
    __syncthreads();
    float* op = g_outr + (size_t)r * N_ * HID_ + (size_t)n * HID_;
    for (int h = tid; h < HID_; h += 256) {
        float acc = 0.f;
        #pragma unroll
        for (int c = 0; c < C_; c++) acc += salpha[c] * sx[c*HID_+h];
        op[h] = acc;
    }
}

__global__ void __launch_bounds__(256) k_pool_global(const float* __restrict__ wg)
{
    int w = (blockIdx.x * blockDim.x + threadIdx.x) >> 5, lane = threadIdx.x & 31;
    if (w >= N_) return;
    const float* pa = g_outr + (size_t)w * HID_;
    const float* pb = g_outr + (size_t)N_ * HID_ + (size_t)w * HID_;
    float a[16], b[16], sa = 0.f, sb = 0.f;
    #pragma unroll
    for (int j = 0; j < 16; j++) {
        int h = lane + 32*j;
        a[j] = pa[h]; b[j] = pb[h];
        float wv = wg[h];
        sa += a[j]*wv; sb += b[j]*wv;
    }
    #pragma unroll
    for (int o = 16; o > 0; o >>= 1) {
        sa += __shfl_xor_sync(0xffffffffu, sa, o);
        sb += __shfl_xor_sync(0xffffffffu, sb, o);
    }
    sa = 1.f/(1.f+expf(-sa)); sb = 1.f/(1.f+expf(-sb));
    float mx = fmaxf(sa, sb), ea = expf(sa-mx), eb = expf(sb-mx);
    float aa = ea/(ea+eb), ab = 1.f - aa;
    float* op = g_hfin + (size_t)w * HID_;
    #pragma unroll
    for (int j = 0; j < 16; j++) op[lane + 32*j] = aa*a[j] + ab*b[j];
}

// ---------------- input mapping ----------------
struct Ins {
    const float *raw, *extra, *label, *femb, *eemb, *lemb;
    const float *w_extra, *w_r, *w_g;
    const float *W1, *b1, *g1, *be1, *a1, *W2, *b2, *g2, *be2, *a2;
    const float *Wf1, *bf1, *af, *Wf2, *bf2;
};
static void resolve(void* const* d_in, const int* sz, Ins& I)
{
    auto F = [&](int i) { return (const float*)d_in[i]; };
    if (sz[0] == R_ * K_ * N_ * V_) {
        I.raw=F(0); I.extra=F(1); I.label=F(2); I.femb=F(3); I.eemb=F(4); I.lemb=F(5);
        I.w_extra=F(6); I.w_r=F(7); I.w_g=F(8);
        I.W1=F(9); I.b1=F(10); I.g1=F(11); I.be1=F(12); I.a1=F(13);
        I.W2=F(14); I.b2=F(15); I.g2=F(16); I.be2=F(17); I.a2=F(18);
        I.Wf1=F(19); I.bf1=F(20); I.af=F(21); I.Wf2=F(22); I.bf2=F(23);
    } else {
        I.W1=F(0); I.W2=F(1); I.Wf1=F(2); I.Wf2=F(3);
        I.a1=F(4); I.a2=F(5); I.af=F(6);
        I.b1=F(7); I.b2=F(8); I.be1=F(9); I.be2=F(10); I.bf1=F(11); I.bf2=F(12);
        I.eemb=F(13); I.extra=F(14); I.femb=F(15); I.g1=F(16); I.g2=F(17);
        I.lemb=F(18); I.label=F(19); I.raw=F(20);
        I.w_extra=F(21); I.w_g=F(22); I.w_r=F(23);
    }
}

extern "C" void kernel_launch(void* const* d_in, const int* in_sizes, int n_in,
                              void* d_out, int out_size)
{
    if (n_in < 24) return;
    Ins I; resolve(d_in, in_sizes, I);

    float *px1, *px2, *pxp, *pWraw, *pWex, *pWlab, *ps1, *phf;
    __nv_bfloat16 *prawA, *plabA, *pxpA, *px1A, *phfA, *pff1A;
    __nv_bfloat16 *pW2T, *pWrawT, *pWexT, *pWlabT, *pWf1T, *pWf2T;
    cudaGetSymbolAddress((void**)&px1, g_x1);     cudaGetSymbolAddress((void**)&px2, g_x2);
    cudaGetSymbolAddress((void**)&pxp, g_xp);     cudaGetSymbolAddress((void**)&pWraw, g_Wraw);
    cudaGetSymbolAddress((void**)&pWex, g_Wex);   cudaGetSymbolAddress((void**)&pWlab, g_Wlab);
    cudaGetSymbolAddress((void**)&ps1, g_stats1); cudaGetSymbolAddress((void**)&phf, g_hfin);
    cudaGetSymbolAddress((void**)&prawA, g_rawA); cudaGetSymbolAddress((void**)&plabA, g_labA);
    cudaGetSymbolAddress((void**)&pxpA, g_xpA);   cudaGetSymbolAddress((void**)&px1A, g_x1A);
    cudaGetSymbolAddress((void**)&phfA, g_hfA);   cudaGetSymbolAddress((void**)&pff1A, g_ff1A);
    cudaGetSymbolAddress((void**)&pW2T, g_W2T);   cudaGetSymbolAddress((void**)&pWrawT, g_WrawT);
    cudaGetSymbolAddress((void**)&pWexT, g_WexT); cudaGetSymbolAddress((void**)&pWlabT, g_WlabT);
    cudaGetSymbolAddress((void**)&pWf1T, g_Wf1T); cudaGetSymbolAddress((void**)&pWf2T, g_Wf2T);

    constexpr int SM256 = 3 * (128 * 80 + 256 * 80);   // 92160 B
    constexpr int SM64  = 3 * (128 * 80 + 64 * 80);    // 46080 B
    cudaFuncSetAttribute(k_tc_gemm<256>, cudaFuncAttributeMaxDynamicSharedMemorySize, SM256);
    cudaFuncSetAttribute(k_tc_gemm<64>,  cudaFuncAttributeMaxDynamicSharedMemorySize, SM64);

    // ---- prolog ----
    k_u<<<1, 256>>>(I.eemb, I.w_extra);
    fuse_weights_kernel<<<dim3(4, 4, 10), 256>>>(I.femb, I.eemb, I.lemb, I.W1);
    k_extra_pool<<<(R_ * N_) / 8, 256>>>(I.extra);

    // ---- weight splits (B-side, transposed to [N, 2K]) ----
    k_splitB<<<dim3(512, 1, 6), 256>>>(pWraw, (long long)V_*HID_, V_, HID_, pWrawT, (long long)HID_*2*V_);
    k_splitB<<<dim3(256, 1, 2), 256>>>(pWex,  (long long)VE_*HID_, VE_, HID_, pWexT, (long long)HID_*2*VE_);
    k_splitB<<<dim3(128, 1, 2), 256>>>(pWlab, (long long)OUT_*HID_, OUT_, HID_, pWlabT, (long long)HID_*2*OUT_);
    k_splitB<<<dim3(1024, 1, 5), 256>>>(I.W2, (long long)HID_*HID_, HID_, HID_, pW2T, (long long)HID_*2*HID_);
    k_splitB<<<dim3(1024, 1, 1), 256>>>(I.Wf1, 0, HID_, HID_, pWf1T, 0);
    k_splitB<<<dim3(128, 1, 1), 256>>>(I.Wf2, 0, HID_, OUT_, pWf2T, 0);

    // ---- activation splits (A-side, [M, 2K]) ----
    k_splitA<<<dim3(4096, 1, 6), 256>>>(I.raw, (long long)N_*V_, V_, V_, prawA, (long long)N_*2*V_);
    k_splitA<<<dim3(1024, 1, 2), 256>>>(I.label, (long long)N_*OUT_, OUT_, OUT_, plabA, (long long)N_*2*OUT_);
    k_splitA<<<dim3(2048, 1, 2), 256>>>(pxp, (long long)N_*VE_, VE_, VE_, pxpA, (long long)N_*2*VE_);

    for (int r = 0; r < R_; r++) {
        // x1 channels 0..2 : [N,2*256] planes @ [512,2*256]^T
        k_tc_gemm<256><<<dim3(HID_/256, N_/128, 3), 512, SM256>>>(
            prawA + (size_t)r*3*N_*(2*V_), (long long)N_*2*V_,
            pWrawT + (size_t)r*3*HID_*(2*V_), (long long)HID_*2*V_, V_,
            I.b1, HID_, px1, CH_, HID_, nullptr);
        // channel 3 (pooled extra), Kd=128
        k_tc_gemm<256><<<dim3(HID_/256, N_/128, 1), 512, SM256>>>(
            pxpA + (size_t)r*N_*(2*VE_), 0,
            pWexT + (size_t)r*HID_*(2*VE_), 0, VE_,
            I.b1 + 3*HID_, 0, px1 + 3*HID_, CH_, 0, nullptr);
        // channel 4 (label), Kd=64
        k_tc_gemm<256><<<dim3(HID_/256, N_/128, 1), 512, SM256>>>(
            plabA + (size_t)r*N_*(2*OUT_), 0,
            pWlabT + (size_t)r*HID_*(2*OUT_), 0, OUT_,
            I.b1 + 4*HID_, 0, px1 + 4*HID_, CH_, 0, nullptr);

        // LN1 stats -> fused LN+PReLU split -> W2 GEMM (Kd=512, z over C)
        k_stats<<<N_ / 8, 256>>>(px1, ps1);
        k_splitA_ln<<<dim3(8192, 1, C_), 256>>>(px1, ps1, I.g1, I.be1, I.a1, px1A);
        k_tc_gemm<256><<<dim3(HID_/256, N_/128, C_), 512, SM256>>>(
            px1A, (long long)N_*2*HID_,
            pW2T, (long long)HID_*2*HID_, HID_,
            I.b2, HID_, px2, CH_, HID_, nullptr);

        k_pool_c<<<N_, 256>>>(I.g2, I.be2, I.a2, I.w_r + r*HID_, r);
    }

    // ---- global pool + FFN head ----
    k_pool_global<<<N_ / 8, 256>>>(I.w_g);
    k_splitA<<<dim3(8192, 1, 1), 256>>>(phf, 0, HID_, HID_, phfA, 0);
    k_tc_gemm<256><<<dim3(HID_/256, N_/128, 1), 512, SM256>>>(
        phfA, 0, pWf1T, 0, HID_,
        I.bf1, 0, px2, HID_, 0, I.af);                 // PReLU out, [N,512]
    k_splitA<<<dim3(8192, 1, 1), 256>>>(px2, 0, HID_, HID_, pff1A, 0);
    k_tc_gemm<64><<<dim3(1, N_/128, 1), 128, SM64>>>(
        pff1A, 0, pWf2T, 0, HID_,
        I.bf2, 0, (float*)d_out, OUT_, 0, nullptr);
}

// round 10
// speedup vs baseline: 2.4141x; 1.2893x over previous
#include <cuda_runtime.h>
#include <cuda_bf16.h>
#include <math.h>

#define R_   2
#define K_   3
#define N_   16384
#define V_   256
#define L_   8
#define VE_  128
#define OUT_ 64
#define IN_  256
#define HID_ 512
#define C_   5
#define CH_  (C_*HID_)

// ---------------- fp32 workspace ----------------
__device__ float g_x1[(size_t)N_ * CH_];
__device__ float g_x2[(size_t)N_ * CH_];
__device__ float g_outr[(size_t)R_ * N_ * HID_];
__device__ float g_hfin[(size_t)N_ * HID_];
__device__ float g_xp[(size_t)R_ * N_ * VE_];
__device__ float g_u[R_ * VE_];
__device__ float g_Wraw[(size_t)R_ * K_ * V_ * HID_];
__device__ float g_Wex [(size_t)R_ * VE_ * HID_];
__device__ float g_Wlab[(size_t)R_ * OUT_ * HID_];

// ---------------- bf16 2-plane split workspace ([hi|lo], width 2K) ----------------
__device__ __align__(16) __nv_bfloat16 g_rawA[(size_t)R_ * K_ * N_ * (2*V_)];
__device__ __align__(16) __nv_bfloat16 g_labA[(size_t)R_ * N_ * (2*OUT_)];
__device__ __align__(16) __nv_bfloat16 g_xpA [(size_t)R_ * N_ * (2*VE_)];
__device__ __align__(16) __nv_bfloat16 g_x1A [(size_t)C_ * N_ * (2*HID_)];
__device__ __align__(16) __nv_bfloat16 g_hfA [(size_t)N_ * (2*HID_)];
__device__ __align__(16) __nv_bfloat16 g_ff1A[(size_t)N_ * (2*HID_)];
__device__ __align__(16) __nv_bfloat16 g_W2T  [(size_t)C_ * HID_ * (2*HID_)];
__device__ __align__(16) __nv_bfloat16 g_WrawT[(size_t)R_ * K_ * HID_ * (2*V_)];
__device__ __align__(16) __nv_bfloat16 g_WexT [(size_t)R_ * HID_ * (2*VE_)];
__device__ __align__(16) __nv_bfloat16 g_WlabT[(size_t)R_ * HID_ * (2*OUT_)];
__device__ __align__(16) __nv_bfloat16 g_Wf1T [(size_t)HID_ * (2*HID_)];
__device__ __align__(16) __nv_bfloat16 g_Wf2T [(size_t)OUT_ * (2*HID_)];

// ---------------- PTX helpers (base-target features only) ----------------
__device__ __forceinline__ unsigned smem_u32(const void* p) {
    unsigned a;
    asm("{ .reg .u64 t; cvta.to.shared.u64 t, %1; cvt.u32.u64 %0, t; }" : "=r"(a) : "l"(p));
    return a;
}
__device__ __forceinline__ void cp16(unsigned dst, const void* src) {
    asm volatile("cp.async.cg.shared.global [%0], [%1], 16;" :: "r"(dst), "l"(src) : "memory");
}
__device__ __forceinline__ void ldsm4(unsigned* r, unsigned addr) {
    asm volatile("ldmatrix.sync.aligned.m8n8.x4.shared.b16 {%0,%1,%2,%3}, [%4];"
        : "=r"(r[0]), "=r"(r[1]), "=r"(r[2]), "=r"(r[3]) : "r"(addr));
}
__device__ __forceinline__ void mma16816(float* d, const unsigned* a, const unsigned* b) {
    asm volatile(
        "mma.sync.aligned.m16n8k16.row.col.f32.bf16.bf16.f32 "
        "{%0,%1,%2,%3}, {%4,%5,%6,%7}, {%8,%9}, {%0,%1,%2,%3};"
        : "+f"(d[0]), "+f"(d[1]), "+f"(d[2]), "+f"(d[3])
        : "r"(a[0]), "r"(a[1]), "r"(a[2]), "r"(a[3]), "r"(b[0]), "r"(b[1]));
}

// =========================================================================
// bf16 tensor-core GEMM, fused 3-product split per k-block.
// Logical C[M,Ncols] = Ah.Bh^T + Ah.Bl^T + Al.Bh^T  (A,B 2-plane [hi|lo]).
// Each k-block stages {Ah, Al, Bh, Bl} (BKx) and runs all 3 phases before
// the next barrier -> 1/3 the k-iterations/syncs of phase-sequential.
// CTA: 128 x BN; warps 4(M) x (BN/64)(N); warp tile 32x64; BK=32; 3 stages.
// =========================================================================
template<int BN>
__global__ void __launch_bounds__(128 * (BN > 64 ? BN / 64 : 1), 1) k_tc_gemm(
    const __nv_bfloat16* __restrict__ A, long long aZ,
    const __nv_bfloat16* __restrict__ B, long long bZ, int Kd,
    const float* __restrict__ bias, long long biasZ,
    float* __restrict__ Co, int ldc, long long cZ,
    const float* __restrict__ alpha_p)
{
    constexpr int BM = 128, BK = 32;
    constexpr int NWN = (BN > 64 ? BN / 64 : 1);
    constexpr int THREADS = 128 * NWN;
    constexpr int WN  = BN / NWN;                 // 64
    constexpr int NT8 = WN / 8;                   // 8
    constexpr int ABP = BM * 80;                  // one A plane (pitch 80 B)
    constexpr int BBP = BN * 80;
    constexpr int STAGE = 2 * ABP + 2 * BBP;
    constexpr int APL = BM * 4, BPL = BN * 4;     // 16B chunks per plane
    constexpr int TOT = 2 * (APL + BPL);

    extern __shared__ char smem[];
    const int tid = threadIdx.x, lane = tid & 31, wid = tid >> 5;
    const int warp_m = wid & 3, warp_n = wid >> 2;
    const int m0 = blockIdx.y * BM, n0 = blockIdx.x * BN;
    const long long z = blockIdx.z;
    const int ldAB = 2 * Kd;
    const __nv_bfloat16* Az = A + z * aZ;
    const __nv_bfloat16* Bz = B + z * bZ;
    float* Cz = Co + z * cZ;
    const float* biasz = bias ? bias + z * biasZ : nullptr;

    const unsigned sb = smem_u32(smem);
    const int nkb = Kd / BK;

    float acc[2][NT8][4];
    #pragma unroll
    for (int mt = 0; mt < 2; mt++)
        #pragma unroll
        for (int nt = 0; nt < NT8; nt++)
            #pragma unroll
            for (int j = 0; j < 4; j++) acc[mt][nt][j] = 0.f;

    auto load = [&](int kb) {
        if (kb < nkb) {
            unsigned st = sb + (unsigned)(kb % 3) * STAGE;
            int k0 = kb * BK;
            #pragma unroll
            for (int q = 0; q < TOT / THREADS; q++) {
                int ch = tid + q * THREADS;
                unsigned dst; const __nv_bfloat16* src;
                if (ch < 2 * APL) {
                    int pl = (ch >= APL) ? 1 : 0;
                    int cc = ch - pl * APL;
                    int row = cc >> 2, c = cc & 3;
                    dst = st + pl * ABP + row * 80 + c * 16;
                    src = Az + (size_t)(m0 + row) * ldAB + pl * Kd + k0 + c * 8;
                } else {
                    int ch2 = ch - 2 * APL;
                    int pl = (ch2 >= BPL) ? 1 : 0;
                    int cc = ch2 - pl * BPL;
                    int row = cc >> 2, c = cc & 3;
                    dst = st + 2 * ABP + pl * BBP + row * 80 + c * 16;
                    src = Bz + (size_t)(n0 + row) * ldAB + pl * Kd + k0 + c * 8;
                }
                cp16(dst, src);
            }
        }
        asm volatile("cp.async.commit_group;" ::: "memory");
    };

    load(0); load(1); load(2);

    for (int kb = 0; kb < nkb; kb++) {
        asm volatile("cp.async.wait_group 2;" ::: "memory");
        __syncthreads();
        unsigned st = sb + (unsigned)(kb % 3) * STAGE;
        unsigned ah = st, al = st + ABP, bh = st + 2 * ABP, bl = bh + BBP;

        #pragma unroll
        for (int ks = 0; ks < 2; ks++) {
            int k0 = ks * 16;
            unsigned af[2][4], bf[NT8 / 2][4];
            const int arow = warp_m * 32 + (lane & 15);
            const unsigned aoff = (unsigned)(arow * 80 + (k0 + (lane >> 4) * 8) * 2);
            const int rowi = lane & 7, quad = lane >> 3;
            const int nofs = (quad >> 1) * 8, kofs = (quad & 1) * 8;
            const unsigned bkc = (unsigned)((k0 + kofs) * 2);

            // phase 0: Ah . Bh
            ldsm4(af[0], ah + aoff);
            ldsm4(af[1], ah + aoff + 16 * 80);
            #pragma unroll
            for (int j = 0; j < NT8 / 2; j++) {
                int nb = warp_n * WN + j * 16 + nofs + rowi;
                ldsm4(bf[j], bh + nb * 80 + bkc);
            }
            #pragma unroll
            for (int mt = 0; mt < 2; mt++)
                #pragma unroll
                for (int nt = 0; nt < NT8; nt++)
                    mma16816(acc[mt][nt], af[mt], &bf[nt >> 1][(nt & 1) * 2]);

            // phase 2: Al . Bh  (bf reused)
            ldsm4(af[0], al + aoff);
            ldsm4(af[1], al + aoff + 16 * 80);
            #pragma unroll
            for (int mt = 0; mt < 2; mt++)
                #pragma unroll
                for (int nt = 0; nt < NT8; nt++)
                    mma16816(acc[mt][nt], af[mt], &bf[nt >> 1][(nt & 1) * 2]);

            // phase 1: Ah . Bl
            ldsm4(af[0], ah + aoff);
            ldsm4(af[1], ah + aoff + 16 * 80);
            #pragma unroll
            for (int j = 0; j < NT8 / 2; j++) {
                int nb = warp_n * WN + j * 16 + nofs + rowi;
                ldsm4(bf[j], bl + nb * 80 + bkc);
            }
            #pragma unroll
            for (int mt = 0; mt < 2; mt++)
                #pragma unroll
                for (int nt = 0; nt < NT8; nt++)
                    mma16816(acc[mt][nt], af[mt], &bf[nt >> 1][(nt & 1) * 2]);
        }
        __syncthreads();
        load(kb + 3);
    }

    // ---- epilogue ----
    float alpha = alpha_p ? __ldg(alpha_p) : 0.f;
    int g = lane >> 2, q = lane & 3;
    #pragma unroll
    for (int mt = 0; mt < 2; mt++) {
        int row = m0 + warp_m * 32 + mt * 16 + g;
        #pragma unroll
        for (int nt = 0; nt < NT8; nt++) {
            int col = n0 + warp_n * WN + nt * 8 + q * 2;
            float b0 = 0.f, b1 = 0.f;
            if (biasz) { b0 = biasz[col]; b1 = biasz[col + 1]; }
            float2 v0 = make_float2(acc[mt][nt][0] + b0, acc[mt][nt][1] + b1);
            float2 v1 = make_float2(acc[mt][nt][2] + b0, acc[mt][nt][3] + b1);
            if (alpha_p) {
                v0.x = v0.x >= 0.f ? v0.x : alpha * v0.x;
                v0.y = v0.y >= 0.f ? v0.y : alpha * v0.y;
                v1.x = v1.x >= 0.f ? v1.x : alpha * v1.x;
                v1.y = v1.y >= 0.f ? v1.y : alpha * v1.y;
            }
            *reinterpret_cast<float2*>(Cz + (size_t)row * ldc + col) = v0;
            *reinterpret_cast<float2*>(Cz + (size_t)(row + 8) * ldc + col) = v1;
        }
    }
}

// ---------------- split conversions (2-plane [hi|lo]) ----------------
__device__ __forceinline__ void split2(float x, unsigned short& h, unsigned short& l) {
    __nv_bfloat16 hb = __float2bfloat16(x);
    __nv_bfloat16 lb = __float2bfloat16(x - __bfloat162float(hb));
    h = __bfloat16_as_ushort(hb); l = __bfloat16_as_ushort(lb);
}

// A-side: fp32 [N_, ldin] -> bf16 [N_, 2K]
__global__ void __launch_bounds__(256) k_splitA(
    const float* __restrict__ in, long long inZ, int ldin, int K,
    __nv_bfloat16* __restrict__ out, long long outZ)
{
    long long z = blockIdx.z;
    in += z * inZ; out += z * outZ;
    int K4 = K / 4;
    int idx = blockIdx.x * 256 + threadIdx.x;
    if (idx >= N_ * K4) return;
    int m = idx / K4, k4 = (idx % K4) * 4;
    float4 v = *reinterpret_cast<const float4*>(in + (size_t)m * ldin + k4);
    ushort4 h, l;
    split2(v.x, h.x, l.x); split2(v.y, h.y, l.y);
    split2(v.z, h.z, l.z); split2(v.w, h.w, l.w);
    size_t b = (size_t)m * 2 * K;
    *reinterpret_cast<ushort4*>(out + b + k4) = h;
    *reinterpret_cast<ushort4*>(out + b + K + k4) = l;
}

// Fused per-row LN1 stats + LN + PReLU + split. Block per row n.
// x1 row [C*HID] -> per-channel planes out[c][n][2*HID] = [hi|lo].
__global__ void __launch_bounds__(256) k_lnsplit(
    const float* __restrict__ x1,
    const float* __restrict__ g1, const float* __restrict__ be1,
    const float* __restrict__ a1p, __nv_bfloat16* __restrict__ out)
{
    int n = blockIdx.x, tid = threadIdx.x;
    __shared__ __align__(16) float sx[CH_];
    __shared__ float rsum[8], rsum2[8], smn, srs;
    const float* xr = x1 + (size_t)n * CH_;

    float s = 0.f, s2 = 0.f;
    for (int i = tid; i < CH_ / 4; i += 256) {
        float4 t = reinterpret_cast<const float4*>(xr)[i];
        reinterpret_cast<float4*>(sx)[i] = t;
        s  += t.x + t.y + t.z + t.w;
        s2 += t.x*t.x + t.y*t.y + t.z*t.z + t.w*t.w;
    }
    int lane = tid & 31, wid = tid >> 5;
    #pragma unroll
    for (int o = 16; o > 0; o >>= 1) {
        s  += __shfl_xor_sync(0xffffffffu, s,  o);
        s2 += __shfl_xor_sync(0xffffffffu, s2, o);
    }
    if (lane == 0) { rsum[wid] = s; rsum2[wid] = s2; }
    __syncthreads();
    if (tid == 0) {
        float ts = 0.f, ts2 = 0.f;
        #pragma unroll
        for (int w2 = 0; w2 < 8; w2++) { ts += rsum[w2]; ts2 += rsum2[w2]; }
        float m = ts / (float)CH_;
        smn = m; srs = rsqrtf(ts2 / (float)CH_ - m * m + 1e-5f);
    }
    __syncthreads();

    float mn = smn, rs = srs, a = __ldg(a1p);
    for (int i4 = tid; i4 < CH_ / 4; i4 += 256) {
        int i = i4 * 4;
        int c = i / HID_, col = i % HID_;
        float4 v = reinterpret_cast<const float4*>(sx)[i4];
        float4 g = reinterpret_cast<const float4*>(g1)[i4];
        float4 b = reinterpret_cast<const float4*>(be1)[i4];
        v.x = (v.x-mn)*rs*g.x + b.x; v.y = (v.y-mn)*rs*g.y + b.y;
        v.z = (v.z-mn)*rs*g.z + b.z; v.w = (v.w-mn)*rs*g.w + b.w;
        v.x = v.x >= 0.f ? v.x : a*v.x; v.y = v.y >= 0.f ? v.y : a*v.y;
        v.z = v.z >= 0.f ? v.z : a*v.z; v.w = v.w >= 0.f ? v.w : a*v.w;
        ushort4 h, l;
        split2(v.x, h.x, l.x); split2(v.y, h.y, l.y);
        split2(v.z, h.z, l.z); split2(v.w, h.w, l.w);
        __nv_bfloat16* op = out + (size_t)c * N_ * (2*HID_) + (size_t)n * (2*HID_);
        *reinterpret_cast<ushort4*>(op + col) = h;
        *reinterpret_cast<ushort4*>(op + HID_ + col) = l;
    }
}

// B-side: fp32 [Kd, Nn] -> bf16 [Nn, 2Kd] (transposed)
__global__ void __launch_bounds__(256) k_splitB(
    const float* __restrict__ in, long long inZ, int Kd, int Nn,
    __nv_bfloat16* __restrict__ out, long long outZ)
{
    long long z = blockIdx.z;
    in += z * inZ; out += z * outZ;
    int idx = blockIdx.x * 256 + threadIdx.x;
    if (idx >= Kd * Nn) return;
    int n = idx / Kd, k = idx % Kd;
    float x = in[(size_t)k * Nn + n];
    unsigned short h, l;
    split2(x, h, l);
    size_t b = (size_t)n * 2 * Kd;
    out[b + k] = __ushort_as_bfloat16(h);
    out[b + Kd + k] = __ushort_as_bfloat16(l);
}

// ---------------- plain fp32 GEMM for tiny weight fusion ----------------
__global__ void __launch_bounds__(256, 2) fuse_weights_kernel(
    const float* __restrict__ femb, const float* __restrict__ eemb,
    const float* __restrict__ lemb, const float* __restrict__ W1)
{
    constexpr int BM = 64, TM = 4, BN = 128, BK = 16, TN = 8;
    int zz = blockIdx.z, r = zz / C_, c = zz % C_;
    const float* A; int M; float* out;
    if (c < K_)      { A = femb + (size_t)(r*K_+c)*V_*IN_; M = V_;   out = g_Wraw + (size_t)(r*K_+c)*V_*HID_; }
    else if (c == 3) { A = eemb + (size_t)r*VE_*IN_;       M = VE_;  out = g_Wex  + (size_t)r*VE_*HID_; }
    else             { A = lemb + (size_t)r*OUT_*IN_;      M = OUT_; out = g_Wlab + (size_t)r*OUT_*HID_; }
    const float* B = W1 + (size_t)c * IN_ * HID_;

    __shared__ __align__(16) float As[BK][BM+4];
    __shared__ __align__(16) float Bs[BK][BN];
    int tid = threadIdx.x, tx = tid % (BN/TN), ty = tid / (BN/TN);
    int row0 = blockIdx.y * BM, col0 = blockIdx.x * BN;
    float acc[TM][TN] = {};
    for (int k0 = 0; k0 < IN_; k0 += BK) {
        for (int v = tid; v < BM*(BK/4); v += 256) {
            int rr = v / (BK/4), kq = (v % (BK/4)) * 4, gr = row0 + rr;
            float4 val = make_float4(0,0,0,0);
            if (gr < M) val = *reinterpret_cast<const float4*>(A + (size_t)gr*IN_ + k0 + kq);
            As[kq][rr] = val.x; As[kq+1][rr] = val.y; As[kq+2][rr] = val.z; As[kq+3][rr] = val.w;
        }
        for (int v = tid; v < BK*(BN/4); v += 256) {
            int rr = v / (BN/4), c4 = (v % (BN/4)) * 4;
            *reinterpret_cast<float4*>(&Bs[rr][c4]) =
                *reinterpret_cast<const float4*>(B + (size_t)(k0+rr)*HID_ + col0 + c4);
        }
        __syncthreads();
        #pragma unroll
        for (int kk = 0; kk < BK; kk++) {
            float a[TM], b[TN];
            #pragma unroll
            for (int i = 0; i < TM; i++) a[i] = As[kk][ty*TM+i];
            #pragma unroll
            for (int j = 0; j < TN; j++) b[j] = Bs[kk][tx*TN+j];
            #pragma unroll
            for (int i = 0; i < TM; i++)
                #pragma unroll
                for (int j = 0; j < TN; j++) acc[i][j] += a[i]*b[j];
        }
        __syncthreads();
    }
    #pragma unroll
    for (int i = 0; i < TM; i++) {
        int gr = row0 + ty*TM + i;
        if (gr >= M) continue;
        #pragma unroll
        for (int j = 0; j < TN; j++) out[(size_t)gr*HID_ + col0 + tx*TN + j] = acc[i][j];
    }
}

// ---------------- small SIMT kernels ----------------
__global__ void k_u(const float* __restrict__ eemb, const float* __restrict__ wx)
{
    int t = blockIdx.x * blockDim.x + threadIdx.x;
    if (t >= R_ * VE_) return;
    const float* row = eemb + (size_t)t * IN_;
    float s = 0.f;
    for (int d = 0; d < IN_; d++) s += row[d] * wx[d];
    g_u[t] = s;
}

__global__ void __launch_bounds__(256) k_extra_pool(const float* __restrict__ extra)
{
    int wg = (blockIdx.x * blockDim.x + threadIdx.x) >> 5, lane = threadIdx.x & 31;
    if (wg >= R_ * N_) return;
    int r = wg / N_;
    const float* base = extra + (size_t)wg * (L_ * VE_);
    float u[4];
    #pragma unroll
    for (int j = 0; j < 4; j++) u[j] = g_u[r * VE_ + lane + 32*j];
    float x[L_][4], s[L_];
    #pragma unroll
    for (int l = 0; l < L_; l++) {
        float p = 0.f;
        #pragma unroll
        for (int j = 0; j < 4; j++) { x[l][j] = base[l*VE_ + lane + 32*j]; p += x[l][j]*u[j]; }
        #pragma unroll
        for (int o = 16; o > 0; o >>= 1) p += __shfl_xor_sync(0xffffffffu, p, o);
        s[l] = 1.f / (1.f + expf(-p));
    }
    float mx = s[0];
    #pragma unroll
    for (int l = 1; l < L_; l++) mx = fmaxf(mx, s[l]);
    float e[L_], es = 0.f;
    #pragma unroll
    for (int l = 0; l < L_; l++) { e[l] = expf(s[l]-mx); es += e[l]; }
    float inv = 1.f / es, out[4] = {0,0,0,0};
    #pragma unroll
    for (int l = 0; l < L_; l++) {
        float w = e[l]*inv;
        #pragma unroll
        for (int j = 0; j < 4; j++) out[j] += w * x[l][j];
    }
    float* op = g_xp + (size_t)wg * VE_;
    #pragma unroll
    for (int j = 0; j < 4; j++) op[lane + 32*j] = out[j];
}

__global__ void __launch_bounds__(256) k_pool_c(
    const float* __restrict__ g2, const float* __restrict__ be2,
    const float* __restrict__ a2p, const float* __restrict__ wr, int r)
{
    int n = blockIdx.x, tid = threadIdx.x;
    __shared__ __align__(16) float sx[CH_];
    __shared__ float red[C_][8], rsum[8], rsum2[8], salpha[C_], smn, srs;
    const float* xr = g_x2 + (size_t)n * CH_;
    float s = 0.f, s2 = 0.f;
    for (int i = tid; i < CH_/4; i += 256) {
        float4 t = reinterpret_cast<const float4*>(xr)[i];
        reinterpret_cast<float4*>(sx)[i] = t;
        s += t.x+t.y+t.z+t.w; s2 += t.x*t.x+t.y*t.y+t.z*t.z+t.w*t.w;
    }
    int lane = tid & 31, wid = tid >> 5;
    #pragma unroll
    for (int o = 16; o > 0; o >>= 1) {
        s += __shfl_xor_sync(0xffffffffu, s, o);
        s2 += __shfl_xor_sync(0xffffffffu, s2, o);
    }
    if (lane == 0) { rsum[wid] = s; rsum2[wid] = s2; }
    __syncthreads();
    if (tid == 0) {
        float ts = 0.f, ts2 = 0.f;
        #pragma unroll
        for (int w2 = 0; w2 < 8; w2++) { ts += rsum[w2]; ts2 += rsum2[w2]; }
        float m = ts/(float)CH_;
        smn = m; srs = rsqrtf(ts2/(float)CH_ - m*m + 1e-5f);
    }
    __syncthreads();
    float mn = smn, rs = srs, a = __ldg(a2p);
    for (int i = tid; i < CH_; i += 256) {
        float v = (sx[i]-mn)*rs*g2[i] + be2[i];
        sx[i] = v >= 0.f ? v : a*v;
    }
    __syncthreads();
    float p[C_] = {0,0,0,0,0};
    for (int h = tid; h < HID_; h += 256) {
        float w = wr[h];
        #pragma unroll
        for (int c = 0; c < C_; c++) p[c] += sx[c*HID_+h] * w;
    }
    #pragma unroll
    for (int c = 0; c < C_; c++)
        #pragma unroll
        for (int o = 16; o > 0; o >>= 1) p[c] += __shfl_xor_sync(0xffffffffu, p[c], o);
    if (lane == 0)
        #pragma unroll
        for (int c = 0; c < C_; c++) red[c][wid] = p[c];
    __syncthreads();
    if (tid == 0) {
        float sv[C_], mx = -1e30f;
        #pragma unroll
        for (int c = 0; c < C_; c++) {
            float t = 0.f;
            #pragma unroll
            for (int w2 = 0; w2 < 8; w2++) t += red[c][w2];
            sv[c] = 1.f / (1.f + expf(-t)); mx = fmaxf(mx, sv[c]);
        }
        float es = 0.f, e[C_];
        #pragma unroll
        for (int c = 0; c < C_; c++) { e[c] = expf(sv[c]-mx); es += e[c]; }
        #pragma unroll
        for (int c = 0; c < C_; c++) salpha[c] = e[c] / es;
    }
    __syncthreads();
    float* op = g_outr + (size_t)r * N_ * HID_ + (size_t)n * HID_;
    for (int h = tid; h < HID_; h += 256) {
        float acc = 0.f;
        #pragma unroll
        for (int c = 0; c < C_; c++) acc += salpha[c] * sx[c*HID_+h];
        op[h] = acc;
    }
}

__global__ void __launch_bounds__(256) k_pool_global(const float* __restrict__ wg)
{
    int w = (blockIdx.x * blockDim.x + threadIdx.x) >> 5, lane = threadIdx.x & 31;
    if (w >= N_) return;
    const float* pa = g_outr + (size_t)w * HID_;
    const float* pb = g_outr + (size_t)N_ * HID_ + (size_t)w * HID_;
    float a[16], b[16], sa = 0.f, sb = 0.f;
    #pragma unroll
    for (int j = 0; j < 16; j++) {
        int h = lane + 32*j;
        a[j] = pa[h]; b[j] = pb[h];
        float wv = wg[h];
        sa += a[j]*wv; sb += b[j]*wv;
    }
    #pragma unroll
    for (int o = 16; o > 0; o >>= 1) {
        sa += __shfl_xor_sync(0xffffffffu, sa, o);
        sb += __shfl_xor_sync(0xffffffffu, sb, o);
    }
    sa = 1.f/(1.f+expf(-sa)); sb = 1.f/(1.f+expf(-sb));
    float mx = fmaxf(sa, sb), ea = expf(sa-mx), eb = expf(sb-mx);
    float aa = ea/(ea+eb), ab = 1.f - aa;
    float* op = g_hfin + (size_t)w * HID_;
    #pragma unroll
    for (int j = 0; j < 16; j++) op[lane + 32*j] = aa*a[j] + ab*b[j];
}

// ---------------- input mapping ----------------
struct Ins {
    const float *raw, *extra, *label, *femb, *eemb, *lemb;
    const float *w_extra, *w_r, *w_g;
    const float *W1, *b1, *g1, *be1, *a1, *W2, *b2, *g2, *be2, *a2;
    const float *Wf1, *bf1, *af, *Wf2, *bf2;
};
static void resolve(void* const* d_in, const int* sz, Ins& I)
{
    auto F = [&](int i) { return (const float*)d_in[i]; };
    if (sz[0] == R_ * K_ * N_ * V_) {
        I.raw=F(0); I.extra=F(1); I.label=F(2); I.femb=F(3); I.eemb=F(4); I.lemb=F(5);
        I.w_extra=F(6); I.w_r=F(7); I.w_g=F(8);
        I.W1=F(9); I.b1=F(10); I.g1=F(11); I.be1=F(12); I.a1=F(13);
        I.W2=F(14); I.b2=F(15); I.g2=F(16); I.be2=F(17); I.a2=F(18);
        I.Wf1=F(19); I.bf1=F(20); I.af=F(21); I.Wf2=F(22); I.bf2=F(23);
    } else {
        I.W1=F(0); I.W2=F(1); I.Wf1=F(2); I.Wf2=F(3);
        I.a1=F(4); I.a2=F(5); I.af=F(6);
        I.b1=F(7); I.b2=F(8); I.be1=F(9); I.be2=F(10); I.bf1=F(11); I.bf2=F(12);
        I.eemb=F(13); I.extra=F(14); I.femb=F(15); I.g1=F(16); I.g2=F(17);
        I.lemb=F(18); I.label=F(19); I.raw=F(20);
        I.w_extra=F(21); I.w_g=F(22); I.w_r=F(23);
    }
}

extern "C" void kernel_launch(void* const* d_in, const int* in_sizes, int n_in,
                              void* d_out, int out_size)
{
    if (n_in < 24) return;
    Ins I; resolve(d_in, in_sizes, I);

    float *px1, *px2, *pxp, *pWraw, *pWex, *pWlab, *phf;
    __nv_bfloat16 *prawA, *plabA, *pxpA, *px1A, *phfA, *pff1A;
    __nv_bfloat16 *pW2T, *pWrawT, *pWexT, *pWlabT, *pWf1T, *pWf2T;
    cudaGetSymbolAddress((void**)&px1, g_x1);     cudaGetSymbolAddress((void**)&px2, g_x2);
    cudaGetSymbolAddress((void**)&pxp, g_xp);     cudaGetSymbolAddress((void**)&pWraw, g_Wraw);
    cudaGetSymbolAddress((void**)&pWex, g_Wex);   cudaGetSymbolAddress((void**)&pWlab, g_Wlab);
    cudaGetSymbolAddress((void**)&phf, g_hfin);
    cudaGetSymbolAddress((void**)&prawA, g_rawA); cudaGetSymbolAddress((void**)&plabA, g_labA);
    cudaGetSymbolAddress((void**)&pxpA, g_xpA);   cudaGetSymbolAddress((void**)&px1A, g_x1A);
    cudaGetSymbolAddress((void**)&phfA, g_hfA);   cudaGetSymbolAddress((void**)&pff1A, g_ff1A);
    cudaGetSymbolAddress((void**)&pW2T, g_W2T);   cudaGetSymbolAddress((void**)&pWrawT, g_WrawT);
    cudaGetSymbolAddress((void**)&pWexT, g_WexT); cudaGetSymbolAddress((void**)&pWlabT, g_WlabT);
    cudaGetSymbolAddress((void**)&pWf1T, g_Wf1T); cudaGetSymbolAddress((void**)&pWf2T, g_Wf2T);

    constexpr int SM256 = 3 * (2 * 128 * 80 + 2 * 256 * 80);   // 184320 B
    constexpr int SM64  = 3 * (2 * 128 * 80 + 2 * 64 * 80);    // 92160 B
    cudaFuncSetAttribute(k_tc_gemm<256>, cudaFuncAttributeMaxDynamicSharedMemorySize, SM256);
    cudaFuncSetAttribute(k_tc_gemm<64>,  cudaFuncAttributeMaxDynamicSharedMemorySize, SM64);

    // ---- prolog (ordered so launch #6 = the raw GEMM, for ncu -s 5 -c 1) ----
    k_u<<<1, 256>>>(I.eemb, I.w_extra);                                          // 1
    fuse_weights_kernel<<<dim3(4, 4, 10), 256>>>(I.femb, I.eemb, I.lemb, I.W1);  // 2
    k_extra_pool<<<(R_ * N_) / 8, 256>>>(I.extra);                               // 3
    k_splitB<<<dim3(512, 1, 6), 256>>>(pWraw, (long long)V_*HID_, V_, HID_, pWrawT, (long long)HID_*2*V_);  // 4
    k_splitA<<<dim3(4096, 1, 6), 256>>>(I.raw, (long long)N_*V_, V_, V_, prawA, (long long)N_*2*V_);        // 5
    // r=0 raw GEMM — launch #6, profiled by ncu
    k_tc_gemm<256><<<dim3(HID_/256, N_/128, 3), 512, SM256>>>(
        prawA, (long long)N_*2*V_, pWrawT, (long long)HID_*2*V_, V_,
        I.b1, HID_, px1, CH_, HID_, nullptr);

    // ---- remaining weight/activation splits ----
    k_splitB<<<dim3(256, 1, 2), 256>>>(pWex,  (long long)VE_*HID_, VE_, HID_, pWexT, (long long)HID_*2*VE_);
    k_splitB<<<dim3(128, 1, 2), 256>>>(pWlab, (long long)OUT_*HID_, OUT_, HID_, pWlabT, (long long)HID_*2*OUT_);
    k_splitB<<<dim3(1024, 1, 5), 256>>>(I.W2, (long long)HID_*HID_, HID_, HID_, pW2T, (long long)HID_*2*HID_);
    k_splitB<<<dim3(1024, 1, 1), 256>>>(I.Wf1, 0, HID_, HID_, pWf1T, 0);
    k_splitB<<<dim3(128, 1, 1), 256>>>(I.Wf2, 0, HID_, OUT_, pWf2T, 0);
    k_splitA<<<dim3(1024, 1, 2), 256>>>(I.label, (long long)N_*OUT_, OUT_, OUT_, plabA, (long long)N_*2*OUT_);
    k_splitA<<<dim3(2048, 1, 2), 256>>>(pxp, (long long)N_*VE_, VE_, VE_, pxpA, (long long)N_*2*VE_);

    for (int r = 0; r < R_; r++) {
        if (r > 0) {
            k_tc_gemm<256><<<dim3(HID_/256, N_/128, 3), 512, SM256>>>(
                prawA + (size_t)r*3*N_*(2*V_), (long long)N_*2*V_,
                pWrawT + (size_t)r*3*HID_*(2*V_), (long long)HID_*2*V_, V_,
                I.b1, HID_, px1, CH_, HID_, nullptr);
        }
        // channel 3 (pooled extra), Kd=128
        k_tc_gemm<256><<<dim3(HID_/256, N_/128, 1), 512, SM256>>>(
            pxpA + (size_t)r*N_*(2*VE_), 0,
            pWexT + (size_t)r*HID_*(2*VE_), 0, VE_,
            I.b1 + 3*HID_, 0, px1 + 3*HID_, CH_, 0, nullptr);
        // channel 4 (label), Kd=64
        k_tc_gemm<256><<<dim3(HID_/256, N_/128, 1), 512, SM256>>>(
            plabA + (size_t)r*N_*(2*OUT_), 0,
            pWlabT + (size_t)r*HID_*(2*OUT_), 0, OUT_,
            I.b1 + 4*HID_, 0, px1 + 4*HID_, CH_, 0, nullptr);

        // fused LN1 stats + LN + PReLU + split -> W2 GEMM (Kd=512, z over C)
        k_lnsplit<<<N_, 256>>>(px1, I.g1, I.be1, I.a1, px1A);
        k_tc_gemm<256><<<dim3(HID_/256, N_/128, C_), 512, SM256>>>(
            px1A, (long long)N_*2*HID_,
            pW2T, (long long)HID_*2*HID_, HID_,
            I.b2, HID_, px2, CH_, HID_, nullptr);

        k_pool_c<<<N_, 256>>>(I.g2, I.be2, I.a2, I.w_r + r*HID_, r);
    }

    // ---- global pool + FFN head ----
    k_pool_global<<<N_ / 8, 256>>>(I.w_g);
    k_splitA<<<dim3(8192, 1, 1), 256>>>(phf, 0, HID_, HID_, phfA, 0);
    k_tc_gemm<256><<<dim3(HID_/256, N_/128, 1), 512, SM256>>>(
        phfA, 0, pWf1T, 0, HID_,
        I.bf1, 0, px2, HID_, 0, I.af);                 // PReLU out, [N,512]
    k_splitA<<<dim3(8192, 1, 1), 256>>>(px2, 0, HID_, HID_, pff1A, 0);
    k_tc_gemm<64><<<dim3(1, N_/128, 1), 128, SM64>>>(
        pff1A, 0, pWf2T, 0, HID_,
        I.bf2, 0, (float*)d_out, OUT_, 0, nullptr);
}

// round 11
// speedup vs baseline: 2.5012x; 1.0361x over previous
#include <cuda_runtime.h>
#include <cuda_bf16.h>
#include <math.h>

#define R_   2
#define K_   3
#define N_   16384
#define V_   256
#define L_   8
#define VE_  128
#define OUT_ 64
#define IN_  256
#define HID_ 512
#define C_   5
#define CH_  (C_*HID_)

// ---------------- fp32 workspace (both relations resident) ----------------
__device__ float g_x1[(size_t)R_ * N_ * CH_];
__device__ float g_x2[(size_t)R_ * N_ * CH_];
__device__ float g_outr[(size_t)R_ * N_ * HID_];
__device__ float g_hfin[(size_t)N_ * HID_];
__device__ float g_xp[(size_t)R_ * N_ * VE_];
__device__ float g_u[R_ * VE_];
__device__ float g_Wraw[(size_t)R_ * K_ * V_ * HID_];
__device__ float g_Wex [(size_t)R_ * VE_ * HID_];
__device__ float g_Wlab[(size_t)R_ * OUT_ * HID_];

// ---------------- bf16 2-plane split workspace ([hi|lo], width 2K) ----------------
__device__ __align__(16) __nv_bfloat16 g_rawA[(size_t)R_ * K_ * N_ * (2*V_)];
__device__ __align__(16) __nv_bfloat16 g_labA[(size_t)R_ * N_ * (2*OUT_)];
__device__ __align__(16) __nv_bfloat16 g_xpA [(size_t)R_ * N_ * (2*VE_)];
__device__ __align__(16) __nv_bfloat16 g_x1A [(size_t)R_ * C_ * N_ * (2*HID_)];
__device__ __align__(16) __nv_bfloat16 g_hfA [(size_t)N_ * (2*HID_)];
__device__ __align__(16) __nv_bfloat16 g_ff1A[(size_t)N_ * (2*HID_)];
__device__ __align__(16) __nv_bfloat16 g_W2T  [(size_t)C_ * HID_ * (2*HID_)];
__device__ __align__(16) __nv_bfloat16 g_WrawT[(size_t)R_ * K_ * HID_ * (2*V_)];
__device__ __align__(16) __nv_bfloat16 g_WexT [(size_t)R_ * HID_ * (2*VE_)];
__device__ __align__(16) __nv_bfloat16 g_WlabT[(size_t)R_ * HID_ * (2*OUT_)];
__device__ __align__(16) __nv_bfloat16 g_Wf1T [(size_t)HID_ * (2*HID_)];
__device__ __align__(16) __nv_bfloat16 g_Wf2T [(size_t)OUT_ * (2*HID_)];

// ---------------- PTX helpers ----------------
__device__ __forceinline__ unsigned smem_u32(const void* p) {
    unsigned a;
    asm("{ .reg .u64 t; cvta.to.shared.u64 t, %1; cvt.u32.u64 %0, t; }" : "=r"(a) : "l"(p));
    return a;
}
__device__ __forceinline__ void cp16(unsigned dst, const void* src) {
    asm volatile("cp.async.cg.shared.global [%0], [%1], 16;" :: "r"(dst), "l"(src) : "memory");
}
__device__ __forceinline__ void ldsm4(unsigned* r, unsigned addr) {
    asm volatile("ldmatrix.sync.aligned.m8n8.x4.shared.b16 {%0,%1,%2,%3}, [%4];"
        : "=r"(r[0]), "=r"(r[1]), "=r"(r[2]), "=r"(r[3]) : "r"(addr));
}
__device__ __forceinline__ void mma16816(float* d, const unsigned* a, const unsigned* b) {
    asm volatile(
        "mma.sync.aligned.m16n8k16.row.col.f32.bf16.bf16.f32 "
        "{%0,%1,%2,%3}, {%4,%5,%6,%7}, {%8,%9}, {%0,%1,%2,%3};"
        : "+f"(d[0]), "+f"(d[1]), "+f"(d[2]), "+f"(d[3])
        : "r"(a[0]), "r"(a[1]), "r"(a[2]), "r"(a[3]), "r"(b[0]), "r"(b[1]));
}

// =========================================================================
// bf16 tensor-core GEMM, fused 3-product split per k-block.
// C = Ah.Bh^T + Ah.Bl^T + Al.Bh^T  (A,B 2-plane [hi|lo] along K).
// z decomposes: zo = z / zInner, zi = z % zInner for flexible batch strides.
// CTA: 128 x BN; warps 4(M) x (BN/64)(N); warp tile 32x64; BK=32; 3 stages.
// =========================================================================
template<int BN>
__global__ void __launch_bounds__(128 * (BN > 64 ? BN / 64 : 1), 1) k_tc_gemm(
    const __nv_bfloat16* __restrict__ A, long long aZo, long long aZi, int zInner,
    const __nv_bfloat16* __restrict__ B, long long bZo, long long bZi, int Kd,
    const float* __restrict__ bias, long long biasZi,
    float* __restrict__ Co, int ldc, long long cZo, long long cZi,
    const float* __restrict__ alpha_p)
{
    constexpr int BM = 128, BK = 32;
    constexpr int NWN = (BN > 64 ? BN / 64 : 1);
    constexpr int THREADS = 128 * NWN;
    constexpr int WN  = BN / NWN;                 // 64
    constexpr int NT8 = WN / 8;                   // 8
    constexpr int ABP = BM * 80;                  // one A plane (pitch 80 B)
    constexpr int BBP = BN * 80;
    constexpr int STAGE = 2 * ABP + 2 * BBP;
    constexpr int APL = BM * 4, BPL = BN * 4;     // 16B chunks per plane
    constexpr int TOT = 2 * (APL + BPL);

    extern __shared__ char smem[];
    const int tid = threadIdx.x, lane = tid & 31, wid = tid >> 5;
    const int warp_m = wid & 3, warp_n = wid >> 2;
    const int m0 = blockIdx.y * BM, n0 = blockIdx.x * BN;
    const int zo = blockIdx.z / zInner, zi = blockIdx.z % zInner;
    const int ldAB = 2 * Kd;
    const __nv_bfloat16* Az = A + (long long)zo * aZo + (long long)zi * aZi;
    const __nv_bfloat16* Bz = B + (long long)zo * bZo + (long long)zi * bZi;
    float* Cz = Co + (long long)zo * cZo + (long long)zi * cZi;
    const float* biasz = bias ? bias + (long long)zi * biasZi : nullptr;

    const unsigned sb = smem_u32(smem);
    const int nkb = Kd / BK;

    float acc[2][NT8][4];
    #pragma unroll
    for (int mt = 0; mt < 2; mt++)
        #pragma unroll
        for (int nt = 0; nt < NT8; nt++)
            #pragma unroll
            for (int j = 0; j < 4; j++) acc[mt][nt][j] = 0.f;

    auto load = [&](int kb) {
        if (kb < nkb) {
            unsigned st = sb + (unsigned)(kb % 3) * STAGE;
            int k0 = kb * BK;
            #pragma unroll
            for (int q = 0; q < TOT / THREADS; q++) {
                int ch = tid + q * THREADS;
                unsigned dst; const __nv_bfloat16* src;
                if (ch < 2 * APL) {
                    int pl = (ch >= APL) ? 1 : 0;
                    int cc = ch - pl * APL;
                    int row = cc >> 2, c = cc & 3;
                    dst = st + pl * ABP + row * 80 + c * 16;
                    src = Az + (size_t)(m0 + row) * ldAB + pl * Kd + k0 + c * 8;
                } else {
                    int ch2 = ch - 2 * APL;
                    int pl = (ch2 >= BPL) ? 1 : 0;
                    int cc = ch2 - pl * BPL;
                    int row = cc >> 2, c = cc & 3;
                    dst = st + 2 * ABP + pl * BBP + row * 80 + c * 16;
                    src = Bz + (size_t)(n0 + row) * ldAB + pl * Kd + k0 + c * 8;
                }
                cp16(dst, src);
            }
        }
        asm volatile("cp.async.commit_group;" ::: "memory");
    };

    load(0); load(1); load(2);

    for (int kb = 0; kb < nkb; kb++) {
        asm volatile("cp.async.wait_group 2;" ::: "memory");
        __syncthreads();
        unsigned st = sb + (unsigned)(kb % 3) * STAGE;
        unsigned ah = st, al = st + ABP, bh = st + 2 * ABP, bl = bh + BBP;

        #pragma unroll
        for (int ks = 0; ks < 2; ks++) {
            int k0 = ks * 16;
            unsigned af[2][4], bf[NT8 / 2][4];
            const int arow = warp_m * 32 + (lane & 15);
            const unsigned aoff = (unsigned)(arow * 80 + (k0 + (lane >> 4) * 8) * 2);
            const int rowi = lane & 7, quad = lane >> 3;
            const int nofs = (quad >> 1) * 8, kofs = (quad & 1) * 8;
            const unsigned bkc = (unsigned)((k0 + kofs) * 2);

            // phase 0: Ah . Bh
            ldsm4(af[0], ah + aoff);
            ldsm4(af[1], ah + aoff + 16 * 80);
            #pragma unroll
            for (int j = 0; j < NT8 / 2; j++) {
                int nb = warp_n * WN + j * 16 + nofs + rowi;
                ldsm4(bf[j], bh + nb * 80 + bkc);
            }
            #pragma unroll
            for (int mt = 0; mt < 2; mt++)
                #pragma unroll
                for (int nt = 0; nt < NT8; nt++)
                    mma16816(acc[mt][nt], af[mt], &bf[nt >> 1][(nt & 1) * 2]);

            // phase 2: Al . Bh  (bf reused)
            ldsm4(af[0], al + aoff);
            ldsm4(af[1], al + aoff + 16 * 80);
            #pragma unroll
            for (int mt = 0; mt < 2; mt++)
                #pragma unroll
                for (int nt = 0; nt < NT8; nt++)
                    mma16816(acc[mt][nt], af[mt], &bf[nt >> 1][(nt & 1) * 2]);

            // phase 1: Ah . Bl
            ldsm4(af[0], ah + aoff);
            ldsm4(af[1], ah + aoff + 16 * 80);
            #pragma unroll
            for (int j = 0; j < NT8 / 2; j++) {
                int nb = warp_n * WN + j * 16 + nofs + rowi;
                ldsm4(bf[j], bl + nb * 80 + bkc);
            }
            #pragma unroll
            for (int mt = 0; mt < 2; mt++)
                #pragma unroll
                for (int nt = 0; nt < NT8; nt++)
                    mma16816(acc[mt][nt], af[mt], &bf[nt >> 1][(nt & 1) * 2]);
        }
        __syncthreads();
        load(kb + 3);
    }

    // ---- epilogue ----
    float alpha = alpha_p ? __ldg(alpha_p) : 0.f;
    int g = lane >> 2, q = lane & 3;
    #pragma unroll
    for (int mt = 0; mt < 2; mt++) {
        int row = m0 + warp_m * 32 + mt * 16 + g;
        #pragma unroll
        for (int nt = 0; nt < NT8; nt++) {
            int col = n0 + warp_n * WN + nt * 8 + q * 2;
            float b0 = 0.f, b1 = 0.f;
            if (biasz) { b0 = biasz[col]; b1 = biasz[col + 1]; }
            float2 v0 = make_float2(acc[mt][nt][0] + b0, acc[mt][nt][1] + b1);
            float2 v1 = make_float2(acc[mt][nt][2] + b0, acc[mt][nt][3] + b1);
            if (alpha_p) {
                v0.x = v0.x >= 0.f ? v0.x : alpha * v0.x;
                v0.y = v0.y >= 0.f ? v0.y : alpha * v0.y;
                v1.x = v1.x >= 0.f ? v1.x : alpha * v1.x;
                v1.y = v1.y >= 0.f ? v1.y : alpha * v1.y;
            }
            *reinterpret_cast<float2*>(Cz + (size_t)row * ldc + col) = v0;
            *reinterpret_cast<float2*>(Cz + (size_t)(row + 8) * ldc + col) = v1;
        }
    }
}

// ---------------- split conversions (2-plane [hi|lo]) ----------------
__device__ __forceinline__ void split2(float x, unsigned short& h, unsigned short& l) {
    __nv_bfloat16 hb = __float2bfloat16(x);
    __nv_bfloat16 lb = __float2bfloat16(x - __bfloat162float(hb));
    h = __bfloat16_as_ushort(hb); l = __bfloat16_as_ushort(lb);
}

// A-side: fp32 [N_, ldin] -> bf16 [N_, 2K]
__global__ void __launch_bounds__(256) k_splitA(
    const float* __restrict__ in, long long inZ, int ldin, int K,
    __nv_bfloat16* __restrict__ out, long long outZ)
{
    long long z = blockIdx.z;
    in += z * inZ; out += z * outZ;
    int K4 = K / 4;
    int idx = blockIdx.x * 256 + threadIdx.x;
    if (idx >= N_ * K4) return;
    int m = idx / K4, k4 = (idx % K4) * 4;
    float4 v = *reinterpret_cast<const float4*>(in + (size_t)m * ldin + k4);
    ushort4 h, l;
    split2(v.x, h.x, l.x); split2(v.y, h.y, l.y);
    split2(v.z, h.z, l.z); split2(v.w, h.w, l.w);
    size_t b = (size_t)m * 2 * K;
    *reinterpret_cast<ushort4*>(out + b + k4) = h;
    *reinterpret_cast<ushort4*>(out + b + K + k4) = l;
}

// Fused per-row LN1 stats + LN + PReLU + split. Block per (n, r).
__global__ void __launch_bounds__(256) k_lnsplit(
    const float* __restrict__ x1,
    const float* __restrict__ g1, const float* __restrict__ be1,
    const float* __restrict__ a1p, __nv_bfloat16* __restrict__ out)
{
    int n = blockIdx.x, r = blockIdx.y, tid = threadIdx.x;
    __shared__ __align__(16) float sx[CH_];
    __shared__ float rsum[8], rsum2[8], smn, srs;
    const float* xr = x1 + ((size_t)r * N_ + n) * CH_;

    float s = 0.f, s2 = 0.f;
    for (int i = tid; i < CH_ / 4; i += 256) {
        float4 t = reinterpret_cast<const float4*>(xr)[i];
        reinterpret_cast<float4*>(sx)[i] = t;
        s  += t.x + t.y + t.z + t.w;
        s2 += t.x*t.x + t.y*t.y + t.z*t.z + t.w*t.w;
    }
    int lane = tid & 31, wid = tid >> 5;
    #pragma unroll
    for (int o = 16; o > 0; o >>= 1) {
        s  += __shfl_xor_sync(0xffffffffu, s,  o);
        s2 += __shfl_xor_sync(0xffffffffu, s2, o);
    }
    if (lane == 0) { rsum[wid] = s; rsum2[wid] = s2; }
    __syncthreads();
    if (tid == 0) {
        float ts = 0.f, ts2 = 0.f;
        #pragma unroll
        for (int w2 = 0; w2 < 8; w2++) { ts += rsum[w2]; ts2 += rsum2[w2]; }
        float m = ts / (float)CH_;
        smn = m; srs = rsqrtf(ts2 / (float)CH_ - m * m + 1e-5f);
    }
    __syncthreads();

    float mn = smn, rs = srs, a = __ldg(a1p);
    for (int i4 = tid; i4 < CH_ / 4; i4 += 256) {
        int i = i4 * 4;
        int c = i / HID_, col = i % HID_;
        float4 v = reinterpret_cast<const float4*>(sx)[i4];
        float4 g = reinterpret_cast<const float4*>(g1)[i4];
        float4 b = reinterpret_cast<const float4*>(be1)[i4];
        v.x = (v.x-mn)*rs*g.x + b.x; v.y = (v.y-mn)*rs*g.y + b.y;
        v.z = (v.z-mn)*rs*g.z + b.z; v.w = (v.w-mn)*rs*g.w + b.w;
        v.x = v.x >= 0.f ? v.x : a*v.x; v.y = v.y >= 0.f ? v.y : a*v.y;
        v.z = v.z >= 0.f ? v.z : a*v.z; v.w = v.w >= 0.f ? v.w : a*v.w;
        ushort4 h, l;
        split2(v.x, h.x, l.x); split2(v.y, h.y, l.y);
        split2(v.z, h.z, l.z); split2(v.w, h.w, l.w);
        __nv_bfloat16* op = out + ((size_t)r * C_ + c) * N_ * (2*HID_) + (size_t)n * (2*HID_);
        *reinterpret_cast<ushort4*>(op + col) = h;
        *reinterpret_cast<ushort4*>(op + HID_ + col) = l;
    }
}

// B-side: fp32 [Kd, Nn] -> bf16 [Nn, 2Kd], coalesced via 32x32 smem transpose
__global__ void __launch_bounds__(256) k_splitB(
    const float* __restrict__ in, long long inZ, int Kd, int Nn,
    __nv_bfloat16* __restrict__ out, long long outZ)
{
    __shared__ float tile[32][33];
    long long z = blockIdx.z;
    in += z * inZ; out += z * outZ;
    int k0 = blockIdx.x * 32, n0 = blockIdx.y * 32;
    int tx = threadIdx.x & 31, ty = threadIdx.x >> 5;   // 32 x 8
    #pragma unroll
    for (int j = 0; j < 32; j += 8)
        tile[ty + j][tx] = in[(size_t)(k0 + ty + j) * Nn + n0 + tx];
    __syncthreads();
    #pragma unroll
    for (int j = 0; j < 32; j += 8) {
        int n = n0 + ty + j, k = k0 + tx;
        float x = tile[tx][ty + j];
        unsigned short h, l;
        split2(x, h, l);
        size_t b = (size_t)n * 2 * Kd;
        out[b + k] = __ushort_as_bfloat16(h);
        out[b + Kd + k] = __ushort_as_bfloat16(l);
    }
}

// ---------------- plain fp32 GEMM for tiny weight fusion ----------------
__global__ void __launch_bounds__(256, 2) fuse_weights_kernel(
    const float* __restrict__ femb, const float* __restrict__ eemb,
    const float* __restrict__ lemb, const float* __restrict__ W1)
{
    constexpr int BM = 64, TM = 4, BN = 128, BK = 16, TN = 8;
    int zz = blockIdx.z, r = zz / C_, c = zz % C_;
    const float* A; int M; float* out;
    if (c < K_)      { A = femb + (size_t)(r*K_+c)*V_*IN_; M = V_;   out = g_Wraw + (size_t)(r*K_+c)*V_*HID_; }
    else if (c == 3) { A = eemb + (size_t)r*VE_*IN_;       M = VE_;  out = g_Wex  + (size_t)r*VE_*HID_; }
    else             { A = lemb + (size_t)r*OUT_*IN_;      M = OUT_; out = g_Wlab + (size_t)r*OUT_*HID_; }
    const float* B = W1 + (size_t)c * IN_ * HID_;

    __shared__ __align__(16) float As[BK][BM+4];
    __shared__ __align__(16) float Bs[BK][BN];
    int tid = threadIdx.x, tx = tid % (BN/TN), ty = tid / (BN/TN);
    int row0 = blockIdx.y * BM, col0 = blockIdx.x * BN;
    float acc[TM][TN] = {};
    for (int k0 = 0; k0 < IN_; k0 += BK) {
        for (int v = tid; v < BM*(BK/4); v += 256) {
            int rr = v / (BK/4), kq = (v % (BK/4)) * 4, gr = row0 + rr;
            float4 val = make_float4(0,0,0,0);
            if (gr < M) val = *reinterpret_cast<const float4*>(A + (size_t)gr*IN_ + k0 + kq);
            As[kq][rr] = val.x; As[kq+1][rr] = val.y; As[kq+2][rr] = val.z; As[kq+3][rr] = val.w;
        }
        for (int v = tid; v < BK*(BN/4); v += 256) {
            int rr = v / (BN/4), c4 = (v % (BN/4)) * 4;
            *reinterpret_cast<float4*>(&Bs[rr][c4]) =
                *reinterpret_cast<const float4*>(B + (size_t)(k0+rr)*HID_ + col0 + c4);
        }
        __syncthreads();
        #pragma unroll
        for (int kk = 0; kk < BK; kk++) {
            float a[TM], b[TN];
            #pragma unroll
            for (int i = 0; i < TM; i++) a[i] = As[kk][ty*TM+i];
            #pragma unroll
            for (int j = 0; j < TN; j++) b[j] = Bs[kk][tx*TN+j];
            #pragma unroll
            for (int i = 0; i < TM; i++)
                #pragma unroll
                for (int j = 0; j < TN; j++) acc[i][j] += a[i]*b[j];
        }
        __syncthreads();
    }
    #pragma unroll
    for (int i = 0; i < TM; i++) {
        int gr = row0 + ty*TM + i;
        if (gr >= M) continue;
        #pragma unroll
        for (int j = 0; j < TN; j++) out[(size_t)gr*HID_ + col0 + tx*TN + j] = acc[i][j];
    }
}

// ---------------- small SIMT kernels ----------------
__global__ void k_u(const float* __restrict__ eemb, const float* __restrict__ wx)
{
    int t = blockIdx.x * blockDim.x + threadIdx.x;
    if (t >= R_ * VE_) return;
    const float* row = eemb + (size_t)t * IN_;
    float s = 0.f;
    for (int d = 0; d < IN_; d++) s += row[d] * wx[d];
    g_u[t] = s;
}

__global__ void __launch_bounds__(256) k_extra_pool(const float* __restrict__ extra)
{
    int wg = (blockIdx.x * blockDim.x + threadIdx.x) >> 5, lane = threadIdx.x & 31;
    if (wg >= R_ * N_) return;
    int r = wg / N_;
    const float* base = extra + (size_t)wg * (L_ * VE_);
    float u[4];
    #pragma unroll
    for (int j = 0; j < 4; j++) u[j] = g_u[r * VE_ + lane + 32*j];
    float x[L_][4], s[L_];
    #pragma unroll
    for (int l = 0; l < L_; l++) {
        float p = 0.f;
        #pragma unroll
        for (int j = 0; j < 4; j++) { x[l][j] = base[l*VE_ + lane + 32*j]; p += x[l][j]*u[j]; }
        #pragma unroll
        for (int o = 16; o > 0; o >>= 1) p += __shfl_xor_sync(0xffffffffu, p, o);
        s[l] = 1.f / (1.f + expf(-p));
    }
    float mx = s[0];
    #pragma unroll
    for (int l = 1; l < L_; l++) mx = fmaxf(mx, s[l]);
    float e[L_], es = 0.f;
    #pragma unroll
    for (int l = 0; l < L_; l++) { e[l] = expf(s[l]-mx); es += e[l]; }
    float inv = 1.f / es, out[4] = {0,0,0,0};
    #pragma unroll
    for (int l = 0; l < L_; l++) {
        float w = e[l]*inv;
        #pragma unroll
        for (int j = 0; j < 4; j++) out[j] += w * x[l][j];
    }
    float* op = g_xp + (size_t)wg * VE_;
    #pragma unroll
    for (int j = 0; j < 4; j++) op[lane + 32*j] = out[j];
}

// channel attention pool with in-block LN2; block per (n, r)
__global__ void __launch_bounds__(256) k_pool_c(
    const float* __restrict__ g2, const float* __restrict__ be2,
    const float* __restrict__ a2p, const float* __restrict__ w_r)
{
    int n = blockIdx.x, r = blockIdx.y, tid = threadIdx.x;
    __shared__ __align__(16) float sx[CH_];
    __shared__ float red[C_][8], rsum[8], rsum2[8], salpha[C_], smn, srs;
    const float* xr = g_x2 + ((size_t)r * N_ + n) * CH_;
    const float* wr = w_r + r * HID_;
    float s = 0.f, s2 = 0.f;
    for (int i = tid; i < CH_/4; i += 256) {
        float4 t = reinterpret_cast<const float4*>(xr)[i];
        reinterpret_cast<float4*>(sx)[i] = t;
        s += t.x+t.y+t.z+t.w; s2 += t.x*t.x+t.y*t.y+t.z*t.z+t.w*t.w;
    }
    int lane = tid & 31, wid = tid >> 5;
    #pragma unroll
    for (int o = 16; o > 0; o >>= 1) {
        s += __shfl_xor_sync(0xffffffffu, s, o);
        s2 += __shfl_xor_sync(0xffffffffu, s2, o);
    }
    if (lane == 0) { rsum[wid] = s; rsum2[wid] = s2; }
    __syncthreads();
    if (tid == 0) {
        float ts = 0.f, ts2 = 0.f;
        #pragma unroll
        for (int w2 = 0; w2 < 8; w2++) { ts += rsum[w2]; ts2 += rsum2[w2]; }
        float m = ts/(float)CH_;
        smn = m; srs = rsqrtf(ts2/(float)CH_ - m*m + 1e-5f);
    }
    __syncthreads();
    float mn = smn, rs = srs, a = __ldg(a2p);
    for (int i = tid; i < CH_; i += 256) {
        float v = (sx[i]-mn)*rs*g2[i] + be2[i];
        sx[i] = v >= 0.f ? v : a*v;
    }
    __syncthreads();
    float p[C_] = {0,0,0,0,0};
    for (int h = tid; h < HID_; h += 256) {
        float w = wr[h];
        #pragma unroll
        for (int c = 0; c < C_; c++) p[c] += sx[c*HID_+h] * w;
    }
    #pragma unroll
    for (int c = 0; c < C_; c++)
        #pragma unroll
        for (int o = 16; o > 0; o >>= 1) p[c] += __shfl_xor_sync(0xffffffffu, p[c], o);
    if (lane == 0)
        #pragma unroll
        for (int c = 0; c < C_; c++) red[c][wid] = p[c];
    __syncthreads();
    if (tid == 0) {
        float sv[C_], mx = -1e30f;
        #pragma unroll
        for (int c = 0; c < C_; c++) {
            float t = 0.f;
            #pragma unroll
            for (int w2 = 0; w2 < 8; w2++) t += red[c][w2];
            sv[c] = 1.f / (1.f + expf(-t)); mx = fmaxf(mx, sv[c]);
        }
        float es = 0.f, e[C_];
        #pragma unroll
        for (int c = 0; c < C_; c++) { e[c] = expf(sv[c]-mx); es += e[c]; }
        #pragma unroll
        for (int c = 0; c < C_; c++) salpha[c] = e[c] / es;
    }
    __syncthreads();
    float* op = g_outr + ((size_t)r * N_ + n) * HID_;
    for (int h = tid; h < HID_; h += 256) {
        float acc = 0.f;
        #pragma unroll
        for (int c = 0; c < C_; c++) acc += salpha[c] * sx[c*HID_+h];
        op[h] = acc;
    }
}

__global__ void __launch_bounds__(256) k_pool_global(const float* __restrict__ wg)
{
    int w = (blockIdx.x * blockDim.x + threadIdx.x) >> 5, lane = threadIdx.x & 31;
    if (w >= N_) return;
    const float* pa = g_outr + (size_t)w * HID_;
    const float* pb = g_outr + (size_t)N_ * HID_ + (size_t)w * HID_;
    float a[16], b[16], sa = 0.f, sb = 0.f;
    #pragma unroll
    for (int j = 0; j < 16; j++) {
        int h = lane + 32*j;
        a[j] = pa[h]; b[j] = pb[h];
        float wv = wg[h];
        sa += a[j]*wv; sb += b[j]*wv;
    }
    #pragma unroll
    for (int o = 16; o > 0; o >>= 1) {
        sa += __shfl_xor_sync(0xffffffffu, sa, o);
        sb += __shfl_xor_sync(0xffffffffu, sb, o);
    }
    sa = 1.f/(1.f+expf(-sa)); sb = 1.f/(1.f+expf(-sb));
    float mx = fmaxf(sa, sb), ea = expf(sa-mx), eb = expf(sb-mx);
    float aa = ea/(ea+eb), ab = 1.f - aa;
    float* op = g_hfin + (size_t)w * HID_;
    #pragma unroll
    for (int j = 0; j < 16; j++) op[lane + 32*j] = aa*a[j] + ab*b[j];
}

// ---------------- input mapping ----------------
struct Ins {
    const float *raw, *extra, *label, *femb, *eemb, *lemb;
    const float *w_extra, *w_r, *w_g;
    const float *W1, *b1, *g1, *be1, *a1, *W2, *b2, *g2, *be2, *a2;
    const float *Wf1, *bf1, *af, *Wf2, *bf2;
};
static void resolve(void* const* d_in, const int* sz, Ins& I)
{
    auto F = [&](int i) { return (const float*)d_in[i]; };
    if (sz[0] == R_ * K_ * N_ * V_) {
        I.raw=F(0); I.extra=F(1); I.label=F(2); I.femb=F(3); I.eemb=F(4); I.lemb=F(5);
        I.w_extra=F(6); I.w_r=F(7); I.w_g=F(8);
        I.W1=F(9); I.b1=F(10); I.g1=F(11); I.be1=F(12); I.a1=F(13);
        I.W2=F(14); I.b2=F(15); I.g2=F(16); I.be2=F(17); I.a2=F(18);
        I.Wf1=F(19); I.bf1=F(20); I.af=F(21); I.Wf2=F(22); I.bf2=F(23);
    } else {
        I.W1=F(0); I.W2=F(1); I.Wf1=F(2); I.Wf2=F(3);
        I.a1=F(4); I.a2=F(5); I.af=F(6);
        I.b1=F(7); I.b2=F(8); I.be1=F(9); I.be2=F(10); I.bf1=F(11); I.bf2=F(12);
        I.eemb=F(13); I.extra=F(14); I.femb=F(15); I.g1=F(16); I.g2=F(17);
        I.lemb=F(18); I.label=F(19); I.raw=F(20);
        I.w_extra=F(21); I.w_g=F(22); I.w_r=F(23);
    }
}

extern "C" void kernel_launch(void* const* d_in, const int* in_sizes, int n_in,
                              void* d_out, int out_size)
{
    if (n_in < 24) return;
    Ins I; resolve(d_in, in_sizes, I);

    float *px1, *px2, *pxp, *pWraw, *pWex, *pWlab, *phf;
    __nv_bfloat16 *prawA, *plabA, *pxpA, *px1A, *phfA, *pff1A;
    __nv_bfloat16 *pW2T, *pWrawT, *pWexT, *pWlabT, *pWf1T, *pWf2T;
    cudaGetSymbolAddress((void**)&px1, g_x1);     cudaGetSymbolAddress((void**)&px2, g_x2);
    cudaGetSymbolAddress((void**)&pxp, g_xp);     cudaGetSymbolAddress((void**)&pWraw, g_Wraw);
    cudaGetSymbolAddress((void**)&pWex, g_Wex);   cudaGetSymbolAddress((void**)&pWlab, g_Wlab);
    cudaGetSymbolAddress((void**)&phf, g_hfin);
    cudaGetSymbolAddress((void**)&prawA, g_rawA); cudaGetSymbolAddress((void**)&plabA, g_labA);
    cudaGetSymbolAddress((void**)&pxpA, g_xpA);   cudaGetSymbolAddress((void**)&px1A, g_x1A);
    cudaGetSymbolAddress((void**)&phfA, g_hfA);   cudaGetSymbolAddress((void**)&pff1A, g_ff1A);
    cudaGetSymbolAddress((void**)&pW2T, g_W2T);   cudaGetSymbolAddress((void**)&pWrawT, g_WrawT);
    cudaGetSymbolAddress((void**)&pWexT, g_WexT); cudaGetSymbolAddress((void**)&pWlabT, g_WlabT);
    cudaGetSymbolAddress((void**)&pWf1T, g_Wf1T); cudaGetSymbolAddress((void**)&pWf2T, g_Wf2T);

    constexpr int SM256 = 3 * (2 * 128 * 80 + 2 * 256 * 80);   // 184320 B
    constexpr int SM64  = 3 * (2 * 128 * 80 + 2 * 64 * 80);    // 92160 B
    cudaFuncSetAttribute(k_tc_gemm<256>, cudaFuncAttributeMaxDynamicSharedMemorySize, SM256);
    cudaFuncSetAttribute(k_tc_gemm<64>,  cudaFuncAttributeMaxDynamicSharedMemorySize, SM64);

    // ---- launches ordered so #4 = raw GEMM (ncu capture position) ----
    fuse_weights_kernel<<<dim3(4, 4, 10), 256>>>(I.femb, I.eemb, I.lemb, I.W1);            // 1
    k_splitB<<<dim3(V_/32, HID_/32, 6), 256>>>(pWraw, (long long)V_*HID_, V_, HID_,
                                               pWrawT, (long long)HID_*2*V_);              // 2
    k_splitA<<<dim3(4096, 1, 6), 256>>>(I.raw, (long long)N_*V_, V_, V_,
                                        prawA, (long long)N_*2*V_);                        // 3
    // raw GEMM, z = r*3+c (zInner=3): x1 channels 0..2 for both r             — launch 4
    k_tc_gemm<256><<<dim3(HID_/256, N_/128, R_*K_), 512, SM256>>>(
        prawA, (long long)K_*N_*2*V_, (long long)N_*2*V_, K_,
        pWrawT, (long long)K_*HID_*2*V_, (long long)HID_*2*V_, V_,
        I.b1, HID_,
        px1, CH_, (long long)N_*CH_, HID_, nullptr);

    // ---- rest of prolog ----
    k_u<<<1, 256>>>(I.eemb, I.w_extra);
    k_extra_pool<<<(R_ * N_) / 8, 256>>>(I.extra);
    k_splitB<<<dim3(VE_/32, HID_/32, 2), 256>>>(pWex, (long long)VE_*HID_, VE_, HID_,
                                                pWexT, (long long)HID_*2*VE_);
    k_splitB<<<dim3(OUT_/32, HID_/32, 2), 256>>>(pWlab, (long long)OUT_*HID_, OUT_, HID_,
                                                 pWlabT, (long long)HID_*2*OUT_);
    k_splitB<<<dim3(HID_/32, HID_/32, 5), 256>>>(I.W2, (long long)HID_*HID_, HID_, HID_,
                                                 pW2T, (long long)HID_*2*HID_);
    k_splitB<<<dim3(HID_/32, HID_/32, 1), 256>>>(I.Wf1, 0, HID_, HID_, pWf1T, 0);
    k_splitB<<<dim3(HID_/32, OUT_/32, 1), 256>>>(I.Wf2, 0, HID_, OUT_, pWf2T, 0);
    k_splitA<<<dim3(1024, 1, 2), 256>>>(I.label, (long long)N_*OUT_, OUT_, OUT_,
                                        plabA, (long long)N_*2*OUT_);
    k_splitA<<<dim3(2048, 1, 2), 256>>>(pxp, (long long)N_*VE_, VE_, VE_,
                                        pxpA, (long long)N_*2*VE_);

    // ---- x1 channels 3,4 for both r (z = r, zInner = 1) ----
    k_tc_gemm<256><<<dim3(HID_/256, N_/128, R_), 512, SM256>>>(
        pxpA, (long long)N_*2*VE_, 0, 1,
        pWexT, (long long)HID_*2*VE_, 0, VE_,
        I.b1 + 3*HID_, 0,
        px1 + 3*HID_, CH_, (long long)N_*CH_, 0, nullptr);
    k_tc_gemm<256><<<dim3(HID_/256, N_/128, R_), 512, SM256>>>(
        plabA, (long long)N_*2*OUT_, 0, 1,
        pWlabT, (long long)HID_*2*OUT_, 0, OUT_,
        I.b1 + 4*HID_, 0,
        px1 + 4*HID_, CH_, (long long)N_*CH_, 0, nullptr);

    // ---- LN1+split (both r), W2 GEMM (z=10), pool (both r) ----
    k_lnsplit<<<dim3(N_, R_), 256>>>(px1, I.g1, I.be1, I.a1, px1A);
    k_tc_gemm<256><<<dim3(HID_/256, N_/128, R_*C_), 512, SM256>>>(
        px1A, (long long)C_*N_*2*HID_, (long long)N_*2*HID_, C_,
        pW2T, 0, (long long)HID_*2*HID_, HID_,
        I.b2, HID_,
        px2, CH_, (long long)N_*CH_, HID_, nullptr);
    k_pool_c<<<dim3(N_, R_), 256>>>(I.g2, I.be2, I.a2, I.w_r);

    // ---- global pool + FFN head ----
    k_pool_global<<<N_ / 8, 256>>>(I.w_g);
    k_splitA<<<dim3(8192, 1, 1), 256>>>(phf, 0, HID_, HID_, phfA, 0);
    k_tc_gemm<256><<<dim3(HID_/256, N_/128, 1), 512, SM256>>>(
        phfA, 0, 0, 1, pWf1T, 0, 0, HID_,
        I.bf1, 0,
        px2, HID_, 0, 0, I.af);                        // PReLU out, [N,512]
    k_splitA<<<dim3(8192, 1, 1), 256>>>(px2, 0, HID_, HID_, pff1A, 0);
    k_tc_gemm<64><<<dim3(1, N_/128, 1), 128, SM64>>>(
        pff1A, 0, 0, 1, pWf2T, 0, 0, HID_,
        I.bf2, 0,
        (float*)d_out, OUT_, 0, 0, nullptr);
}

// round 12
// speedup vs baseline: 2.6031x; 1.0408x over previous
#include <cuda_runtime.h>
#include <cuda_bf16.h>
#include <math.h>

#define R_   2
#define K_   3
#define N_   16384
#define V_   256
#define L_   8
#define VE_  128
#define OUT_ 64
#define IN_  256
#define HID_ 512
#define C_   5
#define CH_  (C_*HID_)

// ---------------- fp32 workspace (both relations resident) ----------------
__device__ float g_x1[(size_t)R_ * N_ * CH_];
__device__ float g_x2[(size_t)R_ * N_ * CH_];
__device__ float g_outr[(size_t)R_ * N_ * HID_];
__device__ float g_hfin[(size_t)N_ * HID_];
__device__ float g_xp[(size_t)R_ * N_ * VE_];
__device__ float g_u[R_ * VE_];
__device__ float g_Wraw[(size_t)R_ * K_ * V_ * HID_];
__device__ float g_Wex [(size_t)R_ * VE_ * HID_];
__device__ float g_Wlab[(size_t)R_ * OUT_ * HID_];

// ---------------- bf16 2-plane split workspace ([hi|lo], width 2K) ----------------
__device__ __align__(16) __nv_bfloat16 g_rawA[(size_t)R_ * K_ * N_ * (2*V_)];
__device__ __align__(16) __nv_bfloat16 g_labA[(size_t)R_ * N_ * (2*OUT_)];
__device__ __align__(16) __nv_bfloat16 g_xpA [(size_t)R_ * N_ * (2*VE_)];
__device__ __align__(16) __nv_bfloat16 g_x1A [(size_t)R_ * C_ * N_ * (2*HID_)];
__device__ __align__(16) __nv_bfloat16 g_hfA [(size_t)N_ * (2*HID_)];
__device__ __align__(16) __nv_bfloat16 g_ff1A[(size_t)N_ * (2*HID_)];
__device__ __align__(16) __nv_bfloat16 g_W2T  [(size_t)C_ * HID_ * (2*HID_)];
__device__ __align__(16) __nv_bfloat16 g_WrawT[(size_t)R_ * K_ * HID_ * (2*V_)];
__device__ __align__(16) __nv_bfloat16 g_WexT [(size_t)R_ * HID_ * (2*VE_)];
__device__ __align__(16) __nv_bfloat16 g_WlabT[(size_t)R_ * HID_ * (2*OUT_)];
__device__ __align__(16) __nv_bfloat16 g_Wf1T [(size_t)HID_ * (2*HID_)];
__device__ __align__(16) __nv_bfloat16 g_Wf2T [(size_t)OUT_ * (2*HID_)];

// ---------------- PTX helpers ----------------
__device__ __forceinline__ unsigned smem_u32(const void* p) {
    unsigned a;
    asm("{ .reg .u64 t; cvta.to.shared.u64 t, %1; cvt.u32.u64 %0, t; }" : "=r"(a) : "l"(p));
    return a;
}
__device__ __forceinline__ void cp16(unsigned dst, const void* src) {
    asm volatile("cp.async.cg.shared.global [%0], [%1], 16;" :: "r"(dst), "l"(src) : "memory");
}
__device__ __forceinline__ void ldsm4(unsigned* r, unsigned addr) {
    asm volatile("ldmatrix.sync.aligned.m8n8.x4.shared.b16 {%0,%1,%2,%3}, [%4];"
        : "=r"(r[0]), "=r"(r[1]), "=r"(r[2]), "=r"(r[3]) : "r"(addr));
}
__device__ __forceinline__ void mma16816(float* d, const unsigned* a, const unsigned* b) {
    asm volatile(
        "mma.sync.aligned.m16n8k16.row.col.f32.bf16.bf16.f32 "
        "{%0,%1,%2,%3}, {%4,%5,%6,%7}, {%8,%9}, {%0,%1,%2,%3};"
        : "+f"(d[0]), "+f"(d[1]), "+f"(d[2]), "+f"(d[3])
        : "r"(a[0]), "r"(a[1]), "r"(a[2]), "r"(a[3]), "r"(b[0]), "r"(b[1]));
}

// =========================================================================
// bf16 tensor-core GEMM, fused 3-product split per k-block.
// C = Ah.Bh^T + Ah.Bl^T + Al.Bh^T  (A,B 2-plane [hi|lo] along K).
// Pipeline: 3 smem stages, ONE barrier per k-block, loads issued pre-compute.
// Fragments: af0=Ah, af1=Al persistent per ks; bf reloaded Bh->Bl (12 ldsm/ks).
// CTA: 128 x BN; warps 4(M) x (BN/64)(N); warp tile 32x64; BK=32.
// =========================================================================
template<int BN>
__global__ void __launch_bounds__(128 * (BN > 64 ? BN / 64 : 1), 1) k_tc_gemm(
    const __nv_bfloat16* __restrict__ A, long long aZo, long long aZi, int zInner,
    const __nv_bfloat16* __restrict__ B, long long bZo, long long bZi, int Kd,
    const float* __restrict__ bias, long long biasZi,
    float* __restrict__ Co, int ldc, long long cZo, long long cZi,
    const float* __restrict__ alpha_p)
{
    constexpr int BM = 128, BK = 32;
    constexpr int NWN = (BN > 64 ? BN / 64 : 1);
    constexpr int THREADS = 128 * NWN;
    constexpr int WN  = BN / NWN;                 // 64
    constexpr int NT8 = WN / 8;                   // 8
    constexpr int ABP = BM * 80;                  // one A plane (pitch 80 B)
    constexpr int BBP = BN * 80;
    constexpr int STAGE = 2 * ABP + 2 * BBP;
    constexpr int APL = BM * 4, BPL = BN * 4;     // 16B chunks per plane
    constexpr int TOT = 2 * (APL + BPL);

    extern __shared__ char smem[];
    const int tid = threadIdx.x, lane = tid & 31, wid = tid >> 5;
    const int warp_m = wid & 3, warp_n = wid >> 2;
    const int m0 = blockIdx.y * BM, n0 = blockIdx.x * BN;
    const int zo = blockIdx.z / zInner, zi = blockIdx.z % zInner;
    const int ldAB = 2 * Kd;
    const __nv_bfloat16* Az = A + (long long)zo * aZo + (long long)zi * aZi;
    const __nv_bfloat16* Bz = B + (long long)zo * bZo + (long long)zi * bZi;
    float* Cz = Co + (long long)zo * cZo + (long long)zi * cZi;
    const float* biasz = bias ? bias + (long long)zi * biasZi : nullptr;

    const unsigned sb = smem_u32(smem);
    const int nkb = Kd / BK;

    float acc[2][NT8][4];
    #pragma unroll
    for (int mt = 0; mt < 2; mt++)
        #pragma unroll
        for (int nt = 0; nt < NT8; nt++)
            #pragma unroll
            for (int j = 0; j < 4; j++) acc[mt][nt][j] = 0.f;

    auto load = [&](int kb) {
        if (kb < nkb) {
            unsigned st = sb + (unsigned)(kb % 3) * STAGE;
            int k0 = kb * BK;
            #pragma unroll
            for (int q = 0; q < TOT / THREADS; q++) {
                int ch = tid + q * THREADS;
                unsigned dst; const __nv_bfloat16* src;
                if (ch < 2 * APL) {
                    int pl = (ch >= APL) ? 1 : 0;
                    int cc = ch - pl * APL;
                    int row = cc >> 2, c = cc & 3;
                    dst = st + pl * ABP + row * 80 + c * 16;
                    src = Az + (size_t)(m0 + row) * ldAB + pl * Kd + k0 + c * 8;
                } else {
                    int ch2 = ch - 2 * APL;
                    int pl = (ch2 >= BPL) ? 1 : 0;
                    int cc = ch2 - pl * BPL;
                    int row = cc >> 2, c = cc & 3;
                    dst = st + 2 * ABP + pl * BBP + row * 80 + c * 16;
                    src = Bz + (size_t)(n0 + row) * ldAB + pl * Kd + k0 + c * 8;
                }
                cp16(dst, src);
            }
        }
        asm volatile("cp.async.commit_group;" ::: "memory");
    };

    load(0); load(1);

    for (int kb = 0; kb < nkb; kb++) {
        // group kb complete for this thread:
        asm volatile("cp.async.wait_group 1;" ::: "memory");
        // all threads past their wait => stage kb fully written; all warps
        // finished compute(kb-1) => stage (kb+2)%3 == (kb-1)%3 reusable.
        __syncthreads();
        load(kb + 2);                       // prefetch BEFORE compute

        unsigned st = sb + (unsigned)(kb % 3) * STAGE;
        unsigned ah = st, al = st + ABP, bh = st + 2 * ABP, bl = bh + BBP;

        #pragma unroll
        for (int ks = 0; ks < 2; ks++) {
            int k0 = ks * 16;
            unsigned af0[2][4], af1[2][4], bf[NT8 / 2][4];
            const int arow = warp_m * 32 + (lane & 15);
            const unsigned aoff = (unsigned)(arow * 80 + (k0 + (lane >> 4) * 8) * 2);
            const int rowi = lane & 7, quad = lane >> 3;
            const int nofs = (quad >> 1) * 8, kofs = (quad & 1) * 8;
            const unsigned bkc = (unsigned)((k0 + kofs) * 2);

            // issue all Ah, Al, Bh loads up front (no false deps)
            ldsm4(af0[0], ah + aoff);
            ldsm4(af0[1], ah + aoff + 16 * 80);
            ldsm4(af1[0], al + aoff);
            ldsm4(af1[1], al + aoff + 16 * 80);
            #pragma unroll
            for (int j = 0; j < NT8 / 2; j++) {
                int nb = warp_n * WN + j * 16 + nofs + rowi;
                ldsm4(bf[j], bh + nb * 80 + bkc);
            }
            // phase 0: Ah . Bh
            #pragma unroll
            for (int mt = 0; mt < 2; mt++)
                #pragma unroll
                for (int nt = 0; nt < NT8; nt++)
                    mma16816(acc[mt][nt], af0[mt], &bf[nt >> 1][(nt & 1) * 2]);
            // phase 2: Al . Bh
            #pragma unroll
            for (int mt = 0; mt < 2; mt++)
                #pragma unroll
                for (int nt = 0; nt < NT8; nt++)
                    mma16816(acc[mt][nt], af1[mt], &bf[nt >> 1][(nt & 1) * 2]);
            // phase 1: Ah . Bl
            #pragma unroll
            for (int j = 0; j < NT8 / 2; j++) {
                int nb = warp_n * WN + j * 16 + nofs + rowi;
                ldsm4(bf[j], bl + nb * 80 + bkc);
            }
            #pragma unroll
            for (int mt = 0; mt < 2; mt++)
                #pragma unroll
                for (int nt = 0; nt < NT8; nt++)
                    mma16816(acc[mt][nt], af0[mt], &bf[nt >> 1][(nt & 1) * 2]);
        }
    }

    // ---- epilogue ----
    float alpha = alpha_p ? __ldg(alpha_p) : 0.f;
    int g = lane >> 2, q = lane & 3;
    #pragma unroll
    for (int mt = 0; mt < 2; mt++) {
        int row = m0 + warp_m * 32 + mt * 16 + g;
        #pragma unroll
        for (int nt = 0; nt < NT8; nt++) {
            int col = n0 + warp_n * WN + nt * 8 + q * 2;
            float b0 = 0.f, b1 = 0.f;
            if (biasz) { b0 = biasz[col]; b1 = biasz[col + 1]; }
            float2 v0 = make_float2(acc[mt][nt][0] + b0, acc[mt][nt][1] + b1);
            float2 v1 = make_float2(acc[mt][nt][2] + b0, acc[mt][nt][3] + b1);
            if (alpha_p) {
                v0.x = v0.x >= 0.f ? v0.x : alpha * v0.x;
                v0.y = v0.y >= 0.f ? v0.y : alpha * v0.y;
                v1.x = v1.x >= 0.f ? v1.x : alpha * v1.x;
                v1.y = v1.y >= 0.f ? v1.y : alpha * v1.y;
            }
            *reinterpret_cast<float2*>(Cz + (size_t)row * ldc + col) = v0;
            *reinterpret_cast<float2*>(Cz + (size_t)(row + 8) * ldc + col) = v1;
        }
    }
}

// ---------------- split conversions (2-plane [hi|lo]) ----------------
__device__ __forceinline__ void split2(float x, unsigned short& h, unsigned short& l) {
    __nv_bfloat16 hb = __float2bfloat16(x);
    __nv_bfloat16 lb = __float2bfloat16(x - __bfloat162float(hb));
    h = __bfloat16_as_ushort(hb); l = __bfloat16_as_ushort(lb);
}

// A-side: fp32 [N_, ldin] -> bf16 [N_, 2K]
__global__ void __launch_bounds__(256) k_splitA(
    const float* __restrict__ in, long long inZ, int ldin, int K,
    __nv_bfloat16* __restrict__ out, long long outZ)
{
    long long z = blockIdx.z;
    in += z * inZ; out += z * outZ;
    int K4 = K / 4;
    int idx = blockIdx.x * 256 + threadIdx.x;
    if (idx >= N_ * K4) return;
    int m = idx / K4, k4 = (idx % K4) * 4;
    float4 v = *reinterpret_cast<const float4*>(in + (size_t)m * ldin + k4);
    ushort4 h, l;
    split2(v.x, h.x, l.x); split2(v.y, h.y, l.y);
    split2(v.z, h.z, l.z); split2(v.w, h.w, l.w);
    size_t b = (size_t)m * 2 * K;
    *reinterpret_cast<ushort4*>(out + b + k4) = h;
    *reinterpret_cast<ushort4*>(out + b + K + k4) = l;
}

// Fused per-row LN1 stats + LN + PReLU + split. Block per (n, r).
__global__ void __launch_bounds__(256) k_lnsplit(
    const float* __restrict__ x1,
    const float* __restrict__ g1, const float* __restrict__ be1,
    const float* __restrict__ a1p, __nv_bfloat16* __restrict__ out)
{
    int n = blockIdx.x, r = blockIdx.y, tid = threadIdx.x;
    __shared__ __align__(16) float sx[CH_];
    __shared__ float rsum[8], rsum2[8], smn, srs;
    const float* xr = x1 + ((size_t)r * N_ + n) * CH_;

    float s = 0.f, s2 = 0.f;
    for (int i = tid; i < CH_ / 4; i += 256) {
        float4 t = reinterpret_cast<const float4*>(xr)[i];
        reinterpret_cast<float4*>(sx)[i] = t;
        s  += t.x + t.y + t.z + t.w;
        s2 += t.x*t.x + t.y*t.y + t.z*t.z + t.w*t.w;
    }
    int lane = tid & 31, wid = tid >> 5;
    #pragma unroll
    for (int o = 16; o > 0; o >>= 1) {
        s  += __shfl_xor_sync(0xffffffffu, s,  o);
        s2 += __shfl_xor_sync(0xffffffffu, s2, o);
    }
    if (lane == 0) { rsum[wid] = s; rsum2[wid] = s2; }
    __syncthreads();
    if (tid == 0) {
        float ts = 0.f, ts2 = 0.f;
        #pragma unroll
        for (int w2 = 0; w2 < 8; w2++) { ts += rsum[w2]; ts2 += rsum2[w2]; }
        float m = ts / (float)CH_;
        smn = m; srs = rsqrtf(ts2 / (float)CH_ - m * m + 1e-5f);
    }
    __syncthreads();

    float mn = smn, rs = srs, a = __ldg(a1p);
    for (int i4 = tid; i4 < CH_ / 4; i4 += 256) {
        int i = i4 * 4;
        int c = i / HID_, col = i % HID_;
        float4 v = reinterpret_cast<const float4*>(sx)[i4];
        float4 g = reinterpret_cast<const float4*>(g1)[i4];
        float4 b = reinterpret_cast<const float4*>(be1)[i4];
        v.x = (v.x-mn)*rs*g.x + b.x; v.y = (v.y-mn)*rs*g.y + b.y;
        v.z = (v.z-mn)*rs*g.z + b.z; v.w = (v.w-mn)*rs*g.w + b.w;
        v.x = v.x >= 0.f ? v.x : a*v.x; v.y = v.y >= 0.f ? v.y : a*v.y;
        v.z = v.z >= 0.f ? v.z : a*v.z; v.w = v.w >= 0.f ? v.w : a*v.w;
        ushort4 h, l;
        split2(v.x, h.x, l.x); split2(v.y, h.y, l.y);
        split2(v.z, h.z, l.z); split2(v.w, h.w, l.w);
        __nv_bfloat16* op = out + ((size_t)r * C_ + c) * N_ * (2*HID_) + (size_t)n * (2*HID_);
        *reinterpret_cast<ushort4*>(op + col) = h;
        *reinterpret_cast<ushort4*>(op + HID_ + col) = l;
    }
}

// B-side: fp32 [Kd, Nn] -> bf16 [Nn, 2Kd], coalesced via 32x32 smem transpose
__global__ void __launch_bounds__(256) k_splitB(
    const float* __restrict__ in, long long inZ, int Kd, int Nn,
    __nv_bfloat16* __restrict__ out, long long outZ)
{
    __shared__ float tile[32][33];
    long long z = blockIdx.z;
    in += z * inZ; out += z * outZ;
    int k0 = blockIdx.x * 32, n0 = blockIdx.y * 32;
    int tx = threadIdx.x & 31, ty = threadIdx.x >> 5;   // 32 x 8
    #pragma unroll
    for (int j = 0; j < 32; j += 8)
        tile[ty + j][tx] = in[(size_t)(k0 + ty + j) * Nn + n0 + tx];
    __syncthreads();
    #pragma unroll
    for (int j = 0; j < 32; j += 8) {
        int n = n0 + ty + j, k = k0 + tx;
        float x = tile[tx][ty + j];
        unsigned short h, l;
        split2(x, h, l);
        size_t b = (size_t)n * 2 * Kd;
        out[b + k] = __ushort_as_bfloat16(h);
        out[b + Kd + k] = __ushort_as_bfloat16(l);
    }
}

// ---------------- plain fp32 GEMM for tiny weight fusion ----------------
__global__ void __launch_bounds__(256, 2) fuse_weights_kernel(
    const float* __restrict__ femb, const float* __restrict__ eemb,
    const float* __restrict__ lemb, const float* __restrict__ W1)
{
    constexpr int BM = 64, TM = 4, BN = 128, BK = 16, TN = 8;
    int zz = blockIdx.z, r = zz / C_, c = zz % C_;
    const float* A; int M; float* out;
    if (c < K_)      { A = femb + (size_t)(r*K_+c)*V_*IN_; M = V_;   out = g_Wraw + (size_t)(r*K_+c)*V_*HID_; }
    else if (c == 3) { A = eemb + (size_t)r*VE_*IN_;       M = VE_;  out = g_Wex  + (size_t)r*VE_*HID_; }
    else             { A = lemb + (size_t)r*OUT_*IN_;      M = OUT_; out = g_Wlab + (size_t)r*OUT_*HID_; }
    const float* B = W1 + (size_t)c * IN_ * HID_;

    __shared__ __align__(16) float As[BK][BM+4];
    __shared__ __align__(16) float Bs[BK][BN];
    int tid = threadIdx.x, tx = tid % (BN/TN), ty = tid / (BN/TN);
    int row0 = blockIdx.y * BM, col0 = blockIdx.x * BN;
    float acc[TM][TN] = {};
    for (int k0 = 0; k0 < IN_; k0 += BK) {
        for (int v = tid; v < BM*(BK/4); v += 256) {
            int rr = v / (BK/4), kq = (v % (BK/4)) * 4, gr = row0 + rr;
            float4 val = make_float4(0,0,0,0);
            if (gr < M) val = *reinterpret_cast<const float4*>(A + (size_t)gr*IN_ + k0 + kq);
            As[kq][rr] = val.x; As[kq+1][rr] = val.y; As[kq+2][rr] = val.z; As[kq+3][rr] = val.w;
        }
        for (int v = tid; v < BK*(BN/4); v += 256) {
            int rr = v / (BN/4), c4 = (v % (BN/4)) * 4;
            *reinterpret_cast<float4*>(&Bs[rr][c4]) =
                *reinterpret_cast<const float4*>(B + (size_t)(k0+rr)*HID_ + col0 + c4);
        }
        __syncthreads();
        #pragma unroll
        for (int kk = 0; kk < BK; kk++) {
            float a[TM], b[TN];
            #pragma unroll
            for (int i = 0; i < TM; i++) a[i] = As[kk][ty*TM+i];
            #pragma unroll
            for (int j = 0; j < TN; j++) b[j] = Bs[kk][tx*TN+j];
            #pragma unroll
            for (int i = 0; i < TM; i++)
                #pragma unroll
                for (int j = 0; j < TN; j++) acc[i][j] += a[i]*b[j];
        }
        __syncthreads();
    }
    #pragma unroll
    for (int i = 0; i < TM; i++) {
        int gr = row0 + ty*TM + i;
        if (gr >= M) continue;
        #pragma unroll
        for (int j = 0; j < TN; j++) out[(size_t)gr*HID_ + col0 + tx*TN + j] = acc[i][j];
    }
}

// ---------------- small SIMT kernels ----------------
__global__ void k_u(const float* __restrict__ eemb, const float* __restrict__ wx)
{
    int t = blockIdx.x * blockDim.x + threadIdx.x;
    if (t >= R_ * VE_) return;
    const float* row = eemb + (size_t)t * IN_;
    float s = 0.f;
    for (int d = 0; d < IN_; d++) s += row[d] * wx[d];
    g_u[t] = s;
}

__global__ void __launch_bounds__(256) k_extra_pool(const float* __restrict__ extra)
{
    int wg = (blockIdx.x * blockDim.x + threadIdx.x) >> 5, lane = threadIdx.x & 31;
    if (wg >= R_ * N_) return;
    int r = wg / N_;
    const float* base = extra + (size_t)wg * (L_ * VE_);
    float u[4];
    #pragma unroll
    for (int j = 0; j < 4; j++) u[j] = g_u[r * VE_ + lane + 32*j];
    float x[L_][4], s[L_];
    #pragma unroll
    for (int l = 0; l < L_; l++) {
        float p = 0.f;
        #pragma unroll
        for (int j = 0; j < 4; j++) { x[l][j] = base[l*VE_ + lane + 32*j]; p += x[l][j]*u[j]; }
        #pragma unroll
        for (int o = 16; o > 0; o >>= 1) p += __shfl_xor_sync(0xffffffffu, p, o);
        s[l] = 1.f / (1.f + expf(-p));
    }
    float mx = s[0];
    #pragma unroll
    for (int l = 1; l < L_; l++) mx = fmaxf(mx, s[l]);
    float e[L_], es = 0.f;
    #pragma unroll
    for (int l = 0; l < L_; l++) { e[l] = expf(s[l]-mx); es += e[l]; }
    float inv = 1.f / es, out[4] = {0,0,0,0};
    #pragma unroll
    for (int l = 0; l < L_; l++) {
        float w = e[l]*inv;
        #pragma unroll
        for (int j = 0; j < 4; j++) out[j] += w * x[l][j];
    }
    float* op = g_xp + (size_t)wg * VE_;
    #pragma unroll
    for (int j = 0; j < 4; j++) op[lane + 32*j] = out[j];
}

// channel attention pool with in-block LN2; block per (n, r)
__global__ void __launch_bounds__(256) k_pool_c(
    const float* __restrict__ g2, const float* __restrict__ be2,
    const float* __restrict__ a2p, const float* __restrict__ w_r)
{
    int n = blockIdx.x, r = blockIdx.y, tid = threadIdx.x;
    __shared__ __align__(16) float sx[CH_];
    __shared__ float red[C_][8], rsum[8], rsum2[8], salpha[C_], smn, srs;
    const float* xr = g_x2 + ((size_t)r * N_ + n) * CH_;
    const float* wr = w_r + r * HID_;
    float s = 0.f, s2 = 0.f;
    for (int i = tid; i < CH_/4; i += 256) {
        float4 t = reinterpret_cast<const float4*>(xr)[i];
        reinterpret_cast<float4*>(sx)[i] = t;
        s += t.x+t.y+t.z+t.w; s2 += t.x*t.x+t.y*t.y+t.z*t.z+t.w*t.w;
    }
    int lane = tid & 31, wid = tid >> 5;
    #pragma unroll
    for (int o = 16; o > 0; o >>= 1) {
        s += __shfl_xor_sync(0xffffffffu, s, o);
        s2 += __shfl_xor_sync(0xffffffffu, s2, o);
    }
    if (lane == 0) { rsum[wid] = s; rsum2[wid] = s2; }
    __syncthreads();
    if (tid == 0) {
        float ts = 0.f, ts2 = 0.f;
        #pragma unroll
        for (int w2 = 0; w2 < 8; w2++) { ts += rsum[w2]; ts2 += rsum2[w2]; }
        float m = ts/(float)CH_;
        smn = m; srs = rsqrtf(ts2/(float)CH_ - m*m + 1e-5f);
    }
    __syncthreads();
    float mn = smn, rs = srs, a = __ldg(a2p);
    for (int i = tid; i < CH_; i += 256) {
        float v = (sx[i]-mn)*rs*g2[i] + be2[i];
        sx[i] = v >= 0.f ? v : a*v;
    }
    __syncthreads();
    float p[C_] = {0,0,0,0,0};
    for (int h = tid; h < HID_; h += 256) {
        float w = wr[h];
        #pragma unroll
        for (int c = 0; c < C_; c++) p[c] += sx[c*HID_+h] * w;
    }
    #pragma unroll
    for (int c = 0; c < C_; c++)
        #pragma unroll
        for (int o = 16; o > 0; o >>= 1) p[c] += __shfl_xor_sync(0xffffffffu, p[c], o);
    if (lane == 0)
        #pragma unroll
        for (int c = 0; c < C_; c++) red[c][wid] = p[c];
    __syncthreads();
    if (tid == 0) {
        float sv[C_], mx = -1e30f;
        #pragma unroll
        for (int c = 0; c < C_; c++) {
            float t = 0.f;
            #pragma unroll
            for (int w2 = 0; w2 < 8; w2++) t += red[c][w2];
            sv[c] = 1.f / (1.f + expf(-t)); mx = fmaxf(mx, sv[c]);
        }
        float es = 0.f, e[C_];
        #pragma unroll
        for (int c = 0; c < C_; c++) { e[c] = expf(sv[c]-mx); es += e[c]; }
        #pragma unroll
        for (int c = 0; c < C_; c++) salpha[c] = e[c] / es;
    }
    __syncthreads();
    float* op = g_outr + ((size_t)r * N_ + n) * HID_;
    for (int h = tid; h < HID_; h += 256) {
        float acc = 0.f;
        #pragma unroll
        for (int c = 0; c < C_; c++) acc += salpha[c] * sx[c*HID_+h];
        op[h] = acc;
    }
}

__global__ void __launch_bounds__(256) k_pool_global(const float* __restrict__ wg)
{
    int w = (blockIdx.x * blockDim.x + threadIdx.x) >> 5, lane = threadIdx.x & 31;
    if (w >= N_) return;
    const float* pa = g_outr + (size_t)w * HID_;
    const float* pb = g_outr + (size_t)N_ * HID_ + (size_t)w * HID_;
    float a[16], b[16], sa = 0.f, sb = 0.f;
    #pragma unroll
    for (int j = 0; j < 16; j++) {
        int h = lane + 32*j;
        a[j] = pa[h]; b[j] = pb[h];
        float wv = wg[h];
        sa += a[j]*wv; sb += b[j]*wv;
    }
    #pragma unroll
    for (int o = 16; o > 0; o >>= 1) {
        sa += __shfl_xor_sync(0xffffffffu, sa, o);
        sb += __shfl_xor_sync(0xffffffffu, sb, o);
    }
    sa = 1.f/(1.f+expf(-sa)); sb = 1.f/(1.f+expf(-sb));
    float mx = fmaxf(sa, sb), ea = expf(sa-mx), eb = expf(sb-mx);
    float aa = ea/(ea+eb), ab = 1.f - aa;
    float* op = g_hfin + (size_t)w * HID_;
    #pragma unroll
    for (int j = 0; j < 16; j++) op[lane + 32*j] = aa*a[j] + ab*b[j];
}

// ---------------- input mapping ----------------
struct Ins {
    const float *raw, *extra, *label, *femb, *eemb, *lemb;
    const float *w_extra, *w_r, *w_g;
    const float *W1, *b1, *g1, *be1, *a1, *W2, *b2, *g2, *be2, *a2;
    const float *Wf1, *bf1, *af, *Wf2, *bf2;
};
static void resolve(void* const* d_in, const int* sz, Ins& I)
{
    auto F = [&](int i) { return (const float*)d_in[i]; };
    if (sz[0] == R_ * K_ * N_ * V_) {
        I.raw=F(0); I.extra=F(1); I.label=F(2); I.femb=F(3); I.eemb=F(4); I.lemb=F(5);
        I.w_extra=F(6); I.w_r=F(7); I.w_g=F(8);
        I.W1=F(9); I.b1=F(10); I.g1=F(11); I.be1=F(12); I.a1=F(13);
        I.W2=F(14); I.b2=F(15); I.g2=F(16); I.be2=F(17); I.a2=F(18);
        I.Wf1=F(19); I.bf1=F(20); I.af=F(21); I.Wf2=F(22); I.bf2=F(23);
    } else {
        I.W1=F(0); I.W2=F(1); I.Wf1=F(2); I.Wf2=F(3);
        I.a1=F(4); I.a2=F(5); I.af=F(6);
        I.b1=F(7); I.b2=F(8); I.be1=F(9); I.be2=F(10); I.bf1=F(11); I.bf2=F(12);
        I.eemb=F(13); I.extra=F(14); I.femb=F(15); I.g1=F(16); I.g2=F(17);
        I.lemb=F(18); I.label=F(19); I.raw=F(20);
        I.w_extra=F(21); I.w_g=F(22); I.w_r=F(23);
    }
}

extern "C" void kernel_launch(void* const* d_in, const int* in_sizes, int n_in,
                              void* d_out, int out_size)
{
    if (n_in < 24) return;
    Ins I; resolve(d_in, in_sizes, I);

    float *px1, *px2, *pxp, *pWraw, *pWex, *pWlab, *phf;
    __nv_bfloat16 *prawA, *plabA, *pxpA, *px1A, *phfA, *pff1A;
    __nv_bfloat16 *pW2T, *pWrawT, *pWexT, *pWlabT, *pWf1T, *pWf2T;
    cudaGetSymbolAddress((void**)&px1, g_x1);     cudaGetSymbolAddress((void**)&px2, g_x2);
    cudaGetSymbolAddress((void**)&pxp, g_xp);     cudaGetSymbolAddress((void**)&pWraw, g_Wraw);
    cudaGetSymbolAddress((void**)&pWex, g_Wex);   cudaGetSymbolAddress((void**)&pWlab, g_Wlab);
    cudaGetSymbolAddress((void**)&phf, g_hfin);
    cudaGetSymbolAddress((void**)&prawA, g_rawA); cudaGetSymbolAddress((void**)&plabA, g_labA);
    cudaGetSymbolAddress((void**)&pxpA, g_xpA);   cudaGetSymbolAddress((void**)&px1A, g_x1A);
    cudaGetSymbolAddress((void**)&phfA, g_hfA);   cudaGetSymbolAddress((void**)&pff1A, g_ff1A);
    cudaGetSymbolAddress((void**)&pW2T, g_W2T);   cudaGetSymbolAddress((void**)&pWrawT, g_WrawT);
    cudaGetSymbolAddress((void**)&pWexT, g_WexT); cudaGetSymbolAddress((void**)&pWlabT, g_WlabT);
    cudaGetSymbolAddress((void**)&pWf1T, g_Wf1T); cudaGetSymbolAddress((void**)&pWf2T, g_Wf2T);

    constexpr int SM256 = 3 * (2 * 128 * 80 + 2 * 256 * 80);   // 184320 B
    constexpr int SM64  = 3 * (2 * 128 * 80 + 2 * 64 * 80);    // 92160 B
    cudaFuncSetAttribute(k_tc_gemm<256>, cudaFuncAttributeMaxDynamicSharedMemorySize, SM256);
    cudaFuncSetAttribute(k_tc_gemm<64>,  cudaFuncAttributeMaxDynamicSharedMemorySize, SM64);

    // ---- launches ordered so #4 = raw GEMM (ncu capture position) ----
    fuse_weights_kernel<<<dim3(4, 4, 10), 256>>>(I.femb, I.eemb, I.lemb, I.W1);            // 1
    k_splitB<<<dim3(V_/32, HID_/32, 6), 256>>>(pWraw, (long long)V_*HID_, V_, HID_,
                                               pWrawT, (long long)HID_*2*V_);              // 2
    k_splitA<<<dim3(4096, 1, 6), 256>>>(I.raw, (long long)N_*V_, V_, V_,
                                        prawA, (long long)N_*2*V_);                        // 3
    // raw GEMM, z = r*3+c (zInner=3): x1 channels 0..2 for both r             — launch 4
    k_tc_gemm<256><<<dim3(HID_/256, N_/128, R_*K_), 512, SM256>>>(
        prawA, (long long)K_*N_*2*V_, (long long)N_*2*V_, K_,
        pWrawT, (long long)K_*HID_*2*V_, (long long)HID_*2*V_, V_,
        I.b1, HID_,
        px1, CH_, (long long)N_*CH_, HID_, nullptr);

    // ---- rest of prolog ----
    k_u<<<1, 256>>>(I.eemb, I.w_extra);
    k_extra_pool<<<(R_ * N_) / 8, 256>>>(I.extra);
    k_splitB<<<dim3(VE_/32, HID_/32, 2), 256>>>(pWex, (long long)VE_*HID_, VE_, HID_,
                                                pWexT, (long long)HID_*2*VE_);
    k_splitB<<<dim3(OUT_/32, HID_/32, 2), 256>>>(pWlab, (long long)OUT_*HID_, OUT_, HID_,
                                                 pWlabT, (long long)HID_*2*OUT_);
    k_splitB<<<dim3(HID_/32, HID_/32, 5), 256>>>(I.W2, (long long)HID_*HID_, HID_, HID_,
                                                 pW2T, (long long)HID_*2*HID_);
    k_splitB<<<dim3(HID_/32, HID_/32, 1), 256>>>(I.Wf1, 0, HID_, HID_, pWf1T, 0);
    k_splitB<<<dim3(HID_/32, OUT_/32, 1), 256>>>(I.Wf2, 0, HID_, OUT_, pWf2T, 0);
    k_splitA<<<dim3(1024, 1, 2), 256>>>(I.label, (long long)N_*OUT_, OUT_, OUT_,
                                        plabA, (long long)N_*2*OUT_);
    k_splitA<<<dim3(2048, 1, 2), 256>>>(pxp, (long long)N_*VE_, VE_, VE_,
                                        pxpA, (long long)N_*2*VE_);

    // ---- x1 channels 3,4 for both r (z = r, zInner = 1) ----
    k_tc_gemm<256><<<dim3(HID_/256, N_/128, R_), 512, SM256>>>(
        pxpA, (long long)N_*2*VE_, 0, 1,
        pWexT, (long long)HID_*2*VE_, 0, VE_,
        I.b1 + 3*HID_, 0,
        px1 + 3*HID_, CH_, (long long)N_*CH_, 0, nullptr);
    k_tc_gemm<256><<<dim3(HID_/256, N_/128, R_), 512, SM256>>>(
        plabA, (long long)N_*2*OUT_, 0, 1,
        pWlabT, (long long)HID_*2*OUT_, 0, OUT_,
        I.b1 + 4*HID_, 0,
        px1 + 4*HID_, CH_, (long long)N_*CH_, 0, nullptr);

    // ---- LN1+split (both r), W2 GEMM (z=10), pool (both r) ----
    k_lnsplit<<<dim3(N_, R_), 256>>>(px1, I.g1, I.be1, I.a1, px1A);
    k_tc_gemm<256><<<dim3(HID_/256, N_/128, R_*C_), 512, SM256>>>(
        px1A, (long long)C_*N_*2*HID_, (long long)N_*2*HID_, C_,
        pW2T, 0, (long long)HID_*2*HID_, HID_,
        I.b2, HID_,
        px2, CH_, (long long)N_*CH_, HID_, nullptr);
    k_pool_c<<<dim3(N_, R_), 256>>>(I.g2, I.be2, I.a2, I.w_r);

    // ---- global pool + FFN head ----
    k_pool_global<<<N_ / 8, 256>>>(I.w_g);
    k_splitA<<<dim3(8192, 1, 1), 256>>>(phf, 0, HID_, HID_, phfA, 0);
    k_tc_gemm<256><<<dim3(HID_/256, N_/128, 1), 512, SM256>>>(
        phfA, 0, 0, 1, pWf1T, 0, 0, HID_,
        I.bf1, 0,
        px2, HID_, 0, 0, I.af);                        // PReLU out, [N,512]
    k_splitA<<<dim3(8192, 1, 1), 256>>>(px2, 0, HID_, HID_, pff1A, 0);
    k_tc_gemm<64><<<dim3(1, N_/128, 1), 128, SM64>>>(
        pff1A, 0, 0, 1, pWf2T, 0, 0, HID_,
        I.bf2, 0,
        (float*)d_out, OUT_, 0, 0, nullptr);
}

// round 13
// speedup vs baseline: 2.9694x; 1.1407x over previous
#include <cuda_runtime.h>
#include <cuda_bf16.h>
#include <math.h>

#define R_   2
#define K_   3
#define N_   16384
#define V_   256
#define L_   8
#define VE_  128
#define OUT_ 64
#define IN_  256
#define HID_ 512
#define C_   5
#define CH_  (C_*HID_)

// ---------------- fp32 workspace (both relations resident) ----------------
__device__ float g_x1[(size_t)R_ * N_ * CH_];
__device__ float g_x2[(size_t)R_ * N_ * CH_];
__device__ float g_outr[(size_t)R_ * N_ * HID_];
__device__ float g_hfin[(size_t)N_ * HID_];
__device__ float g_xp[(size_t)R_ * N_ * VE_];
__device__ float g_u[R_ * VE_];
__device__ float g_Wraw[(size_t)R_ * K_ * V_ * HID_];
__device__ float g_Wex [(size_t)R_ * VE_ * HID_];
__device__ float g_Wlab[(size_t)R_ * OUT_ * HID_];

// ---------------- bf16 2-plane split workspace ([hi|lo], width 2K) ----------------
__device__ __align__(16) __nv_bfloat16 g_rawA[(size_t)R_ * K_ * N_ * (2*V_)];
__device__ __align__(16) __nv_bfloat16 g_labA[(size_t)R_ * N_ * (2*OUT_)];
__device__ __align__(16) __nv_bfloat16 g_xpA [(size_t)R_ * N_ * (2*VE_)];
__device__ __align__(16) __nv_bfloat16 g_x1A [(size_t)R_ * C_ * N_ * (2*HID_)];
__device__ __align__(16) __nv_bfloat16 g_hfA [(size_t)N_ * (2*HID_)];
__device__ __align__(16) __nv_bfloat16 g_ff1A[(size_t)N_ * (2*HID_)];
__device__ __align__(16) __nv_bfloat16 g_W2T  [(size_t)C_ * HID_ * (2*HID_)];
__device__ __align__(16) __nv_bfloat16 g_WrawT[(size_t)R_ * K_ * HID_ * (2*V_)];
__device__ __align__(16) __nv_bfloat16 g_WexT [(size_t)R_ * HID_ * (2*VE_)];
__device__ __align__(16) __nv_bfloat16 g_WlabT[(size_t)R_ * HID_ * (2*OUT_)];
__device__ __align__(16) __nv_bfloat16 g_Wf1T [(size_t)HID_ * (2*HID_)];
__device__ __align__(16) __nv_bfloat16 g_Wf2T [(size_t)OUT_ * (2*HID_)];

// ---------------- PTX helpers ----------------
__device__ __forceinline__ unsigned smem_u32(const void* p) {
    unsigned a;
    asm("{ .reg .u64 t; cvta.to.shared.u64 t, %1; cvt.u32.u64 %0, t; }" : "=r"(a) : "l"(p));
    return a;
}
__device__ __forceinline__ void cp16(unsigned dst, const void* src) {
    asm volatile("cp.async.cg.shared.global [%0], [%1], 16;" :: "r"(dst), "l"(src) : "memory");
}
__device__ __forceinline__ void ldsm4(unsigned* r, unsigned addr) {
    asm volatile("ldmatrix.sync.aligned.m8n8.x4.shared.b16 {%0,%1,%2,%3}, [%4];"
        : "=r"(r[0]), "=r"(r[1]), "=r"(r[2]), "=r"(r[3]) : "r"(addr));
}
__device__ __forceinline__ void mma16816(float* d, const unsigned* a, const unsigned* b) {
    asm volatile(
        "mma.sync.aligned.m16n8k16.row.col.f32.bf16.bf16.f32 "
        "{%0,%1,%2,%3}, {%4,%5,%6,%7}, {%8,%9}, {%0,%1,%2,%3};"
        : "+f"(d[0]), "+f"(d[1]), "+f"(d[2]), "+f"(d[3])
        : "r"(a[0]), "r"(a[1]), "r"(a[2]), "r"(a[3]), "r"(b[0]), "r"(b[1]));
}
// packed 64B-pitch smem layout with XOR swizzle: 16B chunk (row, c) ->
// row*64 + ((c ^ ((row>>1)&3))<<4). Conflict-free for STS.128 and ldsm phases.
__device__ __forceinline__ unsigned swz(int row, int c) {
    return (unsigned)((row << 6) + (((c ^ (row >> 1)) & 3) << 4) + ((c & ~3) << 4));
}

// =========================================================================
// bf16 tensor-core GEMM, fused 3-product split per k-block.
// C = Ah.Bh^T + Ah.Bl^T + Al.Bh^T  (A,B 2-plane [hi|lo] along K).
// Packed swizzled smem (64B pitch) -> 3 stages fit 2 CTAs/SM (256 thr each).
// CTA: 128 x BN; warps 4(M) x (BN/64)(N); warp tile 32x64; BK=32.
// =========================================================================
template<int BN>
__global__ void __launch_bounds__(128 * (BN > 64 ? BN / 64 : 1), 2) k_tc_gemm(
    const __nv_bfloat16* __restrict__ A, long long aZo, long long aZi, int zInner,
    const __nv_bfloat16* __restrict__ B, long long bZo, long long bZi, int Kd,
    const float* __restrict__ bias, long long biasZi,
    float* __restrict__ Co, int ldc, long long cZo, long long cZi,
    const float* __restrict__ alpha_p)
{
    constexpr int BM = 128, BK = 32;
    constexpr int NWN = (BN > 64 ? BN / 64 : 1);  // warps along N (2 for BN=128)
    constexpr int THREADS = 128 * NWN;
    constexpr int WN  = BN / NWN;                 // 64
    constexpr int NT8 = WN / 8;                   // 8
    constexpr int ABP = BM * 64;                  // one A plane, packed 64B pitch
    constexpr int BBP = BN * 64;
    constexpr int STAGE = 2 * ABP + 2 * BBP;
    constexpr int APL = BM * 4, BPL = BN * 4;     // 16B chunks per plane
    constexpr int TOT = 2 * (APL + BPL);

    extern __shared__ char smem[];
    const int tid = threadIdx.x, lane = tid & 31, wid = tid >> 5;
    const int warp_m = wid & 3, warp_n = wid >> 2;
    const int m0 = blockIdx.y * BM, n0 = blockIdx.x * BN;
    const int zo = blockIdx.z / zInner, zi = blockIdx.z % zInner;
    const int ldAB = 2 * Kd;
    const __nv_bfloat16* Az = A + (long long)zo * aZo + (long long)zi * aZi;
    const __nv_bfloat16* Bz = B + (long long)zo * bZo + (long long)zi * bZi;
    float* Cz = Co + (long long)zo * cZo + (long long)zi * cZi;
    const float* biasz = bias ? bias + (long long)zi * biasZi : nullptr;

    const unsigned sb = smem_u32(smem);
    const int nkb = Kd / BK;

    float acc[2][NT8][4];
    #pragma unroll
    for (int mt = 0; mt < 2; mt++)
        #pragma unroll
        for (int nt = 0; nt < NT8; nt++)
            #pragma unroll
            for (int j = 0; j < 4; j++) acc[mt][nt][j] = 0.f;

    auto load = [&](int kb) {
        if (kb < nkb) {
            unsigned st = sb + (unsigned)(kb % 3) * STAGE;
            int k0 = kb * BK;
            #pragma unroll
            for (int q = 0; q < TOT / THREADS; q++) {
                int ch = tid + q * THREADS;
                unsigned dst; const __nv_bfloat16* src;
                if (ch < 2 * APL) {
                    int pl = (ch >= APL) ? 1 : 0;
                    int cc = ch - pl * APL;
                    int row = cc >> 2, c = cc & 3;
                    dst = st + pl * ABP + swz(row, c);
                    src = Az + (size_t)(m0 + row) * ldAB + pl * Kd + k0 + c * 8;
                } else {
                    int ch2 = ch - 2 * APL;
                    int pl = (ch2 >= BPL) ? 1 : 0;
                    int cc = ch2 - pl * BPL;
                    int row = cc >> 2, c = cc & 3;
                    dst = st + 2 * ABP + pl * BBP + swz(row, c);
                    src = Bz + (size_t)(n0 + row) * ldAB + pl * Kd + k0 + c * 8;
                }
                cp16(dst, src);
            }
        }
        asm volatile("cp.async.commit_group;" ::: "memory");
    };

    load(0); load(1);

    for (int kb = 0; kb < nkb; kb++) {
        asm volatile("cp.async.wait_group 1;" ::: "memory");
        __syncthreads();
        load(kb + 2);                       // prefetch BEFORE compute

        unsigned st = sb + (unsigned)(kb % 3) * STAGE;
        unsigned ah = st, al = st + ABP, bh = st + 2 * ABP, bl = bh + BBP;

        #pragma unroll
        for (int ks = 0; ks < 2; ks++) {
            unsigned af0[2][4], af1[2][4], bf[NT8 / 2][4];
            const int arow0 = warp_m * 32 + (lane & 15);
            const int c_a = 2 * ks + (lane >> 4);
            const unsigned aoff0 = swz(arow0, c_a);
            const unsigned aoff1 = swz(arow0 + 16, c_a);
            const int rowi = lane & 7, quad = lane >> 3;
            const int nofs = (quad >> 1) * 8;
            const int c_b = 2 * ks + (quad & 1);

            ldsm4(af0[0], ah + aoff0);
            ldsm4(af0[1], ah + aoff1);
            ldsm4(af1[0], al + aoff0);
            ldsm4(af1[1], al + aoff1);
            #pragma unroll
            for (int j = 0; j < NT8 / 2; j++) {
                int nb = warp_n * WN + j * 16 + nofs + rowi;
                ldsm4(bf[j], bh + swz(nb, c_b));
            }
            // phase 0: Ah . Bh
            #pragma unroll
            for (int mt = 0; mt < 2; mt++)
                #pragma unroll
                for (int nt = 0; nt < NT8; nt++)
                    mma16816(acc[mt][nt], af0[mt], &bf[nt >> 1][(nt & 1) * 2]);
            // phase 2: Al . Bh
            #pragma unroll
            for (int mt = 0; mt < 2; mt++)
                #pragma unroll
                for (int nt = 0; nt < NT8; nt++)
                    mma16816(acc[mt][nt], af1[mt], &bf[nt >> 1][(nt & 1) * 2]);
            // phase 1: Ah . Bl
            #pragma unroll
            for (int j = 0; j < NT8 / 2; j++) {
                int nb = warp_n * WN + j * 16 + nofs + rowi;
                ldsm4(bf[j], bl + swz(nb, c_b));
            }
            #pragma unroll
            for (int mt = 0; mt < 2; mt++)
                #pragma unroll
                for (int nt = 0; nt < NT8; nt++)
                    mma16816(acc[mt][nt], af0[mt], &bf[nt >> 1][(nt & 1) * 2]);
        }
    }

    // ---- epilogue ----
    float alpha = alpha_p ? __ldg(alpha_p) : 0.f;
    int g = lane >> 2, q = lane & 3;
    #pragma unroll
    for (int mt = 0; mt < 2; mt++) {
        int row = m0 + warp_m * 32 + mt * 16 + g;
        #pragma unroll
        for (int nt = 0; nt < NT8; nt++) {
            int col = n0 + warp_n * WN + nt * 8 + q * 2;
            float b0 = 0.f, b1 = 0.f;
            if (biasz) { b0 = biasz[col]; b1 = biasz[col + 1]; }
            float2 v0 = make_float2(acc[mt][nt][0] + b0, acc[mt][nt][1] + b1);
            float2 v1 = make_float2(acc[mt][nt][2] + b0, acc[mt][nt][3] + b1);
            if (alpha_p) {
                v0.x = v0.x >= 0.f ? v0.x : alpha * v0.x;
                v0.y = v0.y >= 0.f ? v0.y : alpha * v0.y;
                v1.x = v1.x >= 0.f ? v1.x : alpha * v1.x;
                v1.y = v1.y >= 0.f ? v1.y : alpha * v1.y;
            }
            *reinterpret_cast<float2*>(Cz + (size_t)row * ldc + col) = v0;
            *reinterpret_cast<float2*>(Cz + (size_t)(row + 8) * ldc + col) = v1;
        }
    }
}

// ---------------- split conversions (2-plane [hi|lo]) ----------------
__device__ __forceinline__ void split2(float x, unsigned short& h, unsigned short& l) {
    __nv_bfloat16 hb = __float2bfloat16(x);
    __nv_bfloat16 lb = __float2bfloat16(x - __bfloat162float(hb));
    h = __bfloat16_as_ushort(hb); l = __bfloat16_as_ushort(lb);
}

// A-side: fp32 [N_, ldin] -> bf16 [N_, 2K]
__global__ void __launch_bounds__(256) k_splitA(
    const float* __restrict__ in, long long inZ, int ldin, int K,
    __nv_bfloat16* __restrict__ out, long long outZ)
{
    long long z = blockIdx.z;
    in += z * inZ; out += z * outZ;
    int K4 = K / 4;
    int idx = blockIdx.x * 256 + threadIdx.x;
    if (idx >= N_ * K4) return;
    int m = idx / K4, k4 = (idx % K4) * 4;
    float4 v = *reinterpret_cast<const float4*>(in + (size_t)m * ldin + k4);
    ushort4 h, l;
    split2(v.x, h.x, l.x); split2(v.y, h.y, l.y);
    split2(v.z, h.z, l.z); split2(v.w, h.w, l.w);
    size_t b = (size_t)m * 2 * K;
    *reinterpret_cast<ushort4*>(out + b + k4) = h;
    *reinterpret_cast<ushort4*>(out + b + K + k4) = l;
}

// Fused per-row LN1 stats + LN + PReLU + split. Block per (n, r).
__global__ void __launch_bounds__(256) k_lnsplit(
    const float* __restrict__ x1,
    const float* __restrict__ g1, const float* __restrict__ be1,
    const float* __restrict__ a1p, __nv_bfloat16* __restrict__ out)
{
    int n = blockIdx.x, r = blockIdx.y, tid = threadIdx.x;
    __shared__ __align__(16) float sx[CH_];
    __shared__ float rsum[8], rsum2[8], smn, srs;
    const float* xr = x1 + ((size_t)r * N_ + n) * CH_;

    float s = 0.f, s2 = 0.f;
    for (int i = tid; i < CH_ / 4; i += 256) {
        float4 t = reinterpret_cast<const float4*>(xr)[i];
        reinterpret_cast<float4*>(sx)[i] = t;
        s  += t.x + t.y + t.z + t.w;
        s2 += t.x*t.x + t.y*t.y + t.z*t.z + t.w*t.w;
    }
    int lane = tid & 31, wid = tid >> 5;
    #pragma unroll
    for (int o = 16; o > 0; o >>= 1) {
        s  += __shfl_xor_sync(0xffffffffu, s,  o);
        s2 += __shfl_xor_sync(0xffffffffu, s2, o);
    }
    if (lane == 0) { rsum[wid] = s; rsum2[wid] = s2; }
    __syncthreads();
    if (tid == 0) {
        float ts = 0.f, ts2 = 0.f;
        #pragma unroll
        for (int w2 = 0; w2 < 8; w2++) { ts += rsum[w2]; ts2 += rsum2[w2]; }
        float m = ts / (float)CH_;
        smn = m; srs = rsqrtf(ts2 / (float)CH_ - m * m + 1e-5f);
    }
    __syncthreads();

    float mn = smn, rs = srs, a = __ldg(a1p);
    for (int i4 = tid; i4 < CH_ / 4; i4 += 256) {
        int i = i4 * 4;
        int c = i / HID_, col = i % HID_;
        float4 v = reinterpret_cast<const float4*>(sx)[i4];
        float4 g = reinterpret_cast<const float4*>(g1)[i4];
        float4 b = reinterpret_cast<const float4*>(be1)[i4];
        v.x = (v.x-mn)*rs*g.x + b.x; v.y = (v.y-mn)*rs*g.y + b.y;
        v.z = (v.z-mn)*rs*g.z + b.z; v.w = (v.w-mn)*rs*g.w + b.w;
        v.x = v.x >= 0.f ? v.x : a*v.x; v.y = v.y >= 0.f ? v.y : a*v.y;
        v.z = v.z >= 0.f ? v.z : a*v.z; v.w = v.w >= 0.f ? v.w : a*v.w;
        ushort4 h, l;
        split2(v.x, h.x, l.x); split2(v.y, h.y, l.y);
        split2(v.z, h.z, l.z); split2(v.w, h.w, l.w);
        __nv_bfloat16* op = out + ((size_t)r * C_ + c) * N_ * (2*HID_) + (size_t)n * (2*HID_);
        *reinterpret_cast<ushort4*>(op + col) = h;
        *reinterpret_cast<ushort4*>(op + HID_ + col) = l;
    }
}

// B-side: fp32 [Kd, Nn] -> bf16 [Nn, 2Kd], coalesced via 32x32 smem transpose
__global__ void __launch_bounds__(256) k_splitB(
    const float* __restrict__ in, long long inZ, int Kd, int Nn,
    __nv_bfloat16* __restrict__ out, long long outZ)
{
    __shared__ float tile[32][33];
    long long z = blockIdx.z;
    in += z * inZ; out += z * outZ;
    int k0 = blockIdx.x * 32, n0 = blockIdx.y * 32;
    int tx = threadIdx.x & 31, ty = threadIdx.x >> 5;   // 32 x 8
    #pragma unroll
    for (int j = 0; j < 32; j += 8)
        tile[ty + j][tx] = in[(size_t)(k0 + ty + j) * Nn + n0 + tx];
    __syncthreads();
    #pragma unroll
    for (int j = 0; j < 32; j += 8) {
        int n = n0 + ty + j, k = k0 + tx;
        float x = tile[tx][ty + j];
        unsigned short h, l;
        split2(x, h, l);
        size_t b = (size_t)n * 2 * Kd;
        out[b + k] = __ushort_as_bfloat16(h);
        out[b + Kd + k] = __ushort_as_bfloat16(l);
    }
}

// ---------------- plain fp32 GEMM for tiny weight fusion ----------------
__global__ void __launch_bounds__(256, 2) fuse_weights_kernel(
    const float* __restrict__ femb, const float* __restrict__ eemb,
    const float* __restrict__ lemb, const float* __restrict__ W1)
{
    constexpr int BM = 64, TM = 4, BN = 128, BK = 16, TN = 8;
    int zz = blockIdx.z, r = zz / C_, c = zz % C_;
    const float* A; int M; float* out;
    if (c < K_)      { A = femb + (size_t)(r*K_+c)*V_*IN_; M = V_;   out = g_Wraw + (size_t)(r*K_+c)*V_*HID_; }
    else if (c == 3) { A = eemb + (size_t)r*VE_*IN_;       M = VE_;  out = g_Wex  + (size_t)r*VE_*HID_; }
    else             { A = lemb + (size_t)r*OUT_*IN_;      M = OUT_; out = g_Wlab + (size_t)r*OUT_*HID_; }
    const float* B = W1 + (size_t)c * IN_ * HID_;

    __shared__ __align__(16) float As[BK][BM+4];
    __shared__ __align__(16) float Bs[BK][BN];
    int tid = threadIdx.x, tx = tid % (BN/TN), ty = tid / (BN/TN);
    int row0 = blockIdx.y * BM, col0 = blockIdx.x * BN;
    float acc[TM][TN] = {};
    for (int k0 = 0; k0 < IN_; k0 += BK) {
        for (int v = tid; v < BM*(BK/4); v += 256) {
            int rr = v / (BK/4), kq = (v % (BK/4)) * 4, gr = row0 + rr;
            float4 val = make_float4(0,0,0,0);
            if (gr < M) val = *reinterpret_cast<const float4*>(A + (size_t)gr*IN_ + k0 + kq);
            As[kq][rr] = val.x; As[kq+1][rr] = val.y; As[kq+2][rr] = val.z; As[kq+3][rr] = val.w;
        }
        for (int v = tid; v < BK*(BN/4); v += 256) {
            int rr = v / (BN/4), c4 = (v % (BN/4)) * 4;
            *reinterpret_cast<float4*>(&Bs[rr][c4]) =
                *reinterpret_cast<const float4*>(B + (size_t)(k0+rr)*HID_ + col0 + c4);
        }
        __syncthreads();
        #pragma unroll
        for (int kk = 0; kk < BK; kk++) {
            float a[TM], b[TN];
            #pragma unroll
            for (int i = 0; i < TM; i++) a[i] = As[kk][ty*TM+i];
            #pragma unroll
            for (int j = 0; j < TN; j++) b[j] = Bs[kk][tx*TN+j];
            #pragma unroll
            for (int i = 0; i < TM; i++)
                #pragma unroll
                for (int j = 0; j < TN; j++) acc[i][j] += a[i]*b[j];
        }
        __syncthreads();
    }
    #pragma unroll
    for (int i = 0; i < TM; i++) {
        int gr = row0 + ty*TM + i;
        if (gr >= M) continue;
        #pragma unroll
        for (int j = 0; j < TN; j++) out[(size_t)gr*HID_ + col0 + tx*TN + j] = acc[i][j];
    }
}

// ---------------- small SIMT kernels ----------------
__global__ void k_u(const float* __restrict__ eemb, const float* __restrict__ wx)
{
    int t = blockIdx.x * blockDim.x + threadIdx.x;
    if (t >= R_ * VE_) return;
    const float* row = eemb + (size_t)t * IN_;
    float s = 0.f;
    for (int d = 0; d < IN_; d++) s += row[d] * wx[d];
    g_u[t] = s;
}

__global__ void __launch_bounds__(256) k_extra_pool(const float* __restrict__ extra)
{
    int wg = (blockIdx.x * blockDim.x + threadIdx.x) >> 5, lane = threadIdx.x & 31;
    if (wg >= R_ * N_) return;
    int r = wg / N_;
    const float* base = extra + (size_t)wg * (L_ * VE_);
    float u[4];
    #pragma unroll
    for (int j = 0; j < 4; j++) u[j] = g_u[r * VE_ + lane + 32*j];
    float x[L_][4], s[L_];
    #pragma unroll
    for (int l = 0; l < L_; l++) {
        float p = 0.f;
        #pragma unroll
        for (int j = 0; j < 4; j++) { x[l][j] = base[l*VE_ + lane + 32*j]; p += x[l][j]*u[j]; }
        #pragma unroll
        for (int o = 16; o > 0; o >>= 1) p += __shfl_xor_sync(0xffffffffu, p, o);
        s[l] = 1.f / (1.f + expf(-p));
    }
    float mx = s[0];
    #pragma unroll
    for (int l = 1; l < L_; l++) mx = fmaxf(mx, s[l]);
    float e[L_], es = 0.f;
    #pragma unroll
    for (int l = 0; l < L_; l++) { e[l] = expf(s[l]-mx); es += e[l]; }
    float inv = 1.f / es, out[4] = {0,0,0,0};
    #pragma unroll
    for (int l = 0; l < L_; l++) {
        float w = e[l]*inv;
        #pragma unroll
        for (int j = 0; j < 4; j++) out[j] += w * x[l][j];
    }
    float* op = g_xp + (size_t)wg * VE_;
    #pragma unroll
    for (int j = 0; j < 4; j++) op[lane + 32*j] = out[j];
}

// channel attention pool with in-block LN2; block per (n, r)
__global__ void __launch_bounds__(256) k_pool_c(
    const float* __restrict__ g2, const float* __restrict__ be2,
    const float* __restrict__ a2p, const float* __restrict__ w_r)
{
    int n = blockIdx.x, r = blockIdx.y, tid = threadIdx.x;
    __shared__ __align__(16) float sx[CH_];
    __shared__ float red[C_][8], rsum[8], rsum2[8], salpha[C_], smn, srs;
    const float* xr = g_x2 + ((size_t)r * N_ + n) * CH_;
    const float* wr = w_r + r * HID_;
    float s = 0.f, s2 = 0.f;
    for (int i = tid; i < CH_/4; i += 256) {
        float4 t = reinterpret_cast<const float4*>(xr)[i];
        reinterpret_cast<float4*>(sx)[i] = t;
        s += t.x+t.y+t.z+t.w; s2 += t.x*t.x+t.y*t.y+t.z*t.z+t.w*t.w;
    }
    int lane = tid & 31, wid = tid >> 5;
    #pragma unroll
    for (int o = 16; o > 0; o >>= 1) {
        s += __shfl_xor_sync(0xffffffffu, s, o);
        s2 += __shfl_xor_sync(0xffffffffu, s2, o);
    }
    if (lane == 0) { rsum[wid] = s; rsum2[wid] = s2; }
    __syncthreads();
    if (tid == 0) {
        float ts = 0.f, ts2 = 0.f;
        #pragma unroll
        for (int w2 = 0; w2 < 8; w2++) { ts += rsum[w2]; ts2 += rsum2[w2]; }
        float m = ts/(float)CH_;
        smn = m; srs = rsqrtf(ts2/(float)CH_ - m*m + 1e-5f);
    }
    __syncthreads();
    float mn = smn, rs = srs, a = __ldg(a2p);
    for (int i = tid; i < CH_; i += 256) {
        float v = (sx[i]-mn)*rs*g2[i] + be2[i];
        sx[i] = v >= 0.f ? v : a*v;
    }
    __syncthreads();
    float p[C_] = {0,0,0,0,0};
    for (int h = tid; h < HID_; h += 256) {
        float w = wr[h];
        #pragma unroll
        for (int c = 0; c < C_; c++) p[c] += sx[c*HID_+h] * w;
    }
    #pragma unroll
    for (int c = 0; c < C_; c++)
        #pragma unroll
        for (int o = 16; o > 0; o >>= 1) p[c] += __shfl_xor_sync(0xffffffffu, p[c], o);
    if (lane == 0)
        #pragma unroll
        for (int c = 0; c < C_; c++) red[c][wid] = p[c];
    __syncthreads();
    if (tid == 0) {
        float sv[C_], mx = -1e30f;
        #pragma unroll
        for (int c = 0; c < C_; c++) {
            float t = 0.f;
            #pragma unroll
            for (int w2 = 0; w2 < 8; w2++) t += red[c][w2];
            sv[c] = 1.f / (1.f + expf(-t)); mx = fmaxf(mx, sv[c]);
        }
        float es = 0.f, e[C_];
        #pragma unroll
        for (int c = 0; c < C_; c++) { e[c] = expf(sv[c]-mx); es += e[c]; }
        #pragma unroll
        for (int c = 0; c < C_; c++) salpha[c] = e[c] / es;
    }
    __syncthreads();
    float* op = g_outr + ((size_t)r * N_ + n) * HID_;
    for (int h = tid; h < HID_; h += 256) {
        float acc = 0.f;
        #pragma unroll
        for (int c = 0; c < C_; c++) acc += salpha[c] * sx[c*HID_+h];
        op[h] = acc;
    }
}

__global__ void __launch_bounds__(256) k_pool_global(const float* __restrict__ wg)
{
    int w = (blockIdx.x * blockDim.x + threadIdx.x) >> 5, lane = threadIdx.x & 31;
    if (w >= N_) return;
    const float* pa = g_outr + (size_t)w * HID_;
    const float* pb = g_outr + (size_t)N_ * HID_ + (size_t)w * HID_;
    float a[16], b[16], sa = 0.f, sb = 0.f;
    #pragma unroll
    for (int j = 0; j < 16; j++) {
        int h = lane + 32*j;
        a[j] = pa[h]; b[j] = pb[h];
        float wv = wg[h];
        sa += a[j]*wv; sb += b[j]*wv;
    }
    #pragma unroll
    for (int o = 16; o > 0; o >>= 1) {
        sa += __shfl_xor_sync(0xffffffffu, sa, o);
        sb += __shfl_xor_sync(0xffffffffu, sb, o);
    }
    sa = 1.f/(1.f+expf(-sa)); sb = 1.f/(1.f+expf(-sb));
    float mx = fmaxf(sa, sb), ea = expf(sa-mx), eb = expf(sb-mx);
    float aa = ea/(ea+eb), ab = 1.f - aa;
    float* op = g_hfin + (size_t)w * HID_;
    #pragma unroll
    for (int j = 0; j < 16; j++) op[lane + 32*j] = aa*a[j] + ab*b[j];
}

// ---------------- input mapping ----------------
struct Ins {
    const float *raw, *extra, *label, *femb, *eemb, *lemb;
    const float *w_extra, *w_r, *w_g;
    const float *W1, *b1, *g1, *be1, *a1, *W2, *b2, *g2, *be2, *a2;
    const float *Wf1, *bf1, *af, *Wf2, *bf2;
};
static void resolve(void* const* d_in, const int* sz, Ins& I)
{
    auto F = [&](int i) { return (const float*)d_in[i]; };
    if (sz[0] == R_ * K_ * N_ * V_) {
        I.raw=F(0); I.extra=F(1); I.label=F(2); I.femb=F(3); I.eemb=F(4); I.lemb=F(5);
        I.w_extra=F(6); I.w_r=F(7); I.w_g=F(8);
        I.W1=F(9); I.b1=F(10); I.g1=F(11); I.be1=F(12); I.a1=F(13);
        I.W2=F(14); I.b2=F(15); I.g2=F(16); I.be2=F(17); I.a2=F(18);
        I.Wf1=F(19); I.bf1=F(20); I.af=F(21); I.Wf2=F(22); I.bf2=F(23);
    } else {
        I.W1=F(0); I.W2=F(1); I.Wf1=F(2); I.Wf2=F(3);
        I.a1=F(4); I.a2=F(5); I.af=F(6);
        I.b1=F(7); I.b2=F(8); I.be1=F(9); I.be2=F(10); I.bf1=F(11); I.bf2=F(12);
        I.eemb=F(13); I.extra=F(14); I.femb=F(15); I.g1=F(16); I.g2=F(17);
        I.lemb=F(18); I.label=F(19); I.raw=F(20);
        I.w_extra=F(21); I.w_g=F(22); I.w_r=F(23);
    }
}

extern "C" void kernel_launch(void* const* d_in, const int* in_sizes, int n_in,
                              void* d_out, int out_size)
{
    if (n_in < 24) return;
    Ins I; resolve(d_in, in_sizes, I);

    float *px1, *px2, *pxp, *pWraw, *pWex, *pWlab, *phf;
    __nv_bfloat16 *prawA, *plabA, *pxpA, *px1A, *phfA, *pff1A;
    __nv_bfloat16 *pW2T, *pWrawT, *pWexT, *pWlabT, *pWf1T, *pWf2T;
    cudaGetSymbolAddress((void**)&px1, g_x1);     cudaGetSymbolAddress((void**)&px2, g_x2);
    cudaGetSymbolAddress((void**)&pxp, g_xp);     cudaGetSymbolAddress((void**)&pWraw, g_Wraw);
    cudaGetSymbolAddress((void**)&pWex, g_Wex);   cudaGetSymbolAddress((void**)&pWlab, g_Wlab);
    cudaGetSymbolAddress((void**)&phf, g_hfin);
    cudaGetSymbolAddress((void**)&prawA, g_rawA); cudaGetSymbolAddress((void**)&plabA, g_labA);
    cudaGetSymbolAddress((void**)&pxpA, g_xpA);   cudaGetSymbolAddress((void**)&px1A, g_x1A);
    cudaGetSymbolAddress((void**)&phfA, g_hfA);   cudaGetSymbolAddress((void**)&pff1A, g_ff1A);
    cudaGetSymbolAddress((void**)&pW2T, g_W2T);   cudaGetSymbolAddress((void**)&pWrawT, g_WrawT);
    cudaGetSymbolAddress((void**)&pWexT, g_WexT); cudaGetSymbolAddress((void**)&pWlabT, g_WlabT);
    cudaGetSymbolAddress((void**)&pWf1T, g_Wf1T); cudaGetSymbolAddress((void**)&pWf2T, g_Wf2T);

    constexpr int SM128 = 3 * (2 * 128 * 64 + 2 * 128 * 64);   // 98304 B -> 2 CTAs/SM
    constexpr int SM64  = 3 * (2 * 128 * 64 + 2 * 64 * 64);    // 73728 B
    cudaFuncSetAttribute(k_tc_gemm<128>, cudaFuncAttributeMaxDynamicSharedMemorySize, SM128);
    cudaFuncSetAttribute(k_tc_gemm<64>,  cudaFuncAttributeMaxDynamicSharedMemorySize, SM64);

    // ---- launches ordered so #4 = raw GEMM (ncu capture position) ----
    fuse_weights_kernel<<<dim3(4, 4, 10), 256>>>(I.femb, I.eemb, I.lemb, I.W1);            // 1
    k_splitB<<<dim3(V_/32, HID_/32, 6), 256>>>(pWraw, (long long)V_*HID_, V_, HID_,
                                               pWrawT, (long long)HID_*2*V_);              // 2
    k_splitA<<<dim3(4096, 1, 6), 256>>>(I.raw, (long long)N_*V_, V_, V_,
                                        prawA, (long long)N_*2*V_);                        // 3
    // raw GEMM, z = r*3+c (zInner=3): x1 channels 0..2 for both r             — launch 4
    k_tc_gemm<128><<<dim3(HID_/128, N_/128, R_*K_), 256, SM128>>>(
        prawA, (long long)K_*N_*2*V_, (long long)N_*2*V_, K_,
        pWrawT, (long long)K_*HID_*2*V_, (long long)HID_*2*V_, V_,
        I.b1, HID_,
        px1, CH_, (long long)N_*CH_, HID_, nullptr);

    // ---- rest of prolog ----
    k_u<<<1, 256>>>(I.eemb, I.w_extra);
    k_extra_pool<<<(R_ * N_) / 8, 256>>>(I.extra);
    k_splitB<<<dim3(VE_/32, HID_/32, 2), 256>>>(pWex, (long long)VE_*HID_, VE_, HID_,
                                                pWexT, (long long)HID_*2*VE_);
    k_splitB<<<dim3(OUT_/32, HID_/32, 2), 256>>>(pWlab, (long long)OUT_*HID_, OUT_, HID_,
                                                 pWlabT, (long long)HID_*2*OUT_);
    k_splitB<<<dim3(HID_/32, HID_/32, 5), 256>>>(I.W2, (long long)HID_*HID_, HID_, HID_,
                                                 pW2T, (long long)HID_*2*HID_);
    k_splitB<<<dim3(HID_/32, HID_/32, 1), 256>>>(I.Wf1, 0, HID_, HID_, pWf1T, 0);
    k_splitB<<<dim3(HID_/32, OUT_/32, 1), 256>>>(I.Wf2, 0, HID_, OUT_, pWf2T, 0);
    k_splitA<<<dim3(1024, 1, 2), 256>>>(I.label, (long long)N_*OUT_, OUT_, OUT_,
                                        plabA, (long long)N_*2*OUT_);
    k_splitA<<<dim3(2048, 1, 2), 256>>>(pxp, (long long)N_*VE_, VE_, VE_,
                                        pxpA, (long long)N_*2*VE_);

    // ---- x1 channels 3,4 for both r (z = r, zInner = 1) ----
    k_tc_gemm<128><<<dim3(HID_/128, N_/128, R_), 256, SM128>>>(
        pxpA, (long long)N_*2*VE_, 0, 1,
        pWexT, (long long)HID_*2*VE_, 0, VE_,
        I.b1 + 3*HID_, 0,
        px1 + 3*HID_, CH_, (long long)N_*CH_, 0, nullptr);
    k_tc_gemm<128><<<dim3(HID_/128, N_/128, R_), 256, SM128>>>(
        plabA, (long long)N_*2*OUT_, 0, 1,
        pWlabT, (long long)HID_*2*OUT_, 0, OUT_,
        I.b1 + 4*HID_, 0,
        px1 + 4*HID_, CH_, (long long)N_*CH_, 0, nullptr);

    // ---- LN1+split (both r), W2 GEMM (z=10), pool (both r) ----
    k_lnsplit<<<dim3(N_, R_), 256>>>(px1, I.g1, I.be1, I.a1, px1A);
    k_tc_gemm<128><<<dim3(HID_/128, N_/128, R_*C_), 256, SM128>>>(
        px1A, (long long)C_*N_*2*HID_, (long long)N_*2*HID_, C_,
        pW2T, 0, (long long)HID_*2*HID_, HID_,
        I.b2, HID_,
        px2, CH_, (long long)N_*CH_, HID_, nullptr);
    k_pool_c<<<dim3(N_, R_), 256>>>(I.g2, I.be2, I.a2, I.w_r);

    // ---- global pool + FFN head ----
    k_pool_global<<<N_ / 8, 256>>>(I.w_g);
    k_splitA<<<dim3(8192, 1, 1), 256>>>(phf, 0, HID_, HID_, phfA, 0);
    k_tc_gemm<128><<<dim3(HID_/128, N_/128, 1), 256, SM128>>>(
        phfA, 0, 0, 1, pWf1T, 0, 0, HID_,
        I.bf1, 0,
        px2, HID_, 0, 0, I.af);                        // PReLU out, [N,512]
    k_splitA<<<dim3(8192, 1, 1), 256>>>(px2, 0, HID_, HID_, pff1A, 0);
    k_tc_gemm<64><<<dim3(1, N_/128, 1), 128, SM64>>>(
        pff1A, 0, 0, 1, pWf2T, 0, 0, HID_,
        I.bf2, 0,
        (float*)d_out, OUT_, 0, 0, nullptr);
}